// round 9
// baseline (speedup 1.0000x reference)
#include <cuda_runtime.h>
#include <cuda_fp16.h>
#include <cstdint>

#define HH 512
#define WW 512
#define DH 256
#define HWp (HH*WW)          // 262144
#define BB 2
#define MROWS (BB*HWp)       // 524288

// ---------------- scratch (device globals; no allocation allowed) ----------
__device__ float g_down_x[BB*3*DH*DH];                 // 1.5 MB
__device__ float g_out_full[BB*3*HH*WW];               // 6 MB
__device__ float g_out256[BB*3*DH*DH];                 // 1.5 MB
__device__ float g_feat_tmp[BB*64*128*128];            // 8 MB
__device__ __align__(16) __half g_wHi[5][16384];       // [k][n] row-major, n padded to 128
__device__ __align__(16) __half g_wLo[5][16384];

// ---------------- mma/ldmatrix helpers (base ISA only) ----------------------
__device__ __forceinline__ uint32_t smem_u32(const void* p) {
    uint32_t a;
    asm("{ .reg .u64 t; cvta.to.shared.u64 t, %1; cvt.u32.u64 %0, t; }" : "=r"(a) : "l"(p));
    return a;
}
__device__ __forceinline__ void ldsm_x4(uint32_t addr, uint32_t r[4]) {
    asm volatile("ldmatrix.sync.aligned.m8n8.x4.shared.b16 {%0,%1,%2,%3}, [%4];"
        : "=r"(r[0]), "=r"(r[1]), "=r"(r[2]), "=r"(r[3]) : "r"(addr));
}
__device__ __forceinline__ void ldsm_x4t(uint32_t addr, uint32_t r[4]) {
    asm volatile("ldmatrix.sync.aligned.m8n8.x4.trans.shared.b16 {%0,%1,%2,%3}, [%4];"
        : "=r"(r[0]), "=r"(r[1]), "=r"(r[2]), "=r"(r[3]) : "r"(addr));
}
// fp16 inputs, fp32 accumulate (main pass)
__device__ __forceinline__ void mma_f32(float d[4], const uint32_t a[4], const uint32_t* b) {
    asm volatile("mma.sync.aligned.m16n8k16.row.col.f32.f16.f16.f32 "
        "{%0,%1,%2,%3}, {%4,%5,%6,%7}, {%8,%9}, {%0,%1,%2,%3};"
        : "+f"(d[0]), "+f"(d[1]), "+f"(d[2]), "+f"(d[3])
        : "r"(a[0]), "r"(a[1]), "r"(a[2]), "r"(a[3]), "r"(b[0]), "r"(b[1]));
}
// fp16 inputs, fp16 accumulate (correction passes)
__device__ __forceinline__ void mma_f16(uint32_t d[2], const uint32_t a[4], const uint32_t* b) {
    asm volatile("mma.sync.aligned.m16n8k16.row.col.f16.f16.f16.f16 "
        "{%0,%1}, {%2,%3,%4,%5}, {%6,%7}, {%0,%1};"
        : "+r"(d[0]), "+r"(d[1])
        : "r"(a[0]), "r"(a[1]), "r"(a[2]), "r"(a[3]), "r"(b[0]), "r"(b[1]));
}

// ---------------- bicubic tap helpers (match jax.image.resize, a=-0.5) -----
__device__ __forceinline__ void taps_down2(int o, int n, int idx[4], float w[4]) {
    const float kw0 = -0.0625f, kw1 = 0.5625f;
    float kw[4] = {kw0, kw1, kw1, kw0};
    float s = 0.f;
#pragma unroll
    for (int t = 0; t < 4; ++t) {
        int i = 2*o - 1 + t;
        bool ok = (i >= 0) && (i < n);
        idx[t] = ok ? i : 0;
        w[t]   = ok ? kw[t] : 0.f;
        s += w[t];
    }
    float inv = 1.f / s;
#pragma unroll
    for (int t = 0; t < 4; ++t) w[t] *= inv;
}
__device__ __forceinline__ void taps_up2(int o, int n, int idx[4], float w[4]) {
    int m = o >> 1;
    float kw[4];
    int base;
    if ((o & 1) == 0) {
        base = m - 2;
        kw[0] = -0.0234375f; kw[1] = 0.2265625f; kw[2] = 0.8671875f; kw[3] = -0.0703125f;
    } else {
        base = m - 1;
        kw[0] = -0.0703125f; kw[1] = 0.8671875f; kw[2] = 0.2265625f; kw[3] = -0.0234375f;
    }
    float s = 0.f;
#pragma unroll
    for (int t = 0; t < 4; ++t) {
        int i = base + t;
        bool ok = (i >= 0) && (i < n);
        idx[t] = ok ? i : 0;
        w[t]   = ok ? kw[t] : 0.f;
        s += w[t];
    }
    float inv = 1.f / s;
#pragma unroll
    for (int t = 0; t < 4; ++t) w[t] *= inv;
}

// ---------------- bicubic 2x down / up --------------------------------------
__global__ void k_down2(const float* __restrict__ in, float* __restrict__ out1,
                        float* __restrict__ out2, int Cn, int n_in)
{
    int n_out = n_in >> 1;
    long total = (long)Cn * n_out * n_out;
    long t = (long)blockIdx.x * blockDim.x + threadIdx.x;
    if (t >= total) return;
    int ox = (int)(t % n_out);
    int oy = (int)((t / n_out) % n_out);
    long c = t / ((long)n_out * n_out);
    int iy[4], ix[4]; float wy[4], wx[4];
    taps_down2(oy, n_in, iy, wy);
    taps_down2(ox, n_in, ix, wx);
    const float* ip = in + c * n_in * n_in;
    float s = 0.f;
#pragma unroll
    for (int a = 0; a < 4; ++a) {
        float r = 0.f;
#pragma unroll
        for (int b2 = 0; b2 < 4; ++b2) r += wx[b2] * ip[iy[a]*n_in + ix[b2]];
        s += wy[a] * r;
    }
    out1[t] = s;
    if (out2) out2[t] = s;
}
__global__ void k_up2(const float* __restrict__ in, float* __restrict__ outp,
                      int Cn, int n_in)
{
    int n_out = n_in << 1;
    long total = (long)Cn * n_out * n_out;
    long t = (long)blockIdx.x * blockDim.x + threadIdx.x;
    if (t >= total) return;
    int ox = (int)(t % n_out);
    int oy = (int)((t / n_out) % n_out);
    long c = t / ((long)n_out * n_out);
    int iy[4], ix[4]; float wy[4], wx[4];
    taps_up2(oy, n_in, iy, wy);
    taps_up2(ox, n_in, ix, wx);
    const float* ip = in + c * n_in * n_in;
    float s = 0.f;
#pragma unroll
    for (int a = 0; a < 4; ++a) {
        float r = 0.f;
#pragma unroll
        for (int b2 = 0; b2 < 4; ++b2) r += wx[b2] * ip[iy[a]*n_in + ix[b2]];
        s += wy[a] * r;
    }
    outp[t] = s;
}

// ---------------- weight prep: f32 -> (hi,lo) fp16, [k][n] n-padded --------
__global__ void k_prep_w(const float* __restrict__ W1, const float* __restrict__ W2,
                         const float* __restrict__ W3, const float* __restrict__ W4,
                         const float* __restrict__ Wout)
{
    int t = blockIdx.x * 256 + threadIdx.x;     // 5*16384 = 81920
    if (t >= 81920) return;
    int L = t >> 14, r = t & 16383;
    int k = r >> 7, n = r & 127;
    const float* W = (L == 0) ? W1 : (L == 1) ? W2 : (L == 2) ? W3 : (L == 3) ? W4 : Wout;
    float v = (L < 4) ? W[k * 128 + n] : ((n < 81) ? W[k * 81 + n] : 0.f);
    __half h = __float2half(v);
    g_wHi[L][r] = h;
    g_wLo[L][r] = __float2half(v - __half2float(h));
}

// ---------------- fused MLP + dynamic-filter apply --------------------------
// M=128 pixels/CTA, 512 threads (16 warps = 4/SMSP), 147KB smem.
#define ROWB 272
#define S_AHI 0
#define S_ALO 34816
#define S_BHI 69632            // also reused: lwS (128 x 84 f32)
#define S_BLO 104448
#define S_INP 139264           // 128*8 f32; also x patch (3*3*132 f32)
#define S_WIN 144128           // 7*128 f32
#define S_TOT 147712
#define LWST 84

__device__ __forceinline__ void st_hilo2(char* smem, int row, int col,
                                         float v0, float v1)
{
    __half h0 = __float2half(v0);
    __half h1 = __float2half(v1);
    __half l0 = __float2half(v0 - __half2float(h0));
    __half l1 = __float2half(v1 - __half2float(h1));
    __half2 hp; hp.x = h0; hp.y = h1;
    __half2 lp; lp.x = l0; lp.y = l1;
    int off = row * ROWB + col * 2;
    *(uint32_t*)(smem + S_AHI + off) = *(uint32_t*)&hp;
    *(uint32_t*)(smem + S_ALO + off) = *(uint32_t*)&lp;
}

__global__ __launch_bounds__(512, 1) void fused_mlp_mma(
    const float* __restrict__ x, const float* __restrict__ Win,
    float* __restrict__ outp)
{
    extern __shared__ __align__(16) char smem[];
    const uint32_t sb = smem_u32(smem);
    const int tid = threadIdx.x;
    const int wid = tid >> 5, lane = tid & 31;
    const long row0 = (long)blockIdx.x * 128;
    const int bimg = (int)(row0 >> 18);
    const int n0 = (int)(row0 & (HWp - 1));
    const int irow = n0 >> 9, j0 = n0 & 511;

    // ---- stage W_in, per-pixel inputs ----
    for (int i = tid; i < 896; i += 512) *(float*)(smem + S_WIN + i*4) = Win[i];
    if (tid < 128) {
        int i = irow, j = j0 + tid;
        int iy[4], ix[4]; float wy[4], wx[4];
        taps_up2(i, DH, iy, wy);
        taps_up2(j, DH, ix, wx);
        float* ip = (float*)(smem + S_INP) + tid * 8;
        ip[0] = (i & 1) ? 0.5f : -0.5f;
        ip[1] = (j & 1) ? 0.5f : -0.5f;
        ip[2] = 1.f; ip[3] = 1.f;
#pragma unroll
        for (int c = 0; c < 3; ++c) {
            const float* dp = g_down_x + (long)(bimg*3 + c) * DH * DH;
            float s = 0.f;
#pragma unroll
            for (int a = 0; a < 4; ++a) {
                float rr = 0.f;
#pragma unroll
                for (int b2 = 0; b2 < 4; ++b2) rr += wx[b2] * dp[iy[a]*DH + ix[b2]];
                s += wy[a] * rr;
            }
            ip[4 + c] = x[((long)(bimg*3 + c) * HH + i) * WW + j] - s;
        }
        ip[7] = 0.f;
    }
    __syncthreads();

    // ---- layer 0 (7 -> 128) SIMT, write A hi/lo ----
    {
        int row = tid >> 2;
        int cbase = (tid & 3) * 32;
        const float* ip = (const float*)(smem + S_INP) + row * 8;
        float a0 = ip[0], a1 = ip[1], a2 = ip[2], a3 = ip[3];
        float a4 = ip[4], a5 = ip[5], a6 = ip[6];
        const float* Wn = (const float*)(smem + S_WIN);
#pragma unroll 4
        for (int c = 0; c < 32; c += 2) {
            int o = cbase + c;
            float v0 = a0*Wn[o] + a1*Wn[128+o] + a2*Wn[256+o] + a3*Wn[384+o]
                     + a4*Wn[512+o] + a5*Wn[640+o] + a6*Wn[768+o];
            float v1 = a0*Wn[o+1] + a1*Wn[128+o+1] + a2*Wn[256+o+1] + a3*Wn[384+o+1]
                     + a4*Wn[512+o+1] + a5*Wn[640+o+1] + a6*Wn[768+o+1];
            v0 = v0 > 0.f ? v0 : 0.01f * v0;
            v1 = v1 > 0.f ? v1 : 0.01f * v1;
            st_hilo2(smem, row, o, v0, v1);
        }
    }

    // ---- warp tiling: 4 (m) x 4 (n); warp tile = 32 rows x 32 cols ----
    const int wm = wid & 3, wn = wid >> 2;
    const uint32_t aAddr = sb + S_AHI + (uint32_t)((wm*32 + (lane & 15)) * ROWB + (lane >> 4) * 16);
    const uint32_t bAddr = sb + S_BHI + (uint32_t)((lane & 15) * ROWB + (wn*32)*2 + (lane >> 4) * 16);

#pragma unroll 1
    for (int L = 0; L < 5; ++L) {
        // stage layer weights hi/lo into smem padded rows
        {
            const uint4* srcH = (const uint4*)g_wHi[L];
            const uint4* srcL = (const uint4*)g_wLo[L];
#pragma unroll
            for (int it = 0; it < 4; ++it) {
                int idx = it * 512 + tid;         // 2048 uint4 = 16384 halves
                int row = idx >> 4, col = (idx & 15) * 8;
                *(uint4*)(smem + S_BHI + row * ROWB + col * 2) = srcH[idx];
                *(uint4*)(smem + S_BLO + row * ROWB + col * 2) = srcL[idx];
            }
        }
        __syncthreads();

        float acc[2][4][4];
        uint32_t c16[2][4][2];
#pragma unroll
        for (int mt = 0; mt < 2; ++mt)
#pragma unroll
            for (int nt = 0; nt < 4; ++nt) {
#pragma unroll
                for (int q = 0; q < 4; ++q) acc[mt][nt][q] = 0.f;
                c16[mt][nt][0] = 0u; c16[mt][nt][1] = 0u;
            }

#pragma unroll 1
        for (int k = 0; k < 8; ++k) {
            uint32_t ah[2][4], al[2][4];
#pragma unroll
            for (int mt = 0; mt < 2; ++mt) {
                uint32_t a = aAddr + (uint32_t)(mt * 16 * ROWB + k * 32);
                ldsm_x4(a, ah[mt]);
                ldsm_x4(a + (S_ALO - S_AHI), al[mt]);
            }
#pragma unroll
            for (int np = 0; np < 2; ++np) {
                uint32_t bh[4], bl[4];
                uint32_t b = bAddr + (uint32_t)(k * 16 * ROWB + np * 32);
                ldsm_x4t(b, bh);
                ldsm_x4t(b + (S_BLO - S_BHI), bl);
                // main pass: fp32 accumulate (same-acc distance 4)
                mma_f32(acc[0][np*2],   ah[0], bh);
                mma_f32(acc[0][np*2+1], ah[0], bh + 2);
                mma_f32(acc[1][np*2],   ah[1], bh);
                mma_f32(acc[1][np*2+1], ah[1], bh + 2);
                // corrections: fp16 accumulate
                mma_f16(c16[0][np*2],   ah[0], bl);
                mma_f16(c16[0][np*2+1], ah[0], bl + 2);
                mma_f16(c16[1][np*2],   ah[1], bl);
                mma_f16(c16[1][np*2+1], ah[1], bl + 2);
                mma_f16(c16[0][np*2],   al[0], bh);
                mma_f16(c16[0][np*2+1], al[0], bh + 2);
                mma_f16(c16[1][np*2],   al[1], bh);
                mma_f16(c16[1][np*2+1], al[1], bh + 2);
            }
        }
        __syncthreads();   // all warps done reading A/B before overwriting

        if (L < 4) {
#pragma unroll
            for (int mt = 0; mt < 2; ++mt) {
                int r0 = wm*32 + mt*16 + (lane >> 2);
#pragma unroll
                for (int nt = 0; nt < 4; ++nt) {
                    int c = wn*32 + nt*8 + (lane & 3)*2;
                    __half2 p0 = *(__half2*)&c16[mt][nt][0];
                    __half2 p1 = *(__half2*)&c16[mt][nt][1];
                    float v0 = acc[mt][nt][0] + __half2float(p0.x);
                    float v1 = acc[mt][nt][1] + __half2float(p0.y);
                    float w0 = acc[mt][nt][2] + __half2float(p1.x);
                    float w1 = acc[mt][nt][3] + __half2float(p1.y);
                    v0 = v0 > 0.f ? v0 : 0.01f * v0;
                    v1 = v1 > 0.f ? v1 : 0.01f * v1;
                    w0 = w0 > 0.f ? w0 : 0.01f * w0;
                    w1 = w1 > 0.f ? w1 : 0.01f * w1;
                    st_hilo2(smem, r0,     c, v0, v1);
                    st_hilo2(smem, r0 + 8, c, w0, w1);
                }
            }
            __syncthreads();
        } else {
            // output layer: dump cols < 81 into lwS (reuses B buffer region)
            float* lwS = (float*)(smem + S_BHI);
#pragma unroll
            for (int mt = 0; mt < 2; ++mt) {
                int r0 = wm*32 + mt*16 + (lane >> 2);
#pragma unroll
                for (int nt = 0; nt < 4; ++nt) {
                    int c = wn*32 + nt*8 + (lane & 3)*2;
                    __half2 p0 = *(__half2*)&c16[mt][nt][0];
                    __half2 p1 = *(__half2*)&c16[mt][nt][1];
                    if (c < 81) {
                        lwS[r0 * LWST + c]     = acc[mt][nt][0] + __half2float(p0.x);
                        lwS[(r0+8) * LWST + c] = acc[mt][nt][2] + __half2float(p1.x);
                    }
                    if (c + 1 < 81) {
                        lwS[r0 * LWST + c + 1]     = acc[mt][nt][1] + __half2float(p0.y);
                        lwS[(r0+8) * LWST + c + 1] = acc[mt][nt][3] + __half2float(p1.y);
                    }
                }
            }
        }
    }

    // ---- stage 3ch x 3row x 130col x patch (zero padded) ----
    float* xp = (float*)(smem + S_INP);        // [3][3][132]
    for (int idx = tid; idx < 3*3*130; idx += 512) {
        int c = idx / 390, rem = idx % 390, ki = rem / 130, jj = rem % 130;
        int yy = irow + ki - 1;
        int xx = j0 + jj - 1;
        float v = 0.f;
        if (yy >= 0 && yy < HH && xx >= 0 && xx < WW)
            v = x[((long)(bimg*3 + c) * HH + yy) * WW + xx];
        xp[(c*3 + ki) * 132 + jj] = v;
    }
    __syncthreads();

    // ---- apply: 128 pixels x 3 out channels ----
    if (tid < 384) {
        int p = tid & 127, oc = tid >> 7;
        const float* lwr = (const float*)(smem + S_BHI) + p * LWST;
        float o = 0.f;
#pragma unroll
        for (int c = 0; c < 3; ++c)
#pragma unroll
            for (int ki = 0; ki < 3; ++ki) {
                const float* xr = xp + (c*3 + ki) * 132 + p;
#pragma unroll
                for (int kj = 0; kj < 3; ++kj)
                    o += xr[kj] * lwr[(c*9 + ki*3 + kj) * 3 + oc];
            }
        outp[(long)(bimg*3 + oc) * HWp + n0 + p] = o;
    }
}

// ---------------- 3x3 stride-2 pad-1 conv, 3 -> 64 channels -----------------
__global__ __launch_bounds__(256) void k_conv3x3s2(const float* __restrict__ in,
    const float* __restrict__ wt, const float* __restrict__ bias,
    float* __restrict__ outp, int S)
{
    __shared__ float w_s[1728];
    __shared__ float in_s[3][33][33];
    int tid = threadIdx.x;
    for (int i = tid; i < 1728; i += 256) w_s[i] = wt[i];
    int OS = S >> 1;
    int ox0 = blockIdx.x * 16, oy0 = blockIdx.y * 16, b = blockIdx.z;
    for (int idx = tid; idx < 3*33*33; idx += 256) {
        int c = idx / 1089, rem = idx % 1089, r = rem / 33, col = rem % 33;
        int iy = oy0*2 - 1 + r, ix = ox0*2 - 1 + col;
        float v = 0.f;
        if (iy >= 0 && iy < S && ix >= 0 && ix < S)
            v = in[((long)(b*3 + c) * S + iy) * S + ix];
        in_s[c][r][col] = v;
    }
    __syncthreads();
    int ox = tid & 15, oy = tid >> 4;
    float pix[27];
#pragma unroll
    for (int c = 0; c < 3; ++c)
#pragma unroll
        for (int ki = 0; ki < 3; ++ki)
#pragma unroll
            for (int kj = 0; kj < 3; ++kj)
                pix[c*9 + ki*3 + kj] = in_s[c][2*oy + ki][2*ox + kj];
#pragma unroll 4
    for (int oc = 0; oc < 64; ++oc) {
        float acc = bias[oc];
#pragma unroll
        for (int q = 0; q < 27; ++q) acc += pix[q] * w_s[oc*27 + q];
        outp[(((long)b*64 + oc) * OS + oy0 + oy) * OS + ox0 + ox] = acc;
    }
}

// ---------------- 1x1 mod conv ----------------------------------------------
__global__ void k_mod(const float* __restrict__ dx, const float* __restrict__ o256,
                      const float* __restrict__ mw, const float* __restrict__ mb,
                      float* __restrict__ outp)
{
    int t = blockIdx.x * 256 + threadIdx.x;
    if (t >= BB * DH * DH) return;
    int b = t >> 16, p = t & 65535;
    float in6[6];
#pragma unroll
    for (int c = 0; c < 3; ++c) in6[c]     = dx[(b*3 + c)*65536 + p];
#pragma unroll
    for (int c = 0; c < 3; ++c) in6[3 + c] = o256[(b*3 + c)*65536 + p];
#pragma unroll
    for (int oc = 0; oc < 3; ++oc) {
        float a = mb[oc];
#pragma unroll
        for (int ic = 0; ic < 6; ++ic) a += in6[ic] * mw[oc*6 + ic];
        outp[(b*3 + oc)*65536 + p] = a;
    }
}

// ---------------- launch -----------------------------------------------------
extern "C" void kernel_launch(void* const* d_in, const int* in_sizes, int n_in,
                              void* d_out, int out_size)
{
    const float* x      = (const float*)d_in[0];
    const float* W_in   = (const float*)d_in[1];
    const float* W_h1   = (const float*)d_in[2];
    const float* W_h2   = (const float*)d_in[3];
    const float* W_h3   = (const float*)d_in[4];
    const float* W_h4   = (const float*)d_in[5];
    const float* W_out  = (const float*)d_in[6];
    const float* feat_w = (const float*)d_in[7];
    const float* feat_b = (const float*)d_in[8];
    const float* mod_w  = (const float*)d_in[9];
    const float* mod_b  = (const float*)d_in[10];

    float* outF = (float*)d_out;
    float* dout_mod = outF;                       // 2*3*256*256   = 393216
    float* dout_hr  = outF + 393216;              // 2*64*256*256  = 8388608
    float* dout_new = outF + 8781824;             // 8388608
    float* dout_ori = outF + 17170432;            // 8388608
    float* dout_out = outF + 25559040;            // 393216

    float *downx, *outfull, *out256, *ftmp;
    cudaGetSymbolAddress((void**)&downx,   g_down_x);
    cudaGetSymbolAddress((void**)&outfull, g_out_full);
    cudaGetSymbolAddress((void**)&out256,  g_out256);
    cudaGetSymbolAddress((void**)&ftmp,    g_feat_tmp);

    static int smem_set = 0;
    if (!smem_set) {
        cudaFuncSetAttribute(fused_mlp_mma, cudaFuncAttributeMaxDynamicSharedMemorySize,
                             S_TOT);
        smem_set = 1;
    }

    // 1. down_x = bicubic_down2(x)
    k_down2<<<(BB*3*DH*DH + 255)/256, 256>>>(x, downx, nullptr, BB*3, HH);
    // 2. weight split/prep into fp16 hi/lo [k][n]
    k_prep_w<<<320, 256>>>(W_h1, W_h2, W_h3, W_h4, W_out);
    // 3. hr_feature = conv3x3s2(x)  (independent; keeps the MLP as the 4th
    //    launch so ncu captures it)
    {
        dim3 g(16, 16, BB);
        k_conv3x3s2<<<g, 256>>>(x, feat_w, feat_b, dout_hr, 512);
    }
    // 4. fused tensor-core MLP + dynamic-filter apply -> out_full
    fused_mlp_mma<<<MROWS/128, 512, S_TOT>>>(x, W_in, outfull);
    // 5. out = down2(out_full); keep copy for mod conv
    k_down2<<<(BB*3*DH*DH + 255)/256, 256>>>(outfull, out256, dout_out, BB*3, HH);
    // 6. down_x_mod = 1x1 conv(concat(down_x, out))
    k_mod<<<(BB*DH*DH + 255)/256, 256>>>(downx, out256, mod_w, mod_b, dout_mod);
    // 7. ori_lr_feature = up2(conv3x3s2(down_x))
    {
        dim3 g(8, 8, BB);
        k_conv3x3s2<<<g, 256>>>(downx, feat_w, feat_b, ftmp, 256);
    }
    k_up2<<<(BB*64*256*256 + 255)/256, 256>>>(ftmp, dout_ori, BB*64, 128);
    // 8. new_lr_feature = up2(conv3x3s2(down_x_mod))
    {
        dim3 g(8, 8, BB);
        k_conv3x3s2<<<g, 256>>>(dout_mod, feat_w, feat_b, ftmp, 256);
    }
    k_up2<<<(BB*64*256*256 + 255)/256, 256>>>(ftmp, dout_new, BB*64, 128);
}

// round 10
// speedup vs baseline: 1.4109x; 1.4109x over previous
#include <cuda_runtime.h>
#include <cuda_fp16.h>
#include <cstdint>

#define HH 512
#define WW 512
#define DH 256
#define HWp (HH*WW)          // 262144
#define BB 2
#define MROWS (BB*HWp)       // 524288

// ---------------- scratch (device globals; no allocation allowed) ----------
__device__ float g_down_x[BB*3*DH*DH];                 // 1.5 MB
__device__ float g_out_full[BB*3*HH*WW];               // 6 MB
__device__ float g_out256[BB*3*DH*DH];                 // 1.5 MB
__device__ float g_feat_tmp[BB*64*128*128];            // 8 MB
__device__ __align__(16) __half g_wHi[5][16384];       // [k][n] row-major, n padded to 128
__device__ __align__(16) __half g_wLo[5][16384];

// ---------------- mma/ldmatrix/cp.async helpers (base ISA only) -------------
__device__ __forceinline__ uint32_t smem_u32(const void* p) {
    uint32_t a;
    asm("{ .reg .u64 t; cvta.to.shared.u64 t, %1; cvt.u32.u64 %0, t; }" : "=r"(a) : "l"(p));
    return a;
}
__device__ __forceinline__ void ldsm_x4(uint32_t addr, uint32_t r[4]) {
    asm volatile("ldmatrix.sync.aligned.m8n8.x4.shared.b16 {%0,%1,%2,%3}, [%4];"
        : "=r"(r[0]), "=r"(r[1]), "=r"(r[2]), "=r"(r[3]) : "r"(addr));
}
__device__ __forceinline__ void ldsm_x4t(uint32_t addr, uint32_t r[4]) {
    asm volatile("ldmatrix.sync.aligned.m8n8.x4.trans.shared.b16 {%0,%1,%2,%3}, [%4];"
        : "=r"(r[0]), "=r"(r[1]), "=r"(r[2]), "=r"(r[3]) : "r"(addr));
}
__device__ __forceinline__ void mma_f32(float d[4], const uint32_t a[4], const uint32_t* b) {
    asm volatile("mma.sync.aligned.m16n8k16.row.col.f32.f16.f16.f32 "
        "{%0,%1,%2,%3}, {%4,%5,%6,%7}, {%8,%9}, {%0,%1,%2,%3};"
        : "+f"(d[0]), "+f"(d[1]), "+f"(d[2]), "+f"(d[3])
        : "r"(a[0]), "r"(a[1]), "r"(a[2]), "r"(a[3]), "r"(b[0]), "r"(b[1]));
}
__device__ __forceinline__ void mma_f16(uint32_t d[2], const uint32_t a[4], const uint32_t* b) {
    asm volatile("mma.sync.aligned.m16n8k16.row.col.f16.f16.f16.f16 "
        "{%0,%1}, {%2,%3,%4,%5}, {%6,%7}, {%0,%1};"
        : "+r"(d[0]), "+r"(d[1])
        : "r"(a[0]), "r"(a[1]), "r"(a[2]), "r"(a[3]), "r"(b[0]), "r"(b[1]));
}
__device__ __forceinline__ void cp_async16(uint32_t dst, const void* src) {
    asm volatile("cp.async.cg.shared.global [%0], [%1], 16;" :: "r"(dst), "l"(src));
}
#define CP_COMMIT() asm volatile("cp.async.commit_group;" ::: "memory")
#define CP_WAIT(n)  asm volatile("cp.async.wait_group %0;" :: "n"(n) : "memory")

// ---------------- bicubic tap helpers (match jax.image.resize, a=-0.5) -----
__device__ __forceinline__ void taps_down2(int o, int n, int idx[4], float w[4]) {
    const float kw0 = -0.0625f, kw1 = 0.5625f;
    float kw[4] = {kw0, kw1, kw1, kw0};
    float s = 0.f;
#pragma unroll
    for (int t = 0; t < 4; ++t) {
        int i = 2*o - 1 + t;
        bool ok = (i >= 0) && (i < n);
        idx[t] = ok ? i : 0;
        w[t]   = ok ? kw[t] : 0.f;
        s += w[t];
    }
    float inv = 1.f / s;
#pragma unroll
    for (int t = 0; t < 4; ++t) w[t] *= inv;
}
__device__ __forceinline__ void taps_up2(int o, int n, int idx[4], float w[4]) {
    int m = o >> 1;
    float kw[4];
    int base;
    if ((o & 1) == 0) {
        base = m - 2;
        kw[0] = -0.0234375f; kw[1] = 0.2265625f; kw[2] = 0.8671875f; kw[3] = -0.0703125f;
    } else {
        base = m - 1;
        kw[0] = -0.0703125f; kw[1] = 0.8671875f; kw[2] = 0.2265625f; kw[3] = -0.0234375f;
    }
    float s = 0.f;
#pragma unroll
    for (int t = 0; t < 4; ++t) {
        int i = base + t;
        bool ok = (i >= 0) && (i < n);
        idx[t] = ok ? i : 0;
        w[t]   = ok ? kw[t] : 0.f;
        s += w[t];
    }
    float inv = 1.f / s;
#pragma unroll
    for (int t = 0; t < 4; ++t) w[t] *= inv;
}

// ---------------- bicubic 2x down / up --------------------------------------
__global__ void k_down2(const float* __restrict__ in, float* __restrict__ out1,
                        float* __restrict__ out2, int Cn, int n_in)
{
    int n_out = n_in >> 1;
    long total = (long)Cn * n_out * n_out;
    long t = (long)blockIdx.x * blockDim.x + threadIdx.x;
    if (t >= total) return;
    int ox = (int)(t % n_out);
    int oy = (int)((t / n_out) % n_out);
    long c = t / ((long)n_out * n_out);
    int iy[4], ix[4]; float wy[4], wx[4];
    taps_down2(oy, n_in, iy, wy);
    taps_down2(ox, n_in, ix, wx);
    const float* ip = in + c * n_in * n_in;
    float s = 0.f;
#pragma unroll
    for (int a = 0; a < 4; ++a) {
        float r = 0.f;
#pragma unroll
        for (int b2 = 0; b2 < 4; ++b2) r += wx[b2] * ip[iy[a]*n_in + ix[b2]];
        s += wy[a] * r;
    }
    out1[t] = s;
    if (out2) out2[t] = s;
}
__global__ void k_up2(const float* __restrict__ in, float* __restrict__ outp,
                      int Cn, int n_in)
{
    int n_out = n_in << 1;
    long total = (long)Cn * n_out * n_out;
    long t = (long)blockIdx.x * blockDim.x + threadIdx.x;
    if (t >= total) return;
    int ox = (int)(t % n_out);
    int oy = (int)((t / n_out) % n_out);
    long c = t / ((long)n_out * n_out);
    int iy[4], ix[4]; float wy[4], wx[4];
    taps_up2(oy, n_in, iy, wy);
    taps_up2(ox, n_in, ix, wx);
    const float* ip = in + c * n_in * n_in;
    float s = 0.f;
#pragma unroll
    for (int a = 0; a < 4; ++a) {
        float r = 0.f;
#pragma unroll
        for (int b2 = 0; b2 < 4; ++b2) r += wx[b2] * ip[iy[a]*n_in + ix[b2]];
        s += wy[a] * r;
    }
    outp[t] = s;
}

// ---------------- weight prep: f32 -> (hi,lo) fp16, [k][n] n-padded --------
__global__ void k_prep_w(const float* __restrict__ W1, const float* __restrict__ W2,
                         const float* __restrict__ W3, const float* __restrict__ W4,
                         const float* __restrict__ Wout)
{
    int t = blockIdx.x * 256 + threadIdx.x;     // 5*16384 = 81920
    if (t >= 81920) return;
    int L = t >> 14, r = t & 16383;
    int k = r >> 7, n = r & 127;
    const float* W = (L == 0) ? W1 : (L == 1) ? W2 : (L == 2) ? W3 : (L == 3) ? W4 : Wout;
    float v = (L < 4) ? W[k * 128 + n] : ((n < 81) ? W[k * 81 + n] : 0.f);
    __half h = __float2half(v);
    g_wHi[L][r] = h;
    g_wLo[L][r] = __float2half(v - __half2float(h));
}

// ---------------- fused MLP + dynamic-filter apply --------------------------
// M=128 pixels/CTA, 256 threads; 2-term fp16 split (A_hi only);
// double-buffered cp.async weight staging.
#define ROWB 272
#define S_AHI 0                // 128*272 = 34816
#define S_B0  34816            // hi 34816 + lo 34816 = 69632
#define S_B1  104448           // ping-pong; also reused: lwS (128 x 84 f32)
#define S_INP 174080           // 128*8 f32; also x patch (3*3*132 f32)
#define S_WIN 178944           // 7*128 f32
#define S_TOT 182528
#define LWST 84
#define BLO_OFF 34816          // lo half offset within a B buffer

__device__ __forceinline__ void st_hi2(char* smem, int row, int col,
                                       float v0, float v1)
{
    __half2 hp = __floats2half2_rn(v0, v1);
    *(uint32_t*)(smem + S_AHI + row * ROWB + col * 2) = *(uint32_t*)&hp;
}

__global__ __launch_bounds__(256, 1) void fused_mlp_mma(
    const float* __restrict__ x, const float* __restrict__ Win,
    float* __restrict__ outp)
{
    extern __shared__ __align__(16) char smem[];
    const uint32_t sb = smem_u32(smem);
    const int tid = threadIdx.x;
    const int wid = tid >> 5, lane = tid & 31;
    const long row0 = (long)blockIdx.x * 128;
    const int bimg = (int)(row0 >> 18);
    const int n0 = (int)(row0 & (HWp - 1));
    const int irow = n0 >> 9, j0 = n0 & 511;

    // ---- kick off async staging of layer 0 weights into buf0 ----
    {
        const int buf = S_B0;
#pragma unroll
        for (int it = 0; it < 8; ++it) {
            int idx = it * 256 + tid;              // 2048 chunks of 16B
            int row = idx >> 4, col = (idx & 15) * 8;
            uint32_t d = sb + buf + row * ROWB + col * 2;
            cp_async16(d,           (const char*)g_wHi[0] + idx * 16);
            cp_async16(d + BLO_OFF, (const char*)g_wLo[0] + idx * 16);
        }
        CP_COMMIT();
    }

    // ---- stage W_in, per-pixel inputs ----
    for (int i = tid; i < 896; i += 256) *(float*)(smem + S_WIN + i*4) = Win[i];
    if (tid < 128) {
        int i = irow, j = j0 + tid;
        int iy[4], ix[4]; float wy[4], wx[4];
        taps_up2(i, DH, iy, wy);
        taps_up2(j, DH, ix, wx);
        float* ip = (float*)(smem + S_INP) + tid * 8;
        ip[0] = (i & 1) ? 0.5f : -0.5f;
        ip[1] = (j & 1) ? 0.5f : -0.5f;
        ip[2] = 1.f; ip[3] = 1.f;
#pragma unroll
        for (int c = 0; c < 3; ++c) {
            const float* dp = g_down_x + (long)(bimg*3 + c) * DH * DH;
            float s = 0.f;
#pragma unroll
            for (int a = 0; a < 4; ++a) {
                float rr = 0.f;
#pragma unroll
                for (int b2 = 0; b2 < 4; ++b2) rr += wx[b2] * dp[iy[a]*DH + ix[b2]];
                s += wy[a] * rr;
            }
            ip[4 + c] = x[((long)(bimg*3 + c) * HH + i) * WW + j] - s;
        }
        ip[7] = 0.f;
    }
    __syncthreads();

    // ---- layer 0 (7 -> 128) SIMT, write A_hi ----
    {
        int row = tid >> 1;
        int cbase = (tid & 1) * 64;
        const float* ip = (const float*)(smem + S_INP) + row * 8;
        float a0 = ip[0], a1 = ip[1], a2 = ip[2], a3 = ip[3];
        float a4 = ip[4], a5 = ip[5], a6 = ip[6];
        const float* Wn = (const float*)(smem + S_WIN);
#pragma unroll 8
        for (int c = 0; c < 64; c += 2) {
            int o = cbase + c;
            float v0 = a0*Wn[o] + a1*Wn[128+o] + a2*Wn[256+o] + a3*Wn[384+o]
                     + a4*Wn[512+o] + a5*Wn[640+o] + a6*Wn[768+o];
            float v1 = a0*Wn[o+1] + a1*Wn[128+o+1] + a2*Wn[256+o+1] + a3*Wn[384+o+1]
                     + a4*Wn[512+o+1] + a5*Wn[640+o+1] + a6*Wn[768+o+1];
            v0 = v0 > 0.f ? v0 : 0.01f * v0;
            v1 = v1 > 0.f ? v1 : 0.01f * v1;
            st_hi2(smem, row, o, v0, v1);
        }
    }

    // ---- warp tiling: 4 (m) x 2 (n); warp tile = 32 rows x 64 cols ----
    const int wm = wid & 3, wn = wid >> 2;
    const uint32_t aAddr = sb + S_AHI + (uint32_t)((wm*32 + (lane & 15)) * ROWB + (lane >> 4) * 16);
    const uint32_t bOffW = (uint32_t)((lane & 15) * ROWB + (wn*64)*2 + (lane >> 4) * 16);

#pragma unroll 1
    for (int L = 0; L < 5; ++L) {
        const int pbuf = (L & 1) ? S_B1 : S_B0;
        // prefetch next layer's weights into the other buffer
        if (L < 4) {
            const int nbuf = (L & 1) ? S_B0 : S_B1;
#pragma unroll
            for (int it = 0; it < 8; ++it) {
                int idx = it * 256 + tid;
                int row = idx >> 4, col = (idx & 15) * 8;
                uint32_t d = sb + nbuf + row * ROWB + col * 2;
                cp_async16(d,           (const char*)g_wHi[L+1] + idx * 16);
                cp_async16(d + BLO_OFF, (const char*)g_wLo[L+1] + idx * 16);
            }
            CP_COMMIT();
            CP_WAIT(1);     // layer L's group done; L+1 may still be in flight
        } else {
            CP_WAIT(0);
        }
        __syncthreads();    // B[pbuf] visible to all; prior A writes done

        const uint32_t bAddr = sb + pbuf + bOffW;
        float acc[2][8][4];
        uint32_t c16[2][8][2];
#pragma unroll
        for (int mt = 0; mt < 2; ++mt)
#pragma unroll
            for (int nt = 0; nt < 8; ++nt) {
#pragma unroll
                for (int q = 0; q < 4; ++q) acc[mt][nt][q] = 0.f;
                c16[mt][nt][0] = 0u; c16[mt][nt][1] = 0u;
            }

#pragma unroll 1
        for (int k = 0; k < 8; ++k) {
            uint32_t ah[2][4];
#pragma unroll
            for (int mt = 0; mt < 2; ++mt)
                ldsm_x4(aAddr + (uint32_t)(mt * 16 * ROWB + k * 32), ah[mt]);
#pragma unroll
            for (int np = 0; np < 4; ++np) {
                uint32_t bh[4], bl[4];
                uint32_t b = bAddr + (uint32_t)(k * 16 * ROWB + np * 32);
                ldsm_x4t(b, bh);
                ldsm_x4t(b + BLO_OFF, bl);
                // main: fp32 accumulate (same-acc distance 4)
                mma_f32(acc[0][np*2],   ah[0], bh);
                mma_f32(acc[0][np*2+1], ah[0], bh + 2);
                mma_f32(acc[1][np*2],   ah[1], bh);
                mma_f32(acc[1][np*2+1], ah[1], bh + 2);
                // weight-lo correction: fp16 accumulate
                mma_f16(c16[0][np*2],   ah[0], bl);
                mma_f16(c16[0][np*2+1], ah[0], bl + 2);
                mma_f16(c16[1][np*2],   ah[1], bl);
                mma_f16(c16[1][np*2+1], ah[1], bl + 2);
            }
        }
        __syncthreads();   // all warps done reading A/B before overwriting

        if (L < 4) {
#pragma unroll
            for (int mt = 0; mt < 2; ++mt) {
                int r0 = wm*32 + mt*16 + (lane >> 2);
#pragma unroll
                for (int nt = 0; nt < 8; ++nt) {
                    int c = wn*64 + nt*8 + (lane & 3)*2;
                    __half2 p0 = *(__half2*)&c16[mt][nt][0];
                    __half2 p1 = *(__half2*)&c16[mt][nt][1];
                    float v0 = acc[mt][nt][0] + __half2float(p0.x);
                    float v1 = acc[mt][nt][1] + __half2float(p0.y);
                    float w0 = acc[mt][nt][2] + __half2float(p1.x);
                    float w1 = acc[mt][nt][3] + __half2float(p1.y);
                    v0 = v0 > 0.f ? v0 : 0.01f * v0;
                    v1 = v1 > 0.f ? v1 : 0.01f * v1;
                    w0 = w0 > 0.f ? w0 : 0.01f * w0;
                    w1 = w1 > 0.f ? w1 : 0.01f * w1;
                    st_hi2(smem, r0,     c, v0, v1);
                    st_hi2(smem, r0 + 8, c, w0, w1);
                }
            }
        } else {
            // output layer: dump cols < 81 into lwS (overlays idle buf S_B1)
            float* lwS = (float*)(smem + S_B1);
#pragma unroll
            for (int mt = 0; mt < 2; ++mt) {
                int r0 = wm*32 + mt*16 + (lane >> 2);
#pragma unroll
                for (int nt = 0; nt < 8; ++nt) {
                    int c = wn*64 + nt*8 + (lane & 3)*2;
                    __half2 p0 = *(__half2*)&c16[mt][nt][0];
                    __half2 p1 = *(__half2*)&c16[mt][nt][1];
                    if (c < 81) {
                        lwS[r0 * LWST + c]     = acc[mt][nt][0] + __half2float(p0.x);
                        lwS[(r0+8) * LWST + c] = acc[mt][nt][2] + __half2float(p1.x);
                    }
                    if (c + 1 < 81) {
                        lwS[r0 * LWST + c + 1]     = acc[mt][nt][1] + __half2float(p0.y);
                        lwS[(r0+8) * LWST + c + 1] = acc[mt][nt][3] + __half2float(p1.y);
                    }
                }
            }
        }
    }

    // ---- stage 3ch x 3row x 130col x patch (zero padded) ----
    float* xp = (float*)(smem + S_INP);        // [3][3][132]
    for (int idx = tid; idx < 3*3*130; idx += 256) {
        int c = idx / 390, rem = idx % 390, ki = rem / 130, jj = rem % 130;
        int yy = irow + ki - 1;
        int xx = j0 + jj - 1;
        float v = 0.f;
        if (yy >= 0 && yy < HH && xx >= 0 && xx < WW)
            v = x[((long)(bimg*3 + c) * HH + yy) * WW + xx];
        xp[(c*3 + ki) * 132 + jj] = v;
    }
    __syncthreads();

    // ---- apply: 128 pixels x 3 out channels ----
    for (int idx = tid; idx < 384; idx += 256) {
        int p = idx & 127, oc = idx >> 7;
        const float* lwr = (const float*)(smem + S_B1) + p * LWST;
        float o = 0.f;
#pragma unroll
        for (int c = 0; c < 3; ++c)
#pragma unroll
            for (int ki = 0; ki < 3; ++ki) {
                const float* xr = xp + (c*3 + ki) * 132 + p;
#pragma unroll
                for (int kj = 0; kj < 3; ++kj)
                    o += xr[kj] * lwr[(c*9 + ki*3 + kj) * 3 + oc];
            }
        outp[(long)(bimg*3 + oc) * HWp + n0 + p] = o;
    }
}

// ---------------- 3x3 stride-2 pad-1 conv, 3 -> 64 channels -----------------
__global__ __launch_bounds__(256) void k_conv3x3s2(const float* __restrict__ in,
    const float* __restrict__ wt, const float* __restrict__ bias,
    float* __restrict__ outp, int S)
{
    __shared__ float w_s[1728];
    __shared__ float in_s[3][33][33];
    int tid = threadIdx.x;
    for (int i = tid; i < 1728; i += 256) w_s[i] = wt[i];
    int OS = S >> 1;
    int ox0 = blockIdx.x * 16, oy0 = blockIdx.y * 16, b = blockIdx.z;
    for (int idx = tid; idx < 3*33*33; idx += 256) {
        int c = idx / 1089, rem = idx % 1089, r = rem / 33, col = rem % 33;
        int iy = oy0*2 - 1 + r, ix = ox0*2 - 1 + col;
        float v = 0.f;
        if (iy >= 0 && iy < S && ix >= 0 && ix < S)
            v = in[((long)(b*3 + c) * S + iy) * S + ix];
        in_s[c][r][col] = v;
    }
    __syncthreads();
    int ox = tid & 15, oy = tid >> 4;
    float pix[27];
#pragma unroll
    for (int c = 0; c < 3; ++c)
#pragma unroll
        for (int ki = 0; ki < 3; ++ki)
#pragma unroll
            for (int kj = 0; kj < 3; ++kj)
                pix[c*9 + ki*3 + kj] = in_s[c][2*oy + ki][2*ox + kj];
#pragma unroll 4
    for (int oc = 0; oc < 64; ++oc) {
        float acc = bias[oc];
#pragma unroll
        for (int q = 0; q < 27; ++q) acc += pix[q] * w_s[oc*27 + q];
        outp[(((long)b*64 + oc) * OS + oy0 + oy) * OS + ox0 + ox] = acc;
    }
}

// ---------------- 1x1 mod conv ----------------------------------------------
__global__ void k_mod(const float* __restrict__ dx, const float* __restrict__ o256,
                      const float* __restrict__ mw, const float* __restrict__ mb,
                      float* __restrict__ outp)
{
    int t = blockIdx.x * 256 + threadIdx.x;
    if (t >= BB * DH * DH) return;
    int b = t >> 16, p = t & 65535;
    float in6[6];
#pragma unroll
    for (int c = 0; c < 3; ++c) in6[c]     = dx[(b*3 + c)*65536 + p];
#pragma unroll
    for (int c = 0; c < 3; ++c) in6[3 + c] = o256[(b*3 + c)*65536 + p];
#pragma unroll
    for (int oc = 0; oc < 3; ++oc) {
        float a = mb[oc];
#pragma unroll
        for (int ic = 0; ic < 6; ++ic) a += in6[ic] * mw[oc*6 + ic];
        outp[(b*3 + oc)*65536 + p] = a;
    }
}

// ---------------- launch -----------------------------------------------------
extern "C" void kernel_launch(void* const* d_in, const int* in_sizes, int n_in,
                              void* d_out, int out_size)
{
    const float* x      = (const float*)d_in[0];
    const float* W_in   = (const float*)d_in[1];
    const float* W_h1   = (const float*)d_in[2];
    const float* W_h2   = (const float*)d_in[3];
    const float* W_h3   = (const float*)d_in[4];
    const float* W_h4   = (const float*)d_in[5];
    const float* W_out  = (const float*)d_in[6];
    const float* feat_w = (const float*)d_in[7];
    const float* feat_b = (const float*)d_in[8];
    const float* mod_w  = (const float*)d_in[9];
    const float* mod_b  = (const float*)d_in[10];

    float* outF = (float*)d_out;
    float* dout_mod = outF;                       // 2*3*256*256   = 393216
    float* dout_hr  = outF + 393216;              // 2*64*256*256  = 8388608
    float* dout_new = outF + 8781824;             // 8388608
    float* dout_ori = outF + 17170432;            // 8388608
    float* dout_out = outF + 25559040;            // 393216

    float *downx, *outfull, *out256, *ftmp;
    cudaGetSymbolAddress((void**)&downx,   g_down_x);
    cudaGetSymbolAddress((void**)&outfull, g_out_full);
    cudaGetSymbolAddress((void**)&out256,  g_out256);
    cudaGetSymbolAddress((void**)&ftmp,    g_feat_tmp);

    static int smem_set = 0;
    if (!smem_set) {
        cudaFuncSetAttribute(fused_mlp_mma, cudaFuncAttributeMaxDynamicSharedMemorySize,
                             S_TOT);
        smem_set = 1;
    }

    // 1. down_x = bicubic_down2(x)
    k_down2<<<(BB*3*DH*DH + 255)/256, 256>>>(x, downx, nullptr, BB*3, HH);
    // 2. weight split/prep into fp16 hi/lo [k][n]
    k_prep_w<<<320, 256>>>(W_h1, W_h2, W_h3, W_h4, W_out);
    // 3. hr_feature = conv3x3s2(x)  (keeps the MLP as the 4th launch for ncu)
    {
        dim3 g(16, 16, BB);
        k_conv3x3s2<<<g, 256>>>(x, feat_w, feat_b, dout_hr, 512);
    }
    // 4. fused tensor-core MLP + dynamic-filter apply -> out_full
    fused_mlp_mma<<<MROWS/128, 256, S_TOT>>>(x, W_in, outfull);
    // 5. out = down2(out_full); keep copy for mod conv
    k_down2<<<(BB*3*DH*DH + 255)/256, 256>>>(outfull, out256, dout_out, BB*3, HH);
    // 6. down_x_mod = 1x1 conv(concat(down_x, out))
    k_mod<<<(BB*DH*DH + 255)/256, 256>>>(downx, out256, mod_w, mod_b, dout_mod);
    // 7. ori_lr_feature = up2(conv3x3s2(down_x))
    {
        dim3 g(8, 8, BB);
        k_conv3x3s2<<<g, 256>>>(downx, feat_w, feat_b, ftmp, 256);
    }
    k_up2<<<(BB*64*256*256 + 255)/256, 256>>>(ftmp, dout_ori, BB*64, 128);
    // 8. new_lr_feature = up2(conv3x3s2(down_x_mod))
    {
        dim3 g(8, 8, BB);
        k_conv3x3s2<<<g, 256>>>(dout_mod, feat_w, feat_b, ftmp, 256);
    }
    k_up2<<<(BB*64*256*256 + 255)/256, 256>>>(ftmp, dout_new, BB*64, 128);
}

// round 11
// speedup vs baseline: 1.6754x; 1.1875x over previous
#include <cuda_runtime.h>
#include <cuda_fp16.h>
#include <cstdint>

#define HH 512
#define WW 512
#define DH 256
#define HWp (HH*WW)          // 262144
#define BB 2
#define MROWS (BB*HWp)       // 524288

// ---------------- scratch (device globals; no allocation allowed) ----------
__device__ float g_down_x[BB*3*DH*DH];                 // 1.5 MB
__device__ float g_out_full[BB*3*HH*WW];               // 6 MB
__device__ float g_out256[BB*3*DH*DH];                 // 1.5 MB
__device__ float g_feat_tmp[BB*64*128*128];            // 8 MB
__device__ __align__(16) __half g_wHi[5][16384];       // [k][n] row-major, n padded to 128
__device__ __align__(16) __half g_wLo[5][16384];

// ---------------- mma/ldmatrix/cp.async helpers (base ISA only) -------------
__device__ __forceinline__ uint32_t smem_u32(const void* p) {
    uint32_t a;
    asm("{ .reg .u64 t; cvta.to.shared.u64 t, %1; cvt.u32.u64 %0, t; }" : "=r"(a) : "l"(p));
    return a;
}
__device__ __forceinline__ void ldsm_x4(uint32_t addr, uint32_t r[4]) {
    asm volatile("ldmatrix.sync.aligned.m8n8.x4.shared.b16 {%0,%1,%2,%3}, [%4];"
        : "=r"(r[0]), "=r"(r[1]), "=r"(r[2]), "=r"(r[3]) : "r"(addr));
}
__device__ __forceinline__ void ldsm_x4t(uint32_t addr, uint32_t r[4]) {
    asm volatile("ldmatrix.sync.aligned.m8n8.x4.trans.shared.b16 {%0,%1,%2,%3}, [%4];"
        : "=r"(r[0]), "=r"(r[1]), "=r"(r[2]), "=r"(r[3]) : "r"(addr));
}
__device__ __forceinline__ void mma_f32(float d[4], const uint32_t a[4], const uint32_t* b) {
    asm volatile("mma.sync.aligned.m16n8k16.row.col.f32.f16.f16.f32 "
        "{%0,%1,%2,%3}, {%4,%5,%6,%7}, {%8,%9}, {%0,%1,%2,%3};"
        : "+f"(d[0]), "+f"(d[1]), "+f"(d[2]), "+f"(d[3])
        : "r"(a[0]), "r"(a[1]), "r"(a[2]), "r"(a[3]), "r"(b[0]), "r"(b[1]));
}
__device__ __forceinline__ void mma_f16(uint32_t d[2], const uint32_t a[4], const uint32_t* b) {
    asm volatile("mma.sync.aligned.m16n8k16.row.col.f16.f16.f16.f16 "
        "{%0,%1}, {%2,%3,%4,%5}, {%6,%7}, {%0,%1};"
        : "+r"(d[0]), "+r"(d[1])
        : "r"(a[0]), "r"(a[1]), "r"(a[2]), "r"(a[3]), "r"(b[0]), "r"(b[1]));
}
__device__ __forceinline__ void cp_async16(uint32_t dst, const void* src) {
    asm volatile("cp.async.cg.shared.global [%0], [%1], 16;" :: "r"(dst), "l"(src));
}
#define CP_COMMIT() asm volatile("cp.async.commit_group;" ::: "memory")
#define CP_WAIT(n)  asm volatile("cp.async.wait_group %0;" :: "n"(n) : "memory")

// XOR-swizzled tile addressing: 256B rows, 16B units permuted by row&7
__device__ __forceinline__ uint32_t swz(int row, int cg) {
    return (uint32_t)(row * 256 + ((cg ^ (row & 7)) << 4));
}

// ---------------- bicubic tap helpers (match jax.image.resize, a=-0.5) -----
__device__ __forceinline__ void taps_down2(int o, int n, int idx[4], float w[4]) {
    const float kw0 = -0.0625f, kw1 = 0.5625f;
    float kw[4] = {kw0, kw1, kw1, kw0};
    float s = 0.f;
#pragma unroll
    for (int t = 0; t < 4; ++t) {
        int i = 2*o - 1 + t;
        bool ok = (i >= 0) && (i < n);
        idx[t] = ok ? i : 0;
        w[t]   = ok ? kw[t] : 0.f;
        s += w[t];
    }
    float inv = 1.f / s;
#pragma unroll
    for (int t = 0; t < 4; ++t) w[t] *= inv;
}
__device__ __forceinline__ void taps_up2(int o, int n, int idx[4], float w[4]) {
    int m = o >> 1;
    float kw[4];
    int base;
    if ((o & 1) == 0) {
        base = m - 2;
        kw[0] = -0.0234375f; kw[1] = 0.2265625f; kw[2] = 0.8671875f; kw[3] = -0.0703125f;
    } else {
        base = m - 1;
        kw[0] = -0.0703125f; kw[1] = 0.8671875f; kw[2] = 0.2265625f; kw[3] = -0.0234375f;
    }
    float s = 0.f;
#pragma unroll
    for (int t = 0; t < 4; ++t) {
        int i = base + t;
        bool ok = (i >= 0) && (i < n);
        idx[t] = ok ? i : 0;
        w[t]   = ok ? kw[t] : 0.f;
        s += w[t];
    }
    float inv = 1.f / s;
#pragma unroll
    for (int t = 0; t < 4; ++t) w[t] *= inv;
}

// ---------------- bicubic 2x down / up --------------------------------------
__global__ void k_down2(const float* __restrict__ in, float* __restrict__ out1,
                        float* __restrict__ out2, int Cn, int n_in)
{
    int n_out = n_in >> 1;
    long total = (long)Cn * n_out * n_out;
    long t = (long)blockIdx.x * blockDim.x + threadIdx.x;
    if (t >= total) return;
    int ox = (int)(t % n_out);
    int oy = (int)((t / n_out) % n_out);
    long c = t / ((long)n_out * n_out);
    int iy[4], ix[4]; float wy[4], wx[4];
    taps_down2(oy, n_in, iy, wy);
    taps_down2(ox, n_in, ix, wx);
    const float* ip = in + c * n_in * n_in;
    float s = 0.f;
#pragma unroll
    for (int a = 0; a < 4; ++a) {
        float r = 0.f;
#pragma unroll
        for (int b2 = 0; b2 < 4; ++b2) r += wx[b2] * ip[iy[a]*n_in + ix[b2]];
        s += wy[a] * r;
    }
    out1[t] = s;
    if (out2) out2[t] = s;
}
__global__ void k_up2(const float* __restrict__ in, float* __restrict__ outp,
                      int Cn, int n_in)
{
    int n_out = n_in << 1;
    long total = (long)Cn * n_out * n_out;
    long t = (long)blockIdx.x * blockDim.x + threadIdx.x;
    if (t >= total) return;
    int ox = (int)(t % n_out);
    int oy = (int)((t / n_out) % n_out);
    long c = t / ((long)n_out * n_out);
    int iy[4], ix[4]; float wy[4], wx[4];
    taps_up2(oy, n_in, iy, wy);
    taps_up2(ox, n_in, ix, wx);
    const float* ip = in + c * n_in * n_in;
    float s = 0.f;
#pragma unroll
    for (int a = 0; a < 4; ++a) {
        float r = 0.f;
#pragma unroll
        for (int b2 = 0; b2 < 4; ++b2) r += wx[b2] * ip[iy[a]*n_in + ix[b2]];
        s += wy[a] * r;
    }
    outp[t] = s;
}

// ---------------- weight prep: f32 -> (hi,lo) fp16, [k][n] n-padded --------
__global__ void k_prep_w(const float* __restrict__ W1, const float* __restrict__ W2,
                         const float* __restrict__ W3, const float* __restrict__ W4,
                         const float* __restrict__ Wout)
{
    int t = blockIdx.x * 256 + threadIdx.x;     // 5*16384 = 81920
    if (t >= 81920) return;
    int L = t >> 14, r = t & 16383;
    int k = r >> 7, n = r & 127;
    const float* W = (L == 0) ? W1 : (L == 1) ? W2 : (L == 2) ? W3 : (L == 3) ? W4 : Wout;
    float v = (L < 4) ? W[k * 128 + n] : ((n < 81) ? W[k * 81 + n] : 0.f);
    __half h = __float2half(v);
    g_wHi[L][r] = h;
    g_wLo[L][r] = __float2half(v - __half2float(h));
}

// ---------------- fused MLP + dynamic-filter apply --------------------------
// M=128 pixels/CTA, 256 threads, 103.5KB smem -> 2 CTAs/SM.
// 2-term fp16 split; XOR-swizzled 256B rows; single B buffer with
// cp.async staging overlapped with the epilogue.
#define S_A   0                // 128*256 = 32768
#define S_BHI 32768            // 32768
#define S_BLO 65536            // 32768
#define S_LW  32768            // overlays B after last layer (128*84*4=43008)
#define S_INP 98304            // 128*8 f32 = 4096; later x patch (3*3*132 f32)
#define S_WIN 102400           // 7*128 f32 = 3584
#define S_TOT 105984
#define LWST 84

__device__ __forceinline__ void st_hi2(char* smem, int row, int col,
                                       float v0, float v1)
{
    __half2 hp = __floats2half2_rn(v0, v1);
    *(uint32_t*)(smem + S_A + swz(row, col >> 3) + (col & 7) * 2) = *(uint32_t*)&hp;
}

__global__ __launch_bounds__(256, 2) void fused_mlp_mma(
    const float* __restrict__ x, const float* __restrict__ Win,
    float* __restrict__ outp)
{
    extern __shared__ __align__(16) char smem[];
    const uint32_t sb = smem_u32(smem);
    const int tid = threadIdx.x;
    const int wid = tid >> 5, lane = tid & 31;
    const long row0 = (long)blockIdx.x * 128;
    const int bimg = (int)(row0 >> 18);
    const int n0 = (int)(row0 & (HWp - 1));
    const int irow = n0 >> 9, j0 = n0 & 511;

    // ---- async stage of layer-0 weights (overlaps input compute) ----
#pragma unroll
    for (int it = 0; it < 8; ++it) {
        int idx = it * 256 + tid;              // 2048 chunks of 16B
        int row = idx >> 4, cg = idx & 15;
        uint32_t d = sb + S_BHI + swz(row, cg);
        cp_async16(d,         (const char*)g_wHi[0] + idx * 16);
        cp_async16(d + 32768, (const char*)g_wLo[0] + idx * 16);
    }
    CP_COMMIT();

    // ---- stage W_in, per-pixel inputs ----
    for (int i = tid; i < 896; i += 256) *(float*)(smem + S_WIN + i*4) = Win[i];
    if (tid < 128) {
        int i = irow, j = j0 + tid;
        int iy[4], ix[4]; float wy[4], wx[4];
        taps_up2(i, DH, iy, wy);
        taps_up2(j, DH, ix, wx);
        float* ip = (float*)(smem + S_INP) + tid * 8;
        ip[0] = (i & 1) ? 0.5f : -0.5f;
        ip[1] = (j & 1) ? 0.5f : -0.5f;
        ip[2] = 1.f; ip[3] = 1.f;
#pragma unroll
        for (int c = 0; c < 3; ++c) {
            const float* dp = g_down_x + (long)(bimg*3 + c) * DH * DH;
            float s = 0.f;
#pragma unroll
            for (int a = 0; a < 4; ++a) {
                float rr = 0.f;
#pragma unroll
                for (int b2 = 0; b2 < 4; ++b2) rr += wx[b2] * dp[iy[a]*DH + ix[b2]];
                s += wy[a] * rr;
            }
            ip[4 + c] = x[((long)(bimg*3 + c) * HH + i) * WW + j] - s;
        }
        ip[7] = 0.f;
    }
    __syncthreads();

    // ---- layer 0 (7 -> 128) SIMT, write A_hi ----
    {
        int row = tid >> 1;
        int cbase = (tid & 1) * 64;
        const float* ip = (const float*)(smem + S_INP) + row * 8;
        float a0 = ip[0], a1 = ip[1], a2 = ip[2], a3 = ip[3];
        float a4 = ip[4], a5 = ip[5], a6 = ip[6];
        const float* Wn = (const float*)(smem + S_WIN);
#pragma unroll 8
        for (int c = 0; c < 64; c += 2) {
            int o = cbase + c;
            float v0 = a0*Wn[o] + a1*Wn[128+o] + a2*Wn[256+o] + a3*Wn[384+o]
                     + a4*Wn[512+o] + a5*Wn[640+o] + a6*Wn[768+o];
            float v1 = a0*Wn[o+1] + a1*Wn[128+o+1] + a2*Wn[256+o+1] + a3*Wn[384+o+1]
                     + a4*Wn[512+o+1] + a5*Wn[640+o+1] + a6*Wn[768+o+1];
            v0 = v0 > 0.f ? v0 : 0.01f * v0;
            v1 = v1 > 0.f ? v1 : 0.01f * v1;
            st_hi2(smem, row, o, v0, v1);
        }
    }

    // ---- warp tiling: 2 (m) x 4 (n); warp tile = 64 rows x 32 cols ----
    // (minimizes smem re-reads: cost = nw*|A| + mw*|B|)
    const int wm = wid & 1, wn = wid >> 1;
    const int lr = lane & 15, lh = lane >> 4, lx = lane & 7;

#pragma unroll 1
    for (int L = 0; L < 5; ++L) {
        CP_WAIT(0);
        __syncthreads();    // B staged + A writes visible

        float acc[4][4][4];
        uint32_t c16[4][4][2];
#pragma unroll
        for (int mt = 0; mt < 4; ++mt)
#pragma unroll
            for (int nt = 0; nt < 4; ++nt) {
#pragma unroll
                for (int q = 0; q < 4; ++q) acc[mt][nt][q] = 0.f;
                c16[mt][nt][0] = 0u; c16[mt][nt][1] = 0u;
            }

#pragma unroll 1
        for (int k = 0; k < 8; ++k) {
            uint32_t ah[4][4];
#pragma unroll
            for (int mt = 0; mt < 4; ++mt) {
                uint32_t a = sb + S_A
                    + (uint32_t)((wm*64 + mt*16 + lr) * 256)
                    + (uint32_t)((((k*2 + lh) ^ lx)) << 4);
                ldsm_x4(a, ah[mt]);
            }
#pragma unroll
            for (int np = 0; np < 2; ++np) {
                uint32_t bh[4], bl[4];
                uint32_t b = sb + S_BHI
                    + (uint32_t)((k*16 + lr) * 256)
                    + (uint32_t)(((wn*4 + np*2 + lh) ^ lx) << 4);
                ldsm_x4t(b, bh);
                ldsm_x4t(b + 32768, bl);
                // main: fp32 accumulate (same-acc distance 8)
                mma_f32(acc[0][np*2],   ah[0], bh);
                mma_f32(acc[0][np*2+1], ah[0], bh + 2);
                mma_f32(acc[1][np*2],   ah[1], bh);
                mma_f32(acc[1][np*2+1], ah[1], bh + 2);
                mma_f32(acc[2][np*2],   ah[2], bh);
                mma_f32(acc[2][np*2+1], ah[2], bh + 2);
                mma_f32(acc[3][np*2],   ah[3], bh);
                mma_f32(acc[3][np*2+1], ah[3], bh + 2);
                // weight-lo correction: fp16 accumulate
                mma_f16(c16[0][np*2],   ah[0], bl);
                mma_f16(c16[0][np*2+1], ah[0], bl + 2);
                mma_f16(c16[1][np*2],   ah[1], bl);
                mma_f16(c16[1][np*2+1], ah[1], bl + 2);
                mma_f16(c16[2][np*2],   ah[2], bl);
                mma_f16(c16[2][np*2+1], ah[2], bl + 2);
                mma_f16(c16[3][np*2],   ah[3], bl);
                mma_f16(c16[3][np*2+1], ah[3], bl + 2);
            }
        }
        __syncthreads();   // all warps done reading A/B

        // prefetch next layer's weights now; flight covered by epilogue
        if (L < 4) {
#pragma unroll
            for (int it = 0; it < 8; ++it) {
                int idx = it * 256 + tid;
                int row = idx >> 4, cg = idx & 15;
                uint32_t d = sb + S_BHI + swz(row, cg);
                cp_async16(d,         (const char*)g_wHi[L+1] + idx * 16);
                cp_async16(d + 32768, (const char*)g_wLo[L+1] + idx * 16);
            }
            CP_COMMIT();

#pragma unroll
            for (int mt = 0; mt < 4; ++mt) {
                int r0 = wm*64 + mt*16 + (lane >> 2);
#pragma unroll
                for (int nt = 0; nt < 4; ++nt) {
                    int c = wn*32 + nt*8 + (lane & 3)*2;
                    __half2 p0 = *(__half2*)&c16[mt][nt][0];
                    __half2 p1 = *(__half2*)&c16[mt][nt][1];
                    float v0 = acc[mt][nt][0] + __half2float(p0.x);
                    float v1 = acc[mt][nt][1] + __half2float(p0.y);
                    float w0 = acc[mt][nt][2] + __half2float(p1.x);
                    float w1 = acc[mt][nt][3] + __half2float(p1.y);
                    v0 = v0 > 0.f ? v0 : 0.01f * v0;
                    v1 = v1 > 0.f ? v1 : 0.01f * v1;
                    w0 = w0 > 0.f ? w0 : 0.01f * w0;
                    w1 = w1 > 0.f ? w1 : 0.01f * w1;
                    st_hi2(smem, r0,     c, v0, v1);
                    st_hi2(smem, r0 + 8, c, w0, w1);
                }
            }
        } else {
            // output layer: dump cols < 81 into lwS (overlays B region)
            float* lwS = (float*)(smem + S_LW);
#pragma unroll
            for (int mt = 0; mt < 4; ++mt) {
                int r0 = wm*64 + mt*16 + (lane >> 2);
#pragma unroll
                for (int nt = 0; nt < 4; ++nt) {
                    int c = wn*32 + nt*8 + (lane & 3)*2;
                    __half2 p0 = *(__half2*)&c16[mt][nt][0];
                    __half2 p1 = *(__half2*)&c16[mt][nt][1];
                    if (c < 81) {
                        lwS[r0 * LWST + c]     = acc[mt][nt][0] + __half2float(p0.x);
                        lwS[(r0+8) * LWST + c] = acc[mt][nt][2] + __half2float(p1.x);
                    }
                    if (c + 1 < 81) {
                        lwS[r0 * LWST + c + 1]     = acc[mt][nt][1] + __half2float(p0.y);
                        lwS[(r0+8) * LWST + c + 1] = acc[mt][nt][3] + __half2float(p1.y);
                    }
                }
            }
        }
    }

    // ---- stage 3ch x 3row x 130col x patch (zero padded) ----
    float* xp = (float*)(smem + S_INP);        // [3][3][132]
    for (int idx = tid; idx < 3*3*130; idx += 256) {
        int c = idx / 390, rem = idx % 390, ki = rem / 130, jj = rem % 130;
        int yy = irow + ki - 1;
        int xx = j0 + jj - 1;
        float v = 0.f;
        if (yy >= 0 && yy < HH && xx >= 0 && xx < WW)
            v = x[((long)(bimg*3 + c) * HH + yy) * WW + xx];
        xp[(c*3 + ki) * 132 + jj] = v;
    }
    __syncthreads();

    // ---- apply: 128 pixels x 3 out channels ----
    for (int idx = tid; idx < 384; idx += 256) {
        int p = idx & 127, oc = idx >> 7;
        const float* lwr = (const float*)(smem + S_LW) + p * LWST;
        float o = 0.f;
#pragma unroll
        for (int c = 0; c < 3; ++c)
#pragma unroll
            for (int ki = 0; ki < 3; ++ki) {
                const float* xr = xp + (c*3 + ki) * 132 + p;
#pragma unroll
                for (int kj = 0; kj < 3; ++kj)
                    o += xr[kj] * lwr[(c*9 + ki*3 + kj) * 3 + oc];
            }
        outp[(long)(bimg*3 + oc) * HWp + n0 + p] = o;
    }
}

// ---------------- 3x3 stride-2 pad-1 conv, 3 -> 64 channels -----------------
__global__ __launch_bounds__(256) void k_conv3x3s2(const float* __restrict__ in,
    const float* __restrict__ wt, const float* __restrict__ bias,
    float* __restrict__ outp, int S)
{
    __shared__ float w_s[1728];
    __shared__ float in_s[3][33][33];
    int tid = threadIdx.x;
    for (int i = tid; i < 1728; i += 256) w_s[i] = wt[i];
    int OS = S >> 1;
    int ox0 = blockIdx.x * 16, oy0 = blockIdx.y * 16, b = blockIdx.z;
    for (int idx = tid; idx < 3*33*33; idx += 256) {
        int c = idx / 1089, rem = idx % 1089, r = rem / 33, col = rem % 33;
        int iy = oy0*2 - 1 + r, ix = ox0*2 - 1 + col;
        float v = 0.f;
        if (iy >= 0 && iy < S && ix >= 0 && ix < S)
            v = in[((long)(b*3 + c) * S + iy) * S + ix];
        in_s[c][r][col] = v;
    }
    __syncthreads();
    int ox = tid & 15, oy = tid >> 4;
    float pix[27];
#pragma unroll
    for (int c = 0; c < 3; ++c)
#pragma unroll
        for (int ki = 0; ki < 3; ++ki)
#pragma unroll
            for (int kj = 0; kj < 3; ++kj)
                pix[c*9 + ki*3 + kj] = in_s[c][2*oy + ki][2*ox + kj];
#pragma unroll 4
    for (int oc = 0; oc < 64; ++oc) {
        float acc = bias[oc];
#pragma unroll
        for (int q = 0; q < 27; ++q) acc += pix[q] * w_s[oc*27 + q];
        outp[(((long)b*64 + oc) * OS + oy0 + oy) * OS + ox0 + ox] = acc;
    }
}

// ---------------- 1x1 mod conv ----------------------------------------------
__global__ void k_mod(const float* __restrict__ dx, const float* __restrict__ o256,
                      const float* __restrict__ mw, const float* __restrict__ mb,
                      float* __restrict__ outp)
{
    int t = blockIdx.x * 256 + threadIdx.x;
    if (t >= BB * DH * DH) return;
    int b = t >> 16, p = t & 65535;
    float in6[6];
#pragma unroll
    for (int c = 0; c < 3; ++c) in6[c]     = dx[(b*3 + c)*65536 + p];
#pragma unroll
    for (int c = 0; c < 3; ++c) in6[3 + c] = o256[(b*3 + c)*65536 + p];
#pragma unroll
    for (int oc = 0; oc < 3; ++oc) {
        float a = mb[oc];
#pragma unroll
        for (int ic = 0; ic < 6; ++ic) a += in6[ic] * mw[oc*6 + ic];
        outp[(b*3 + oc)*65536 + p] = a;
    }
}

// ---------------- launch -----------------------------------------------------
extern "C" void kernel_launch(void* const* d_in, const int* in_sizes, int n_in,
                              void* d_out, int out_size)
{
    const float* x      = (const float*)d_in[0];
    const float* W_in   = (const float*)d_in[1];
    const float* W_h1   = (const float*)d_in[2];
    const float* W_h2   = (const float*)d_in[3];
    const float* W_h3   = (const float*)d_in[4];
    const float* W_h4   = (const float*)d_in[5];
    const float* W_out  = (const float*)d_in[6];
    const float* feat_w = (const float*)d_in[7];
    const float* feat_b = (const float*)d_in[8];
    const float* mod_w  = (const float*)d_in[9];
    const float* mod_b  = (const float*)d_in[10];

    float* outF = (float*)d_out;
    float* dout_mod = outF;                       // 2*3*256*256   = 393216
    float* dout_hr  = outF + 393216;              // 2*64*256*256  = 8388608
    float* dout_new = outF + 8781824;             // 8388608
    float* dout_ori = outF + 17170432;            // 8388608
    float* dout_out = outF + 25559040;            // 393216

    float *downx, *outfull, *out256, *ftmp;
    cudaGetSymbolAddress((void**)&downx,   g_down_x);
    cudaGetSymbolAddress((void**)&outfull, g_out_full);
    cudaGetSymbolAddress((void**)&out256,  g_out256);
    cudaGetSymbolAddress((void**)&ftmp,    g_feat_tmp);

    static int smem_set = 0;
    if (!smem_set) {
        cudaFuncSetAttribute(fused_mlp_mma, cudaFuncAttributeMaxDynamicSharedMemorySize,
                             S_TOT);
        smem_set = 1;
    }

    // 1. down_x = bicubic_down2(x)
    k_down2<<<(BB*3*DH*DH + 255)/256, 256>>>(x, downx, nullptr, BB*3, HH);
    // 2. weight split/prep into fp16 hi/lo [k][n]
    k_prep_w<<<320, 256>>>(W_h1, W_h2, W_h3, W_h4, W_out);
    // 3. hr_feature = conv3x3s2(x)  (keeps the MLP as the 4th launch for ncu)
    {
        dim3 g(16, 16, BB);
        k_conv3x3s2<<<g, 256>>>(x, feat_w, feat_b, dout_hr, 512);
    }
    // 4. fused tensor-core MLP + dynamic-filter apply -> out_full
    fused_mlp_mma<<<MROWS/128, 256, S_TOT>>>(x, W_in, outfull);
    // 5. out = down2(out_full); keep copy for mod conv
    k_down2<<<(BB*3*DH*DH + 255)/256, 256>>>(outfull, out256, dout_out, BB*3, HH);
    // 6. down_x_mod = 1x1 conv(concat(down_x, out))
    k_mod<<<(BB*DH*DH + 255)/256, 256>>>(downx, out256, mod_w, mod_b, dout_mod);
    // 7. ori_lr_feature = up2(conv3x3s2(down_x))
    {
        dim3 g(8, 8, BB);
        k_conv3x3s2<<<g, 256>>>(downx, feat_w, feat_b, ftmp, 256);
    }
    k_up2<<<(BB*64*256*256 + 255)/256, 256>>>(ftmp, dout_ori, BB*64, 128);
    // 8. new_lr_feature = up2(conv3x3s2(down_x_mod))
    {
        dim3 g(8, 8, BB);
        k_conv3x3s2<<<g, 256>>>(dout_mod, feat_w, feat_b, ftmp, 256);
    }
    k_up2<<<(BB*64*256*256 + 255)/256, 256>>>(ftmp, dout_new, BB*64, 128);
}

// round 12
// speedup vs baseline: 1.7268x; 1.0307x over previous
#include <cuda_runtime.h>
#include <cuda_fp16.h>
#include <cstdint>

#define HH 512
#define WW 512
#define DH 256
#define HWp (HH*WW)          // 262144
#define BB 2
#define MROWS (BB*HWp)       // 524288

// ---------------- scratch (device globals; no allocation allowed) ----------
__device__ float g_down_x[BB*3*DH*DH];                 // 1.5 MB
__device__ float g_out_full[BB*3*HH*WW];               // 6 MB
__device__ float g_feat_tmp[BB*64*128*128];            // 8 MB
__device__ float g_feat_tmp2[BB*64*128*128];           // 8 MB
__device__ __align__(16) __half g_wHi[5][16384];       // [k][n] row-major, n padded to 128
__device__ __align__(16) __half g_wLo[5][16384];

// ---------------- mma/ldmatrix/cp.async helpers (base ISA only) -------------
__device__ __forceinline__ uint32_t smem_u32(const void* p) {
    uint32_t a;
    asm("{ .reg .u64 t; cvta.to.shared.u64 t, %1; cvt.u32.u64 %0, t; }" : "=r"(a) : "l"(p));
    return a;
}
__device__ __forceinline__ void ldsm_x4(uint32_t addr, uint32_t r[4]) {
    asm volatile("ldmatrix.sync.aligned.m8n8.x4.shared.b16 {%0,%1,%2,%3}, [%4];"
        : "=r"(r[0]), "=r"(r[1]), "=r"(r[2]), "=r"(r[3]) : "r"(addr));
}
__device__ __forceinline__ void ldsm_x4t(uint32_t addr, uint32_t r[4]) {
    asm volatile("ldmatrix.sync.aligned.m8n8.x4.trans.shared.b16 {%0,%1,%2,%3}, [%4];"
        : "=r"(r[0]), "=r"(r[1]), "=r"(r[2]), "=r"(r[3]) : "r"(addr));
}
__device__ __forceinline__ void mma_f32(float d[4], const uint32_t a[4], const uint32_t* b) {
    asm volatile("mma.sync.aligned.m16n8k16.row.col.f32.f16.f16.f32 "
        "{%0,%1,%2,%3}, {%4,%5,%6,%7}, {%8,%9}, {%0,%1,%2,%3};"
        : "+f"(d[0]), "+f"(d[1]), "+f"(d[2]), "+f"(d[3])
        : "r"(a[0]), "r"(a[1]), "r"(a[2]), "r"(a[3]), "r"(b[0]), "r"(b[1]));
}
__device__ __forceinline__ void mma_f16(uint32_t d[2], const uint32_t a[4], const uint32_t* b) {
    asm volatile("mma.sync.aligned.m16n8k16.row.col.f16.f16.f16.f16 "
        "{%0,%1}, {%2,%3,%4,%5}, {%6,%7}, {%0,%1};"
        : "+r"(d[0]), "+r"(d[1])
        : "r"(a[0]), "r"(a[1]), "r"(a[2]), "r"(a[3]), "r"(b[0]), "r"(b[1]));
}
__device__ __forceinline__ void cp_async16(uint32_t dst, const void* src) {
    asm volatile("cp.async.cg.shared.global [%0], [%1], 16;" :: "r"(dst), "l"(src));
}
#define CP_COMMIT() asm volatile("cp.async.commit_group;" ::: "memory")
#define CP_WAIT(n)  asm volatile("cp.async.wait_group %0;" :: "n"(n) : "memory")

// XOR-swizzled tile addressing: 256B rows, 16B units permuted by row&7
__device__ __forceinline__ uint32_t swz(int row, int cg) {
    return (uint32_t)(row * 256 + ((cg ^ (row & 7)) << 4));
}

// ---------------- bicubic tap helpers (match jax.image.resize, a=-0.5) -----
__device__ __forceinline__ void taps_down2(int o, int n, int idx[4], float w[4]) {
    const float kw0 = -0.0625f, kw1 = 0.5625f;
    float kw[4] = {kw0, kw1, kw1, kw0};
    float s = 0.f;
#pragma unroll
    for (int t = 0; t < 4; ++t) {
        int i = 2*o - 1 + t;
        bool ok = (i >= 0) && (i < n);
        idx[t] = ok ? i : 0;
        w[t]   = ok ? kw[t] : 0.f;
        s += w[t];
    }
    float inv = 1.f / s;
#pragma unroll
    for (int t = 0; t < 4; ++t) w[t] *= inv;
}
__device__ __forceinline__ void taps_up2(int o, int n, int idx[4], float w[4]) {
    int m = o >> 1;
    float kw[4];
    int base;
    if ((o & 1) == 0) {
        base = m - 2;
        kw[0] = -0.0234375f; kw[1] = 0.2265625f; kw[2] = 0.8671875f; kw[3] = -0.0703125f;
    } else {
        base = m - 1;
        kw[0] = -0.0703125f; kw[1] = 0.8671875f; kw[2] = 0.2265625f; kw[3] = -0.0234375f;
    }
    float s = 0.f;
#pragma unroll
    for (int t = 0; t < 4; ++t) {
        int i = base + t;
        bool ok = (i >= 0) && (i < n);
        idx[t] = ok ? i : 0;
        w[t]   = ok ? kw[t] : 0.f;
        s += w[t];
    }
    float inv = 1.f / s;
#pragma unroll
    for (int t = 0; t < 4; ++t) w[t] *= inv;
}

// ---------------- bicubic 2x down / up --------------------------------------
__global__ void k_down2(const float* __restrict__ in, float* __restrict__ out1,
                        int Cn, int n_in)
{
    int n_out = n_in >> 1;
    long total = (long)Cn * n_out * n_out;
    long t = (long)blockIdx.x * blockDim.x + threadIdx.x;
    if (t >= total) return;
    int ox = (int)(t % n_out);
    int oy = (int)((t / n_out) % n_out);
    long c = t / ((long)n_out * n_out);
    int iy[4], ix[4]; float wy[4], wx[4];
    taps_down2(oy, n_in, iy, wy);
    taps_down2(ox, n_in, ix, wx);
    const float* ip = in + c * n_in * n_in;
    float s = 0.f;
#pragma unroll
    for (int a = 0; a < 4; ++a) {
        float r = 0.f;
#pragma unroll
        for (int b2 = 0; b2 < 4; ++b2) r += wx[b2] * ip[iy[a]*n_in + ix[b2]];
        s += wy[a] * r;
    }
    out1[t] = s;
}
__global__ void k_up2(const float* __restrict__ in, float* __restrict__ outp,
                      int Cn, int n_in)
{
    int n_out = n_in << 1;
    long total = (long)Cn * n_out * n_out;
    long t = (long)blockIdx.x * blockDim.x + threadIdx.x;
    if (t >= total) return;
    int ox = (int)(t % n_out);
    int oy = (int)((t / n_out) % n_out);
    long c = t / ((long)n_out * n_out);
    int iy[4], ix[4]; float wy[4], wx[4];
    taps_up2(oy, n_in, iy, wy);
    taps_up2(ox, n_in, ix, wx);
    const float* ip = in + c * n_in * n_in;
    float s = 0.f;
#pragma unroll
    for (int a = 0; a < 4; ++a) {
        float r = 0.f;
#pragma unroll
        for (int b2 = 0; b2 < 4; ++b2) r += wx[b2] * ip[iy[a]*n_in + ix[b2]];
        s += wy[a] * r;
    }
    outp[t] = s;
}

// ---------------- fused: out = down2(out_full); down_x_mod = mod conv -------
__global__ void k_down2_mod(const float* __restrict__ of, const float* __restrict__ dx,
                            const float* __restrict__ mw, const float* __restrict__ mb,
                            float* __restrict__ dout_out, float* __restrict__ dout_mod)
{
    int t = blockIdx.x * 256 + threadIdx.x;
    if (t >= BB * DH * DH) return;
    int b = t >> 16, p = t & 65535;
    int oy = p >> 8, ox = p & 255;
    int iy[4], ix[4]; float wy[4], wx[4];
    taps_down2(oy, HH, iy, wy);
    taps_down2(ox, WW, ix, wx);
    float in6[6];
#pragma unroll
    for (int c = 0; c < 3; ++c) {
        const float* ip = of + (long)(b*3 + c) * HWp;
        float s = 0.f;
#pragma unroll
        for (int a = 0; a < 4; ++a) {
            float r = 0.f;
#pragma unroll
            for (int q = 0; q < 4; ++q) r += wx[q] * ip[iy[a]*WW + ix[q]];
            s += wy[a] * r;
        }
        dout_out[(b*3 + c)*65536 + p] = s;
        in6[3 + c] = s;
    }
#pragma unroll
    for (int c = 0; c < 3; ++c) in6[c] = dx[(b*3 + c)*65536 + p];
#pragma unroll
    for (int oc = 0; oc < 3; ++oc) {
        float a = mb[oc];
#pragma unroll
        for (int ic = 0; ic < 6; ++ic) a += in6[ic] * mw[oc*6 + ic];
        dout_mod[(b*3 + oc)*65536 + p] = a;
    }
}

// ---------------- weight prep: f32 -> (hi,lo) fp16, [k][n] n-padded --------
__global__ void k_prep_w(const float* __restrict__ W1, const float* __restrict__ W2,
                         const float* __restrict__ W3, const float* __restrict__ W4,
                         const float* __restrict__ Wout)
{
    int t = blockIdx.x * 256 + threadIdx.x;     // 5*16384 = 81920
    if (t >= 81920) return;
    int L = t >> 14, r = t & 16383;
    int k = r >> 7, n = r & 127;
    const float* W = (L == 0) ? W1 : (L == 1) ? W2 : (L == 2) ? W3 : (L == 3) ? W4 : Wout;
    float v = (L < 4) ? W[k * 128 + n] : ((n < 81) ? W[k * 81 + n] : 0.f);
    __half h = __float2half(v);
    g_wHi[L][r] = h;
    g_wLo[L][r] = __float2half(v - __half2float(h));
}

// ---------------- fused MLP + dynamic-filter apply --------------------------
// (unchanged from R11: 128 px/CTA, 256 thr, 103.5KB smem, 2 CTAs/SM,
//  2-term fp16 split, XOR swizzle, cp.async staging)
#define S_A   0
#define S_BHI 32768
#define S_BLO 65536
#define S_LW  32768
#define S_INP 98304
#define S_WIN 102400
#define S_TOT 105984
#define LWST 84

__device__ __forceinline__ void st_hi2(char* smem, int row, int col,
                                       float v0, float v1)
{
    __half2 hp = __floats2half2_rn(v0, v1);
    *(uint32_t*)(smem + S_A + swz(row, col >> 3) + (col & 7) * 2) = *(uint32_t*)&hp;
}

__global__ __launch_bounds__(256, 2) void fused_mlp_mma(
    const float* __restrict__ x, const float* __restrict__ Win,
    float* __restrict__ outp)
{
    extern __shared__ __align__(16) char smem[];
    const uint32_t sb = smem_u32(smem);
    const int tid = threadIdx.x;
    const int wid = tid >> 5, lane = tid & 31;
    const long row0 = (long)blockIdx.x * 128;
    const int bimg = (int)(row0 >> 18);
    const int n0 = (int)(row0 & (HWp - 1));
    const int irow = n0 >> 9, j0 = n0 & 511;

#pragma unroll
    for (int it = 0; it < 8; ++it) {
        int idx = it * 256 + tid;
        int row = idx >> 4, cg = idx & 15;
        uint32_t d = sb + S_BHI + swz(row, cg);
        cp_async16(d,         (const char*)g_wHi[0] + idx * 16);
        cp_async16(d + 32768, (const char*)g_wLo[0] + idx * 16);
    }
    CP_COMMIT();

    for (int i = tid; i < 896; i += 256) *(float*)(smem + S_WIN + i*4) = Win[i];
    if (tid < 128) {
        int i = irow, j = j0 + tid;
        int iy[4], ix[4]; float wy[4], wx[4];
        taps_up2(i, DH, iy, wy);
        taps_up2(j, DH, ix, wx);
        float* ip = (float*)(smem + S_INP) + tid * 8;
        ip[0] = (i & 1) ? 0.5f : -0.5f;
        ip[1] = (j & 1) ? 0.5f : -0.5f;
        ip[2] = 1.f; ip[3] = 1.f;
#pragma unroll
        for (int c = 0; c < 3; ++c) {
            const float* dp = g_down_x + (long)(bimg*3 + c) * DH * DH;
            float s = 0.f;
#pragma unroll
            for (int a = 0; a < 4; ++a) {
                float rr = 0.f;
#pragma unroll
                for (int b2 = 0; b2 < 4; ++b2) rr += wx[b2] * dp[iy[a]*DH + ix[b2]];
                s += wy[a] * rr;
            }
            ip[4 + c] = x[((long)(bimg*3 + c) * HH + i) * WW + j] - s;
        }
        ip[7] = 0.f;
    }
    __syncthreads();

    {
        int row = tid >> 1;
        int cbase = (tid & 1) * 64;
        const float* ip = (const float*)(smem + S_INP) + row * 8;
        float a0 = ip[0], a1 = ip[1], a2 = ip[2], a3 = ip[3];
        float a4 = ip[4], a5 = ip[5], a6 = ip[6];
        const float* Wn = (const float*)(smem + S_WIN);
#pragma unroll 8
        for (int c = 0; c < 64; c += 2) {
            int o = cbase + c;
            float v0 = a0*Wn[o] + a1*Wn[128+o] + a2*Wn[256+o] + a3*Wn[384+o]
                     + a4*Wn[512+o] + a5*Wn[640+o] + a6*Wn[768+o];
            float v1 = a0*Wn[o+1] + a1*Wn[128+o+1] + a2*Wn[256+o+1] + a3*Wn[384+o+1]
                     + a4*Wn[512+o+1] + a5*Wn[640+o+1] + a6*Wn[768+o+1];
            v0 = v0 > 0.f ? v0 : 0.01f * v0;
            v1 = v1 > 0.f ? v1 : 0.01f * v1;
            st_hi2(smem, row, o, v0, v1);
        }
    }

    const int wm = wid & 1, wn = wid >> 1;
    const int lr = lane & 15, lh = lane >> 4, lx = lane & 7;

#pragma unroll 1
    for (int L = 0; L < 5; ++L) {
        CP_WAIT(0);
        __syncthreads();

        float acc[4][4][4];
        uint32_t c16[4][4][2];
#pragma unroll
        for (int mt = 0; mt < 4; ++mt)
#pragma unroll
            for (int nt = 0; nt < 4; ++nt) {
#pragma unroll
                for (int q = 0; q < 4; ++q) acc[mt][nt][q] = 0.f;
                c16[mt][nt][0] = 0u; c16[mt][nt][1] = 0u;
            }

#pragma unroll 1
        for (int k = 0; k < 8; ++k) {
            uint32_t ah[4][4];
#pragma unroll
            for (int mt = 0; mt < 4; ++mt) {
                uint32_t a = sb + S_A
                    + (uint32_t)((wm*64 + mt*16 + lr) * 256)
                    + (uint32_t)((((k*2 + lh) ^ lx)) << 4);
                ldsm_x4(a, ah[mt]);
            }
#pragma unroll
            for (int np = 0; np < 2; ++np) {
                uint32_t bh[4], bl[4];
                uint32_t b = sb + S_BHI
                    + (uint32_t)((k*16 + lr) * 256)
                    + (uint32_t)(((wn*4 + np*2 + lh) ^ lx) << 4);
                ldsm_x4t(b, bh);
                ldsm_x4t(b + 32768, bl);
                mma_f32(acc[0][np*2],   ah[0], bh);
                mma_f32(acc[0][np*2+1], ah[0], bh + 2);
                mma_f32(acc[1][np*2],   ah[1], bh);
                mma_f32(acc[1][np*2+1], ah[1], bh + 2);
                mma_f32(acc[2][np*2],   ah[2], bh);
                mma_f32(acc[2][np*2+1], ah[2], bh + 2);
                mma_f32(acc[3][np*2],   ah[3], bh);
                mma_f32(acc[3][np*2+1], ah[3], bh + 2);
                mma_f16(c16[0][np*2],   ah[0], bl);
                mma_f16(c16[0][np*2+1], ah[0], bl + 2);
                mma_f16(c16[1][np*2],   ah[1], bl);
                mma_f16(c16[1][np*2+1], ah[1], bl + 2);
                mma_f16(c16[2][np*2],   ah[2], bl);
                mma_f16(c16[2][np*2+1], ah[2], bl + 2);
                mma_f16(c16[3][np*2],   ah[3], bl);
                mma_f16(c16[3][np*2+1], ah[3], bl + 2);
            }
        }
        __syncthreads();

        if (L < 4) {
#pragma unroll
            for (int it = 0; it < 8; ++it) {
                int idx = it * 256 + tid;
                int row = idx >> 4, cg = idx & 15;
                uint32_t d = sb + S_BHI + swz(row, cg);
                cp_async16(d,         (const char*)g_wHi[L+1] + idx * 16);
                cp_async16(d + 32768, (const char*)g_wLo[L+1] + idx * 16);
            }
            CP_COMMIT();

#pragma unroll
            for (int mt = 0; mt < 4; ++mt) {
                int r0 = wm*64 + mt*16 + (lane >> 2);
#pragma unroll
                for (int nt = 0; nt < 4; ++nt) {
                    int c = wn*32 + nt*8 + (lane & 3)*2;
                    __half2 p0 = *(__half2*)&c16[mt][nt][0];
                    __half2 p1 = *(__half2*)&c16[mt][nt][1];
                    float v0 = acc[mt][nt][0] + __half2float(p0.x);
                    float v1 = acc[mt][nt][1] + __half2float(p0.y);
                    float w0 = acc[mt][nt][2] + __half2float(p1.x);
                    float w1 = acc[mt][nt][3] + __half2float(p1.y);
                    v0 = v0 > 0.f ? v0 : 0.01f * v0;
                    v1 = v1 > 0.f ? v1 : 0.01f * v1;
                    w0 = w0 > 0.f ? w0 : 0.01f * w0;
                    w1 = w1 > 0.f ? w1 : 0.01f * w1;
                    st_hi2(smem, r0,     c, v0, v1);
                    st_hi2(smem, r0 + 8, c, w0, w1);
                }
            }
        } else {
            float* lwS = (float*)(smem + S_LW);
#pragma unroll
            for (int mt = 0; mt < 4; ++mt) {
                int r0 = wm*64 + mt*16 + (lane >> 2);
#pragma unroll
                for (int nt = 0; nt < 4; ++nt) {
                    int c = wn*32 + nt*8 + (lane & 3)*2;
                    __half2 p0 = *(__half2*)&c16[mt][nt][0];
                    __half2 p1 = *(__half2*)&c16[mt][nt][1];
                    if (c < 81) {
                        lwS[r0 * LWST + c]     = acc[mt][nt][0] + __half2float(p0.x);
                        lwS[(r0+8) * LWST + c] = acc[mt][nt][2] + __half2float(p1.x);
                    }
                    if (c + 1 < 81) {
                        lwS[r0 * LWST + c + 1]     = acc[mt][nt][1] + __half2float(p0.y);
                        lwS[(r0+8) * LWST + c + 1] = acc[mt][nt][3] + __half2float(p1.y);
                    }
                }
            }
        }
    }

    float* xp = (float*)(smem + S_INP);        // [3][3][132]
    for (int idx = tid; idx < 3*3*130; idx += 256) {
        int c = idx / 390, rem = idx % 390, ki = rem / 130, jj = rem % 130;
        int yy = irow + ki - 1;
        int xx = j0 + jj - 1;
        float v = 0.f;
        if (yy >= 0 && yy < HH && xx >= 0 && xx < WW)
            v = x[((long)(bimg*3 + c) * HH + yy) * WW + xx];
        xp[(c*3 + ki) * 132 + jj] = v;
    }
    __syncthreads();

    for (int idx = tid; idx < 384; idx += 256) {
        int p = idx & 127, oc = idx >> 7;
        const float* lwr = (const float*)(smem + S_LW) + p * LWST;
        float o = 0.f;
#pragma unroll
        for (int c = 0; c < 3; ++c)
#pragma unroll
            for (int ki = 0; ki < 3; ++ki) {
                const float* xr = xp + (c*3 + ki) * 132 + p;
#pragma unroll
                for (int kj = 0; kj < 3; ++kj)
                    o += xr[kj] * lwr[(c*9 + ki*3 + kj) * 3 + oc];
            }
        outp[(long)(bimg*3 + oc) * HWp + n0 + p] = o;
    }
}

// ---------------- 3x3 stride-2 pad-1 conv, 3 -> 64 channels -----------------
__global__ __launch_bounds__(256) void k_conv3x3s2(const float* __restrict__ in,
    const float* __restrict__ wt, const float* __restrict__ bias,
    float* __restrict__ outp, int S)
{
    __shared__ float w_s[1728];
    __shared__ float in_s[3][33][33];
    int tid = threadIdx.x;
    for (int i = tid; i < 1728; i += 256) w_s[i] = wt[i];
    int OS = S >> 1;
    int ox0 = blockIdx.x * 16, oy0 = blockIdx.y * 16, b = blockIdx.z;
    for (int idx = tid; idx < 3*33*33; idx += 256) {
        int c = idx / 1089, rem = idx % 1089, r = rem / 33, col = rem % 33;
        int iy = oy0*2 - 1 + r, ix = ox0*2 - 1 + col;
        float v = 0.f;
        if (iy >= 0 && iy < S && ix >= 0 && ix < S)
            v = in[((long)(b*3 + c) * S + iy) * S + ix];
        in_s[c][r][col] = v;
    }
    __syncthreads();
    int ox = tid & 15, oy = tid >> 4;
    float pix[27];
#pragma unroll
    for (int c = 0; c < 3; ++c)
#pragma unroll
        for (int ki = 0; ki < 3; ++ki)
#pragma unroll
            for (int kj = 0; kj < 3; ++kj)
                pix[c*9 + ki*3 + kj] = in_s[c][2*oy + ki][2*ox + kj];
#pragma unroll 4
    for (int oc = 0; oc < 64; ++oc) {
        float acc = bias[oc];
#pragma unroll
        for (int q = 0; q < 27; ++q) acc += pix[q] * w_s[oc*27 + q];
        outp[(((long)b*64 + oc) * OS + oy0 + oy) * OS + ox0 + ox] = acc;
    }
}

// ---------------- launch: fork-join two streams ------------------------------
extern "C" void kernel_launch(void* const* d_in, const int* in_sizes, int n_in,
                              void* d_out, int out_size)
{
    const float* x      = (const float*)d_in[0];
    const float* W_in   = (const float*)d_in[1];
    const float* W_h1   = (const float*)d_in[2];
    const float* W_h2   = (const float*)d_in[3];
    const float* W_h3   = (const float*)d_in[4];
    const float* W_h4   = (const float*)d_in[5];
    const float* W_out  = (const float*)d_in[6];
    const float* feat_w = (const float*)d_in[7];
    const float* feat_b = (const float*)d_in[8];
    const float* mod_w  = (const float*)d_in[9];
    const float* mod_b  = (const float*)d_in[10];

    float* outF = (float*)d_out;
    float* dout_mod = outF;                       // 2*3*256*256   = 393216
    float* dout_hr  = outF + 393216;              // 2*64*256*256  = 8388608
    float* dout_new = outF + 8781824;             // 8388608
    float* dout_ori = outF + 17170432;            // 8388608
    float* dout_out = outF + 25559040;            // 393216

    float *downx, *outfull, *ftmp, *ftmp2;
    cudaGetSymbolAddress((void**)&downx,   g_down_x);
    cudaGetSymbolAddress((void**)&outfull, g_out_full);
    cudaGetSymbolAddress((void**)&ftmp,    g_feat_tmp);
    cudaGetSymbolAddress((void**)&ftmp2,   g_feat_tmp2);

    static cudaStream_t s1 = nullptr, s2 = nullptr;
    static cudaEvent_t ev0, evdx, evs1, evs2;
    if (!s1) {
        cudaStreamCreateWithFlags(&s1, cudaStreamNonBlocking);
        cudaStreamCreateWithFlags(&s2, cudaStreamNonBlocking);
        cudaEventCreateWithFlags(&ev0,  cudaEventDisableTiming);
        cudaEventCreateWithFlags(&evdx, cudaEventDisableTiming);
        cudaEventCreateWithFlags(&evs1, cudaEventDisableTiming);
        cudaEventCreateWithFlags(&evs2, cudaEventDisableTiming);
        cudaFuncSetAttribute(fused_mlp_mma,
                             cudaFuncAttributeMaxDynamicSharedMemorySize, S_TOT);
    }

    // fork from the capture-origin (default) stream
    cudaEventRecord(ev0, 0);
    cudaStreamWaitEvent(s1, ev0, 0);
    cudaStreamWaitEvent(s2, ev0, 0);

    // ---- stream 1: critical path (MLP chain) ----
    k_down2<<<(BB*3*DH*DH + 255)/256, 256, 0, s1>>>(x, downx, BB*3, HH);
    cudaEventRecord(evdx, s1);                        // downx ready
    k_prep_w<<<320, 256, 0, s1>>>(W_h1, W_h2, W_h3, W_h4, W_out);
    fused_mlp_mma<<<MROWS/128, 256, S_TOT, s1>>>(x, W_in, outfull);
    k_down2_mod<<<(BB*DH*DH + 255)/256, 256, 0, s1>>>(outfull, downx, mod_w, mod_b,
                                                      dout_out, dout_mod);
    {
        dim3 g(8, 8, BB);
        k_conv3x3s2<<<g, 256, 0, s1>>>(dout_mod, feat_w, feat_b, ftmp2, 256);
    }
    k_up2<<<(BB*64*256*256 + 255)/256, 256, 0, s1>>>(ftmp2, dout_new, BB*64, 128);
    cudaEventRecord(evs1, s1);

    // ---- stream 2: independent features (hidden under the MLP) ----
    {
        dim3 g(16, 16, BB);
        k_conv3x3s2<<<g, 256, 0, s2>>>(x, feat_w, feat_b, dout_hr, 512);
    }
    cudaStreamWaitEvent(s2, evdx, 0);                 // needs downx
    {
        dim3 g(8, 8, BB);
        k_conv3x3s2<<<g, 256, 0, s2>>>(downx, feat_w, feat_b, ftmp, 256);
    }
    k_up2<<<(BB*64*256*256 + 255)/256, 256, 0, s2>>>(ftmp, dout_ori, BB*64, 128);
    cudaEventRecord(evs2, s2);

    // join back onto the origin stream
    cudaStreamWaitEvent(0, evs1, 0);
    cudaStreamWaitEvent(0, evs2, 0);
}

// round 13
// speedup vs baseline: 1.7695x; 1.0247x over previous
#include <cuda_runtime.h>
#include <cuda_fp16.h>
#include <cstdint>

#define HH 512
#define WW 512
#define DH 256
#define HWp (HH*WW)          // 262144
#define BB 2
#define MROWS (BB*HWp)       // 524288

// ---------------- scratch (device globals; no allocation allowed) ----------
__device__ float g_down_x[BB*3*DH*DH];                 // 1.5 MB
__device__ float g_out_full[BB*3*HH*WW];               // 6 MB
__device__ float g_feat_tmp[BB*64*128*128];            // 8 MB
__device__ float g_feat_tmp2[BB*64*128*128];           // 8 MB
__device__ __align__(16) __half g_wHi[5][16384];       // [k][n] row-major, n padded to 128
__device__ __align__(16) __half g_wLo[5][16384];

// ---------------- mma/ldmatrix/stmatrix/cp.async helpers (base ISA) ---------
__device__ __forceinline__ uint32_t smem_u32(const void* p) {
    uint32_t a;
    asm("{ .reg .u64 t; cvta.to.shared.u64 t, %1; cvt.u32.u64 %0, t; }" : "=r"(a) : "l"(p));
    return a;
}
__device__ __forceinline__ void ldsm_x4(uint32_t addr, uint32_t r[4]) {
    asm volatile("ldmatrix.sync.aligned.m8n8.x4.shared.b16 {%0,%1,%2,%3}, [%4];"
        : "=r"(r[0]), "=r"(r[1]), "=r"(r[2]), "=r"(r[3]) : "r"(addr));
}
__device__ __forceinline__ void ldsm_x4t(uint32_t addr, uint32_t r[4]) {
    asm volatile("ldmatrix.sync.aligned.m8n8.x4.trans.shared.b16 {%0,%1,%2,%3}, [%4];"
        : "=r"(r[0]), "=r"(r[1]), "=r"(r[2]), "=r"(r[3]) : "r"(addr));
}
__device__ __forceinline__ void stsm_x4(uint32_t addr, uint32_t t0, uint32_t t1,
                                        uint32_t t2, uint32_t t3) {
    asm volatile("stmatrix.sync.aligned.m8n8.x4.shared.b16 [%0], {%1,%2,%3,%4};"
        :: "r"(addr), "r"(t0), "r"(t1), "r"(t2), "r"(t3) : "memory");
}
__device__ __forceinline__ void mma_f32(float d[4], const uint32_t a[4], const uint32_t* b) {
    asm volatile("mma.sync.aligned.m16n8k16.row.col.f32.f16.f16.f32 "
        "{%0,%1,%2,%3}, {%4,%5,%6,%7}, {%8,%9}, {%0,%1,%2,%3};"
        : "+f"(d[0]), "+f"(d[1]), "+f"(d[2]), "+f"(d[3])
        : "r"(a[0]), "r"(a[1]), "r"(a[2]), "r"(a[3]), "r"(b[0]), "r"(b[1]));
}
__device__ __forceinline__ void mma_f16(uint32_t d[2], const uint32_t a[4], const uint32_t* b) {
    asm volatile("mma.sync.aligned.m16n8k16.row.col.f16.f16.f16.f16 "
        "{%0,%1}, {%2,%3,%4,%5}, {%6,%7}, {%0,%1};"
        : "+r"(d[0]), "+r"(d[1])
        : "r"(a[0]), "r"(a[1]), "r"(a[2]), "r"(a[3]), "r"(b[0]), "r"(b[1]));
}
__device__ __forceinline__ void cp_async16(uint32_t dst, const void* src) {
    asm volatile("cp.async.cg.shared.global [%0], [%1], 16;" :: "r"(dst), "l"(src));
}
#define CP_COMMIT() asm volatile("cp.async.commit_group;" ::: "memory")
#define CP_WAIT(n)  asm volatile("cp.async.wait_group %0;" :: "n"(n) : "memory")

// XOR-swizzled tile addressing: 256B rows, 16B units permuted by row&7
__device__ __forceinline__ uint32_t swz(int row, int cg) {
    return (uint32_t)(row * 256 + ((cg ^ (row & 7)) << 4));
}
__device__ __forceinline__ float lrelu(float v) { return v > 0.f ? v : 0.01f * v; }

// ---------------- bicubic tap helpers (match jax.image.resize, a=-0.5) -----
__device__ __forceinline__ void taps_down2(int o, int n, int idx[4], float w[4]) {
    const float kw0 = -0.0625f, kw1 = 0.5625f;
    float kw[4] = {kw0, kw1, kw1, kw0};
    float s = 0.f;
#pragma unroll
    for (int t = 0; t < 4; ++t) {
        int i = 2*o - 1 + t;
        bool ok = (i >= 0) && (i < n);
        idx[t] = ok ? i : 0;
        w[t]   = ok ? kw[t] : 0.f;
        s += w[t];
    }
    float inv = 1.f / s;
#pragma unroll
    for (int t = 0; t < 4; ++t) w[t] *= inv;
}
__device__ __forceinline__ void taps_up2(int o, int n, int idx[4], float w[4]) {
    int m = o >> 1;
    float kw[4];
    int base;
    if ((o & 1) == 0) {
        base = m - 2;
        kw[0] = -0.0234375f; kw[1] = 0.2265625f; kw[2] = 0.8671875f; kw[3] = -0.0703125f;
    } else {
        base = m - 1;
        kw[0] = -0.0703125f; kw[1] = 0.8671875f; kw[2] = 0.2265625f; kw[3] = -0.0234375f;
    }
    float s = 0.f;
#pragma unroll
    for (int t = 0; t < 4; ++t) {
        int i = base + t;
        bool ok = (i >= 0) && (i < n);
        idx[t] = ok ? i : 0;
        w[t]   = ok ? kw[t] : 0.f;
        s += w[t];
    }
    float inv = 1.f / s;
#pragma unroll
    for (int t = 0; t < 4; ++t) w[t] *= inv;
}

// ---------------- bicubic 2x down / up --------------------------------------
__global__ void k_down2(const float* __restrict__ in, float* __restrict__ out1,
                        int Cn, int n_in)
{
    int n_out = n_in >> 1;
    long total = (long)Cn * n_out * n_out;
    long t = (long)blockIdx.x * blockDim.x + threadIdx.x;
    if (t >= total) return;
    int ox = (int)(t % n_out);
    int oy = (int)((t / n_out) % n_out);
    long c = t / ((long)n_out * n_out);
    int iy[4], ix[4]; float wy[4], wx[4];
    taps_down2(oy, n_in, iy, wy);
    taps_down2(ox, n_in, ix, wx);
    const float* ip = in + c * n_in * n_in;
    float s = 0.f;
#pragma unroll
    for (int a = 0; a < 4; ++a) {
        float r = 0.f;
#pragma unroll
        for (int b2 = 0; b2 < 4; ++b2) r += wx[b2] * ip[iy[a]*n_in + ix[b2]];
        s += wy[a] * r;
    }
    out1[t] = s;
}
__global__ void k_up2(const float* __restrict__ in, float* __restrict__ outp,
                      int Cn, int n_in)
{
    int n_out = n_in << 1;
    long total = (long)Cn * n_out * n_out;
    long t = (long)blockIdx.x * blockDim.x + threadIdx.x;
    if (t >= total) return;
    int ox = (int)(t % n_out);
    int oy = (int)((t / n_out) % n_out);
    long c = t / ((long)n_out * n_out);
    int iy[4], ix[4]; float wy[4], wx[4];
    taps_up2(oy, n_in, iy, wy);
    taps_up2(ox, n_in, ix, wx);
    const float* ip = in + c * n_in * n_in;
    float s = 0.f;
#pragma unroll
    for (int a = 0; a < 4; ++a) {
        float r = 0.f;
#pragma unroll
        for (int b2 = 0; b2 < 4; ++b2) r += wx[b2] * ip[iy[a]*n_in + ix[b2]];
        s += wy[a] * r;
    }
    outp[t] = s;
}

// ---------------- fused: out = down2(out_full); down_x_mod = mod conv -------
__global__ void k_down2_mod(const float* __restrict__ of, const float* __restrict__ dx,
                            const float* __restrict__ mw, const float* __restrict__ mb,
                            float* __restrict__ dout_out, float* __restrict__ dout_mod)
{
    int t = blockIdx.x * 256 + threadIdx.x;
    if (t >= BB * DH * DH) return;
    int b = t >> 16, p = t & 65535;
    int oy = p >> 8, ox = p & 255;
    int iy[4], ix[4]; float wy[4], wx[4];
    taps_down2(oy, HH, iy, wy);
    taps_down2(ox, WW, ix, wx);
    float in6[6];
#pragma unroll
    for (int c = 0; c < 3; ++c) {
        const float* ip = of + (long)(b*3 + c) * HWp;
        float s = 0.f;
#pragma unroll
        for (int a = 0; a < 4; ++a) {
            float r = 0.f;
#pragma unroll
            for (int q = 0; q < 4; ++q) r += wx[q] * ip[iy[a]*WW + ix[q]];
            s += wy[a] * r;
        }
        dout_out[(b*3 + c)*65536 + p] = s;
        in6[3 + c] = s;
    }
#pragma unroll
    for (int c = 0; c < 3; ++c) in6[c] = dx[(b*3 + c)*65536 + p];
#pragma unroll
    for (int oc = 0; oc < 3; ++oc) {
        float a = mb[oc];
#pragma unroll
        for (int ic = 0; ic < 6; ++ic) a += in6[ic] * mw[oc*6 + ic];
        dout_mod[(b*3 + oc)*65536 + p] = a;
    }
}

// ---------------- weight prep: f32 -> (hi,lo) fp16, [k][n] n-padded --------
__global__ void k_prep_w(const float* __restrict__ W1, const float* __restrict__ W2,
                         const float* __restrict__ W3, const float* __restrict__ W4,
                         const float* __restrict__ Wout)
{
    int t = blockIdx.x * 256 + threadIdx.x;     // 5*16384 = 81920
    if (t >= 81920) return;
    int L = t >> 14, r = t & 16383;
    int k = r >> 7, n = r & 127;
    const float* W = (L == 0) ? W1 : (L == 1) ? W2 : (L == 2) ? W3 : (L == 3) ? W4 : Wout;
    float v = (L < 4) ? W[k * 128 + n] : ((n < 81) ? W[k * 81 + n] : 0.f);
    __half h = __float2half(v);
    g_wHi[L][r] = h;
    g_wLo[L][r] = __float2half(v - __half2float(h));
}

// ---------------- fused MLP + dynamic-filter apply --------------------------
// 128 px/CTA, 256 thr, 103.5KB smem, 2 CTAs/SM, 2-term fp16 split,
// XOR swizzle, cp.async staging; stmatrix epilogue; last layer N=96.
#define S_A   0
#define S_BHI 32768
#define S_BLO 65536
#define S_LW  32768
#define S_INP 98304
#define S_WIN 102400
#define S_TOT 105984
#define LWST 84

__device__ __forceinline__ void st_hi2(char* smem, int row, int col,
                                       float v0, float v1)
{
    __half2 hp = __floats2half2_rn(v0, v1);
    *(uint32_t*)(smem + S_A + swz(row, col >> 3) + (col & 7) * 2) = *(uint32_t*)&hp;
}

__global__ __launch_bounds__(256, 2) void fused_mlp_mma(
    const float* __restrict__ x, const float* __restrict__ Win,
    float* __restrict__ outp)
{
    extern __shared__ __align__(16) char smem[];
    const uint32_t sb = smem_u32(smem);
    const int tid = threadIdx.x;
    const int wid = tid >> 5, lane = tid & 31;
    const long row0 = (long)blockIdx.x * 128;
    const int bimg = (int)(row0 >> 18);
    const int n0 = (int)(row0 & (HWp - 1));
    const int irow = n0 >> 9, j0 = n0 & 511;

#pragma unroll
    for (int it = 0; it < 8; ++it) {
        int idx = it * 256 + tid;
        int row = idx >> 4, cg = idx & 15;
        uint32_t d = sb + S_BHI + swz(row, cg);
        cp_async16(d,         (const char*)g_wHi[0] + idx * 16);
        cp_async16(d + 32768, (const char*)g_wLo[0] + idx * 16);
    }
    CP_COMMIT();

    for (int i = tid; i < 896; i += 256) *(float*)(smem + S_WIN + i*4) = Win[i];
    if (tid < 128) {
        int i = irow, j = j0 + tid;
        int iy[4], ix[4]; float wy[4], wx[4];
        taps_up2(i, DH, iy, wy);
        taps_up2(j, DH, ix, wx);
        float* ip = (float*)(smem + S_INP) + tid * 8;
        ip[0] = (i & 1) ? 0.5f : -0.5f;
        ip[1] = (j & 1) ? 0.5f : -0.5f;
        ip[2] = 1.f; ip[3] = 1.f;
#pragma unroll
        for (int c = 0; c < 3; ++c) {
            const float* dp = g_down_x + (long)(bimg*3 + c) * DH * DH;
            float s = 0.f;
#pragma unroll
            for (int a = 0; a < 4; ++a) {
                float rr = 0.f;
#pragma unroll
                for (int b2 = 0; b2 < 4; ++b2) rr += wx[b2] * dp[iy[a]*DH + ix[b2]];
                s += wy[a] * rr;
            }
            ip[4 + c] = x[((long)(bimg*3 + c) * HH + i) * WW + j] - s;
        }
        ip[7] = 0.f;
    }
    __syncthreads();

    {
        int row = tid >> 1;
        int cbase = (tid & 1) * 64;
        const float* ip = (const float*)(smem + S_INP) + row * 8;
        float a0 = ip[0], a1 = ip[1], a2 = ip[2], a3 = ip[3];
        float a4 = ip[4], a5 = ip[5], a6 = ip[6];
        const float* Wn = (const float*)(smem + S_WIN);
#pragma unroll 8
        for (int c = 0; c < 64; c += 2) {
            int o = cbase + c;
            float v0 = a0*Wn[o] + a1*Wn[128+o] + a2*Wn[256+o] + a3*Wn[384+o]
                     + a4*Wn[512+o] + a5*Wn[640+o] + a6*Wn[768+o];
            float v1 = a0*Wn[o+1] + a1*Wn[128+o+1] + a2*Wn[256+o+1] + a3*Wn[384+o+1]
                     + a4*Wn[512+o+1] + a5*Wn[640+o+1] + a6*Wn[768+o+1];
            st_hi2(smem, row, o, lrelu(v0), lrelu(v1));
        }
    }

    const int wm = wid & 1, wn = wid >> 1;
    const int lr = lane & 15, lh = lane >> 4, lx = lane & 7;

#pragma unroll 1
    for (int L = 0; L < 5; ++L) {
        CP_WAIT(0);
        __syncthreads();

        float acc[4][4][4];
        uint32_t c16[4][4][2];
#pragma unroll
        for (int mt = 0; mt < 4; ++mt)
#pragma unroll
            for (int nt = 0; nt < 4; ++nt) {
#pragma unroll
                for (int q = 0; q < 4; ++q) acc[mt][nt][q] = 0.f;
                c16[mt][nt][0] = 0u; c16[mt][nt][1] = 0u;
            }

        // last layer: cols 96..127 are pure zero-padding -> wn==3 skips compute
        if (L < 4 || wn < 3) {
#pragma unroll 1
            for (int k = 0; k < 8; ++k) {
                uint32_t ah[4][4];
#pragma unroll
                for (int mt = 0; mt < 4; ++mt) {
                    uint32_t a = sb + S_A
                        + (uint32_t)((wm*64 + mt*16 + lr) * 256)
                        + (uint32_t)((((k*2 + lh) ^ lx)) << 4);
                    ldsm_x4(a, ah[mt]);
                }
#pragma unroll
                for (int np = 0; np < 2; ++np) {
                    uint32_t bh[4], bl[4];
                    uint32_t b = sb + S_BHI
                        + (uint32_t)((k*16 + lr) * 256)
                        + (uint32_t)(((wn*4 + np*2 + lh) ^ lx) << 4);
                    ldsm_x4t(b, bh);
                    ldsm_x4t(b + 32768, bl);
                    mma_f32(acc[0][np*2],   ah[0], bh);
                    mma_f32(acc[0][np*2+1], ah[0], bh + 2);
                    mma_f32(acc[1][np*2],   ah[1], bh);
                    mma_f32(acc[1][np*2+1], ah[1], bh + 2);
                    mma_f32(acc[2][np*2],   ah[2], bh);
                    mma_f32(acc[2][np*2+1], ah[2], bh + 2);
                    mma_f32(acc[3][np*2],   ah[3], bh);
                    mma_f32(acc[3][np*2+1], ah[3], bh + 2);
                    mma_f16(c16[0][np*2],   ah[0], bl);
                    mma_f16(c16[0][np*2+1], ah[0], bl + 2);
                    mma_f16(c16[1][np*2],   ah[1], bl);
                    mma_f16(c16[1][np*2+1], ah[1], bl + 2);
                    mma_f16(c16[2][np*2],   ah[2], bl);
                    mma_f16(c16[2][np*2+1], ah[2], bl + 2);
                    mma_f16(c16[3][np*2],   ah[3], bl);
                    mma_f16(c16[3][np*2+1], ah[3], bl + 2);
                }
            }
        }
        __syncthreads();

        if (L < 4) {
#pragma unroll
            for (int it = 0; it < 8; ++it) {
                int idx = it * 256 + tid;
                int row = idx >> 4, cg = idx & 15;
                uint32_t d = sb + S_BHI + swz(row, cg);
                cp_async16(d,         (const char*)g_wHi[L+1] + idx * 16);
                cp_async16(d + 32768, (const char*)g_wLo[L+1] + idx * 16);
            }
            CP_COMMIT();

            // stmatrix epilogue: C-fragment layout == ldmatrix 8x8 layout
#pragma unroll
            for (int mt = 0; mt < 4; ++mt) {
                int r = wm*64 + mt*16 + lr;
                uint32_t rowad = sb + S_A + (uint32_t)(r * 256);
#pragma unroll
                for (int ntp = 0; ntp < 2; ++ntp) {
                    int nt0 = ntp*2, nt1 = ntp*2 + 1;
                    __half2 pa = *(__half2*)&c16[mt][nt0][0];
                    __half2 pb = *(__half2*)&c16[mt][nt0][1];
                    __half2 pc = *(__half2*)&c16[mt][nt1][0];
                    __half2 pd = *(__half2*)&c16[mt][nt1][1];
                    __half2 h0 = __floats2half2_rn(
                        lrelu(acc[mt][nt0][0] + __half2float(pa.x)),
                        lrelu(acc[mt][nt0][1] + __half2float(pa.y)));
                    __half2 h1 = __floats2half2_rn(
                        lrelu(acc[mt][nt0][2] + __half2float(pb.x)),
                        lrelu(acc[mt][nt0][3] + __half2float(pb.y)));
                    __half2 h2 = __floats2half2_rn(
                        lrelu(acc[mt][nt1][0] + __half2float(pc.x)),
                        lrelu(acc[mt][nt1][1] + __half2float(pc.y)));
                    __half2 h3 = __floats2half2_rn(
                        lrelu(acc[mt][nt1][2] + __half2float(pd.x)),
                        lrelu(acc[mt][nt1][3] + __half2float(pd.y)));
                    uint32_t cg = (uint32_t)((wn*4 + ntp*2 + lh) ^ (r & 7));
                    stsm_x4(rowad + (cg << 4),
                            *(uint32_t*)&h0, *(uint32_t*)&h1,
                            *(uint32_t*)&h2, *(uint32_t*)&h3);
                }
            }
        } else {
            float* lwS = (float*)(smem + S_LW);
#pragma unroll
            for (int mt = 0; mt < 4; ++mt) {
                int r0 = wm*64 + mt*16 + (lane >> 2);
#pragma unroll
                for (int nt = 0; nt < 4; ++nt) {
                    int c = wn*32 + nt*8 + (lane & 3)*2;
                    __half2 p0 = *(__half2*)&c16[mt][nt][0];
                    __half2 p1 = *(__half2*)&c16[mt][nt][1];
                    if (c < 81) {
                        lwS[r0 * LWST + c]     = acc[mt][nt][0] + __half2float(p0.x);
                        lwS[(r0+8) * LWST + c] = acc[mt][nt][2] + __half2float(p1.x);
                    }
                    if (c + 1 < 81) {
                        lwS[r0 * LWST + c + 1]     = acc[mt][nt][1] + __half2float(p0.y);
                        lwS[(r0+8) * LWST + c + 1] = acc[mt][nt][3] + __half2float(p1.y);
                    }
                }
            }
        }
    }

    float* xp = (float*)(smem + S_INP);        // [3][3][132]
    for (int idx = tid; idx < 3*3*130; idx += 256) {
        int c = idx / 390, rem = idx % 390, ki = rem / 130, jj = rem % 130;
        int yy = irow + ki - 1;
        int xx = j0 + jj - 1;
        float v = 0.f;
        if (yy >= 0 && yy < HH && xx >= 0 && xx < WW)
            v = x[((long)(bimg*3 + c) * HH + yy) * WW + xx];
        xp[(c*3 + ki) * 132 + jj] = v;
    }
    __syncthreads();

    for (int idx = tid; idx < 384; idx += 256) {
        int p = idx & 127, oc = idx >> 7;
        const float* lwr = (const float*)(smem + S_LW) + p * LWST;
        float o = 0.f;
#pragma unroll
        for (int c = 0; c < 3; ++c)
#pragma unroll
            for (int ki = 0; ki < 3; ++ki) {
                const float* xr = xp + (c*3 + ki) * 132 + p;
#pragma unroll
                for (int kj = 0; kj < 3; ++kj)
                    o += xr[kj] * lwr[(c*9 + ki*3 + kj) * 3 + oc];
            }
        outp[(long)(bimg*3 + oc) * HWp + n0 + p] = o;
    }
}

// ---------------- 3x3 stride-2 pad-1 conv, 3 -> 64 channels -----------------
__global__ __launch_bounds__(256) void k_conv3x3s2(const float* __restrict__ in,
    const float* __restrict__ wt, const float* __restrict__ bias,
    float* __restrict__ outp, int S)
{
    __shared__ float w_s[1728];
    __shared__ float in_s[3][33][33];
    int tid = threadIdx.x;
    for (int i = tid; i < 1728; i += 256) w_s[i] = wt[i];
    int OS = S >> 1;
    int ox0 = blockIdx.x * 16, oy0 = blockIdx.y * 16, b = blockIdx.z;
    for (int idx = tid; idx < 3*33*33; idx += 256) {
        int c = idx / 1089, rem = idx % 1089, r = rem / 33, col = rem % 33;
        int iy = oy0*2 - 1 + r, ix = ox0*2 - 1 + col;
        float v = 0.f;
        if (iy >= 0 && iy < S && ix >= 0 && ix < S)
            v = in[((long)(b*3 + c) * S + iy) * S + ix];
        in_s[c][r][col] = v;
    }
    __syncthreads();
    int ox = tid & 15, oy = tid >> 4;
    float pix[27];
#pragma unroll
    for (int c = 0; c < 3; ++c)
#pragma unroll
        for (int ki = 0; ki < 3; ++ki)
#pragma unroll
            for (int kj = 0; kj < 3; ++kj)
                pix[c*9 + ki*3 + kj] = in_s[c][2*oy + ki][2*ox + kj];
#pragma unroll 4
    for (int oc = 0; oc < 64; ++oc) {
        float acc = bias[oc];
#pragma unroll
        for (int q = 0; q < 27; ++q) acc += pix[q] * w_s[oc*27 + q];
        outp[(((long)b*64 + oc) * OS + oy0 + oy) * OS + ox0 + ox] = acc;
    }
}

// ---------------- launch: fork-join two streams ------------------------------
extern "C" void kernel_launch(void* const* d_in, const int* in_sizes, int n_in,
                              void* d_out, int out_size)
{
    const float* x      = (const float*)d_in[0];
    const float* W_in   = (const float*)d_in[1];
    const float* W_h1   = (const float*)d_in[2];
    const float* W_h2   = (const float*)d_in[3];
    const float* W_h3   = (const float*)d_in[4];
    const float* W_h4   = (const float*)d_in[5];
    const float* W_out  = (const float*)d_in[6];
    const float* feat_w = (const float*)d_in[7];
    const float* feat_b = (const float*)d_in[8];
    const float* mod_w  = (const float*)d_in[9];
    const float* mod_b  = (const float*)d_in[10];

    float* outF = (float*)d_out;
    float* dout_mod = outF;                       // 2*3*256*256   = 393216
    float* dout_hr  = outF + 393216;              // 2*64*256*256  = 8388608
    float* dout_new = outF + 8781824;             // 8388608
    float* dout_ori = outF + 17170432;            // 8388608
    float* dout_out = outF + 25559040;            // 393216

    float *downx, *outfull, *ftmp, *ftmp2;
    cudaGetSymbolAddress((void**)&downx,   g_down_x);
    cudaGetSymbolAddress((void**)&outfull, g_out_full);
    cudaGetSymbolAddress((void**)&ftmp,    g_feat_tmp);
    cudaGetSymbolAddress((void**)&ftmp2,   g_feat_tmp2);

    static cudaStream_t s1 = nullptr, s2 = nullptr;
    static cudaEvent_t ev0, evdx, evs1, evs2;
    if (!s1) {
        cudaStreamCreateWithFlags(&s1, cudaStreamNonBlocking);
        cudaStreamCreateWithFlags(&s2, cudaStreamNonBlocking);
        cudaEventCreateWithFlags(&ev0,  cudaEventDisableTiming);
        cudaEventCreateWithFlags(&evdx, cudaEventDisableTiming);
        cudaEventCreateWithFlags(&evs1, cudaEventDisableTiming);
        cudaEventCreateWithFlags(&evs2, cudaEventDisableTiming);
        cudaFuncSetAttribute(fused_mlp_mma,
                             cudaFuncAttributeMaxDynamicSharedMemorySize, S_TOT);
    }

    cudaEventRecord(ev0, 0);
    cudaStreamWaitEvent(s1, ev0, 0);
    cudaStreamWaitEvent(s2, ev0, 0);

    // ---- stream 1: critical path (MLP chain) ----
    k_down2<<<(BB*3*DH*DH + 255)/256, 256, 0, s1>>>(x, downx, BB*3, HH);
    cudaEventRecord(evdx, s1);
    k_prep_w<<<320, 256, 0, s1>>>(W_h1, W_h2, W_h3, W_h4, W_out);
    fused_mlp_mma<<<MROWS/128, 256, S_TOT, s1>>>(x, W_in, outfull);
    k_down2_mod<<<(BB*DH*DH + 255)/256, 256, 0, s1>>>(outfull, downx, mod_w, mod_b,
                                                      dout_out, dout_mod);
    {
        dim3 g(8, 8, BB);
        k_conv3x3s2<<<g, 256, 0, s1>>>(dout_mod, feat_w, feat_b, ftmp2, 256);
    }
    k_up2<<<(BB*64*256*256 + 255)/256, 256, 0, s1>>>(ftmp2, dout_new, BB*64, 128);
    cudaEventRecord(evs1, s1);

    // ---- stream 2: independent features ----
    {
        dim3 g(16, 16, BB);
        k_conv3x3s2<<<g, 256, 0, s2>>>(x, feat_w, feat_b, dout_hr, 512);
    }
    cudaStreamWaitEvent(s2, evdx, 0);
    {
        dim3 g(8, 8, BB);
        k_conv3x3s2<<<g, 256, 0, s2>>>(downx, feat_w, feat_b, ftmp, 256);
    }
    k_up2<<<(BB*64*256*256 + 255)/256, 256, 0, s2>>>(ftmp, dout_ori, BB*64, 128);
    cudaEventRecord(evs2, s2);

    cudaStreamWaitEvent(0, evs1, 0);
    cudaStreamWaitEvent(0, evs2, 0);
}

// round 14
// speedup vs baseline: 1.9062x; 1.0773x over previous
#include <cuda_runtime.h>
#include <cuda_fp16.h>
#include <cstdint>

#define HH 512
#define WW 512
#define DH 256
#define HWp (HH*WW)          // 262144
#define BB 2
#define MROWS (BB*HWp)       // 524288

// ---------------- scratch (device globals; no allocation allowed) ----------
__device__ float g_down_x[BB*3*DH*DH];                 // 1.5 MB
__device__ float g_out_full[BB*3*HH*WW];               // 6 MB
__device__ __align__(16) __half g_wHi[5][16384];       // [k][n] row-major, n padded to 128
__device__ __align__(16) __half g_wLo[5][16384];

// ---------------- mma/ldmatrix/stmatrix/cp.async helpers (base ISA) ---------
__device__ __forceinline__ uint32_t smem_u32(const void* p) {
    uint32_t a;
    asm("{ .reg .u64 t; cvta.to.shared.u64 t, %1; cvt.u32.u64 %0, t; }" : "=r"(a) : "l"(p));
    return a;
}
__device__ __forceinline__ void ldsm_x4(uint32_t addr, uint32_t r[4]) {
    asm volatile("ldmatrix.sync.aligned.m8n8.x4.shared.b16 {%0,%1,%2,%3}, [%4];"
        : "=r"(r[0]), "=r"(r[1]), "=r"(r[2]), "=r"(r[3]) : "r"(addr));
}
__device__ __forceinline__ void ldsm_x4t(uint32_t addr, uint32_t r[4]) {
    asm volatile("ldmatrix.sync.aligned.m8n8.x4.trans.shared.b16 {%0,%1,%2,%3}, [%4];"
        : "=r"(r[0]), "=r"(r[1]), "=r"(r[2]), "=r"(r[3]) : "r"(addr));
}
__device__ __forceinline__ void stsm_x4(uint32_t addr, uint32_t t0, uint32_t t1,
                                        uint32_t t2, uint32_t t3) {
    asm volatile("stmatrix.sync.aligned.m8n8.x4.shared.b16 [%0], {%1,%2,%3,%4};"
        :: "r"(addr), "r"(t0), "r"(t1), "r"(t2), "r"(t3) : "memory");
}
__device__ __forceinline__ void mma_f32(float d[4], const uint32_t a[4], const uint32_t* b) {
    asm volatile("mma.sync.aligned.m16n8k16.row.col.f32.f16.f16.f32 "
        "{%0,%1,%2,%3}, {%4,%5,%6,%7}, {%8,%9}, {%0,%1,%2,%3};"
        : "+f"(d[0]), "+f"(d[1]), "+f"(d[2]), "+f"(d[3])
        : "r"(a[0]), "r"(a[1]), "r"(a[2]), "r"(a[3]), "r"(b[0]), "r"(b[1]));
}
__device__ __forceinline__ void mma_f16(uint32_t d[2], const uint32_t a[4], const uint32_t* b) {
    asm volatile("mma.sync.aligned.m16n8k16.row.col.f16.f16.f16.f16 "
        "{%0,%1}, {%2,%3,%4,%5}, {%6,%7}, {%0,%1};"
        : "+r"(d[0]), "+r"(d[1])
        : "r"(a[0]), "r"(a[1]), "r"(a[2]), "r"(a[3]), "r"(b[0]), "r"(b[1]));
}
__device__ __forceinline__ void cp_async16(uint32_t dst, const void* src) {
    asm volatile("cp.async.cg.shared.global [%0], [%1], 16;" :: "r"(dst), "l"(src));
}
#define CP_COMMIT() asm volatile("cp.async.commit_group;" ::: "memory")
#define CP_WAIT(n)  asm volatile("cp.async.wait_group %0;" :: "n"(n) : "memory")

__device__ __forceinline__ uint32_t swz(int row, int cg) {
    return (uint32_t)(row * 256 + ((cg ^ (row & 7)) << 4));
}
__device__ __forceinline__ float lrelu(float v) { return v > 0.f ? v : 0.01f * v; }

// ---------------- bicubic tap helpers (match jax.image.resize, a=-0.5) -----
__device__ __forceinline__ void taps_down2(int o, int n, int idx[4], float w[4]) {
    const float kw0 = -0.0625f, kw1 = 0.5625f;
    float kw[4] = {kw0, kw1, kw1, kw0};
    float s = 0.f;
#pragma unroll
    for (int t = 0; t < 4; ++t) {
        int i = 2*o - 1 + t;
        bool ok = (i >= 0) && (i < n);
        idx[t] = ok ? i : 0;
        w[t]   = ok ? kw[t] : 0.f;
        s += w[t];
    }
    float inv = 1.f / s;
#pragma unroll
    for (int t = 0; t < 4; ++t) w[t] *= inv;
}
__device__ __forceinline__ void taps_up2(int o, int n, int idx[4], float w[4]) {
    int m = o >> 1;
    float kw[4];
    int base;
    if ((o & 1) == 0) {
        base = m - 2;
        kw[0] = -0.0234375f; kw[1] = 0.2265625f; kw[2] = 0.8671875f; kw[3] = -0.0703125f;
    } else {
        base = m - 1;
        kw[0] = -0.0703125f; kw[1] = 0.8671875f; kw[2] = 0.2265625f; kw[3] = -0.0234375f;
    }
    float s = 0.f;
#pragma unroll
    for (int t = 0; t < 4; ++t) {
        int i = base + t;
        bool ok = (i >= 0) && (i < n);
        idx[t] = ok ? i : 0;
        w[t]   = ok ? kw[t] : 0.f;
        s += w[t];
    }
    float inv = 1.f / s;
#pragma unroll
    for (int t = 0; t < 4; ++t) w[t] *= inv;
}

// ---------------- bicubic 2x down -------------------------------------------
__global__ void k_down2(const float* __restrict__ in, float* __restrict__ out1,
                        int Cn, int n_in)
{
    int n_out = n_in >> 1;
    long total = (long)Cn * n_out * n_out;
    long t = (long)blockIdx.x * blockDim.x + threadIdx.x;
    if (t >= total) return;
    int ox = (int)(t % n_out);
    int oy = (int)((t / n_out) % n_out);
    long c = t / ((long)n_out * n_out);
    int iy[4], ix[4]; float wy[4], wx[4];
    taps_down2(oy, n_in, iy, wy);
    taps_down2(ox, n_in, ix, wx);
    const float* ip = in + c * n_in * n_in;
    float s = 0.f;
#pragma unroll
    for (int a = 0; a < 4; ++a) {
        float r = 0.f;
#pragma unroll
        for (int b2 = 0; b2 < 4; ++b2) r += wx[b2] * ip[iy[a]*n_in + ix[b2]];
        s += wy[a] * r;
    }
    out1[t] = s;
}

// ---------------- fused: out = down2(out_full); down_x_mod = mod conv -------
__global__ void k_down2_mod(const float* __restrict__ of, const float* __restrict__ dx,
                            const float* __restrict__ mw, const float* __restrict__ mb,
                            float* __restrict__ dout_out, float* __restrict__ dout_mod)
{
    int t = blockIdx.x * 256 + threadIdx.x;
    if (t >= BB * DH * DH) return;
    int b = t >> 16, p = t & 65535;
    int oy = p >> 8, ox = p & 255;
    int iy[4], ix[4]; float wy[4], wx[4];
    taps_down2(oy, HH, iy, wy);
    taps_down2(ox, WW, ix, wx);
    float in6[6];
#pragma unroll
    for (int c = 0; c < 3; ++c) {
        const float* ip = of + (long)(b*3 + c) * HWp;
        float s = 0.f;
#pragma unroll
        for (int a = 0; a < 4; ++a) {
            float r = 0.f;
#pragma unroll
            for (int q = 0; q < 4; ++q) r += wx[q] * ip[iy[a]*WW + ix[q]];
            s += wy[a] * r;
        }
        dout_out[(b*3 + c)*65536 + p] = s;
        in6[3 + c] = s;
    }
#pragma unroll
    for (int c = 0; c < 3; ++c) in6[c] = dx[(b*3 + c)*65536 + p];
#pragma unroll
    for (int oc = 0; oc < 3; ++oc) {
        float a = mb[oc];
#pragma unroll
        for (int ic = 0; ic < 6; ++ic) a += in6[ic] * mw[oc*6 + ic];
        dout_mod[(b*3 + oc)*65536 + p] = a;
    }
}

// ---------------- weight prep: f32 -> (hi,lo) fp16, [k][n] n-padded --------
__global__ void k_prep_w(const float* __restrict__ W1, const float* __restrict__ W2,
                         const float* __restrict__ W3, const float* __restrict__ W4,
                         const float* __restrict__ Wout)
{
    int t = blockIdx.x * 256 + threadIdx.x;     // 5*16384 = 81920
    if (t >= 81920) return;
    int L = t >> 14, r = t & 16383;
    int k = r >> 7, n = r & 127;
    const float* W = (L == 0) ? W1 : (L == 1) ? W2 : (L == 2) ? W3 : (L == 3) ? W4 : Wout;
    float v = (L < 4) ? W[k * 128 + n] : ((n < 81) ? W[k * 81 + n] : 0.f);
    __half h = __float2half(v);
    g_wHi[L][r] = h;
    g_wLo[L][r] = __float2half(v - __half2float(h));
}

// ---------------- fused MLP + dynamic-filter apply (unchanged from R13) -----
#define S_A   0
#define S_BHI 32768
#define S_BLO 65536
#define S_LW  32768
#define S_INP 98304
#define S_WIN 102400
#define S_TOT 105984
#define LWST 84

__device__ __forceinline__ void st_hi2(char* smem, int row, int col,
                                       float v0, float v1)
{
    __half2 hp = __floats2half2_rn(v0, v1);
    *(uint32_t*)(smem + S_A + swz(row, col >> 3) + (col & 7) * 2) = *(uint32_t*)&hp;
}

__global__ __launch_bounds__(256, 2) void fused_mlp_mma(
    const float* __restrict__ x, const float* __restrict__ Win,
    float* __restrict__ outp)
{
    extern __shared__ __align__(16) char smem[];
    const uint32_t sb = smem_u32(smem);
    const int tid = threadIdx.x;
    const int wid = tid >> 5, lane = tid & 31;
    const long row0 = (long)blockIdx.x * 128;
    const int bimg = (int)(row0 >> 18);
    const int n0 = (int)(row0 & (HWp - 1));
    const int irow = n0 >> 9, j0 = n0 & 511;

#pragma unroll
    for (int it = 0; it < 8; ++it) {
        int idx = it * 256 + tid;
        int row = idx >> 4, cg = idx & 15;
        uint32_t d = sb + S_BHI + swz(row, cg);
        cp_async16(d,         (const char*)g_wHi[0] + idx * 16);
        cp_async16(d + 32768, (const char*)g_wLo[0] + idx * 16);
    }
    CP_COMMIT();

    for (int i = tid; i < 896; i += 256) *(float*)(smem + S_WIN + i*4) = Win[i];
    if (tid < 128) {
        int i = irow, j = j0 + tid;
        int iy[4], ix[4]; float wy[4], wx[4];
        taps_up2(i, DH, iy, wy);
        taps_up2(j, DH, ix, wx);
        float* ip = (float*)(smem + S_INP) + tid * 8;
        ip[0] = (i & 1) ? 0.5f : -0.5f;
        ip[1] = (j & 1) ? 0.5f : -0.5f;
        ip[2] = 1.f; ip[3] = 1.f;
#pragma unroll
        for (int c = 0; c < 3; ++c) {
            const float* dp = g_down_x + (long)(bimg*3 + c) * DH * DH;
            float s = 0.f;
#pragma unroll
            for (int a = 0; a < 4; ++a) {
                float rr = 0.f;
#pragma unroll
                for (int b2 = 0; b2 < 4; ++b2) rr += wx[b2] * dp[iy[a]*DH + ix[b2]];
                s += wy[a] * rr;
            }
            ip[4 + c] = x[((long)(bimg*3 + c) * HH + i) * WW + j] - s;
        }
        ip[7] = 0.f;
    }
    __syncthreads();

    {
        int row = tid >> 1;
        int cbase = (tid & 1) * 64;
        const float* ip = (const float*)(smem + S_INP) + row * 8;
        float a0 = ip[0], a1 = ip[1], a2 = ip[2], a3 = ip[3];
        float a4 = ip[4], a5 = ip[5], a6 = ip[6];
        const float* Wn = (const float*)(smem + S_WIN);
#pragma unroll 8
        for (int c = 0; c < 64; c += 2) {
            int o = cbase + c;
            float v0 = a0*Wn[o] + a1*Wn[128+o] + a2*Wn[256+o] + a3*Wn[384+o]
                     + a4*Wn[512+o] + a5*Wn[640+o] + a6*Wn[768+o];
            float v1 = a0*Wn[o+1] + a1*Wn[128+o+1] + a2*Wn[256+o+1] + a3*Wn[384+o+1]
                     + a4*Wn[512+o+1] + a5*Wn[640+o+1] + a6*Wn[768+o+1];
            st_hi2(smem, row, o, lrelu(v0), lrelu(v1));
        }
    }

    const int wm = wid & 1, wn = wid >> 1;
    const int lr = lane & 15, lh = lane >> 4, lx = lane & 7;

#pragma unroll 1
    for (int L = 0; L < 5; ++L) {
        CP_WAIT(0);
        __syncthreads();

        float acc[4][4][4];
        uint32_t c16[4][4][2];
#pragma unroll
        for (int mt = 0; mt < 4; ++mt)
#pragma unroll
            for (int nt = 0; nt < 4; ++nt) {
#pragma unroll
                for (int q = 0; q < 4; ++q) acc[mt][nt][q] = 0.f;
                c16[mt][nt][0] = 0u; c16[mt][nt][1] = 0u;
            }

        if (L < 4 || wn < 3) {
#pragma unroll 1
            for (int k = 0; k < 8; ++k) {
                uint32_t ah[4][4];
#pragma unroll
                for (int mt = 0; mt < 4; ++mt) {
                    uint32_t a = sb + S_A
                        + (uint32_t)((wm*64 + mt*16 + lr) * 256)
                        + (uint32_t)((((k*2 + lh) ^ lx)) << 4);
                    ldsm_x4(a, ah[mt]);
                }
#pragma unroll
                for (int np = 0; np < 2; ++np) {
                    uint32_t bh[4], bl[4];
                    uint32_t b = sb + S_BHI
                        + (uint32_t)((k*16 + lr) * 256)
                        + (uint32_t)(((wn*4 + np*2 + lh) ^ lx) << 4);
                    ldsm_x4t(b, bh);
                    ldsm_x4t(b + 32768, bl);
                    mma_f32(acc[0][np*2],   ah[0], bh);
                    mma_f32(acc[0][np*2+1], ah[0], bh + 2);
                    mma_f32(acc[1][np*2],   ah[1], bh);
                    mma_f32(acc[1][np*2+1], ah[1], bh + 2);
                    mma_f32(acc[2][np*2],   ah[2], bh);
                    mma_f32(acc[2][np*2+1], ah[2], bh + 2);
                    mma_f32(acc[3][np*2],   ah[3], bh);
                    mma_f32(acc[3][np*2+1], ah[3], bh + 2);
                    mma_f16(c16[0][np*2],   ah[0], bl);
                    mma_f16(c16[0][np*2+1], ah[0], bl + 2);
                    mma_f16(c16[1][np*2],   ah[1], bl);
                    mma_f16(c16[1][np*2+1], ah[1], bl + 2);
                    mma_f16(c16[2][np*2],   ah[2], bl);
                    mma_f16(c16[2][np*2+1], ah[2], bl + 2);
                    mma_f16(c16[3][np*2],   ah[3], bl);
                    mma_f16(c16[3][np*2+1], ah[3], bl + 2);
                }
            }
        }
        __syncthreads();

        if (L < 4) {
#pragma unroll
            for (int it = 0; it < 8; ++it) {
                int idx = it * 256 + tid;
                int row = idx >> 4, cg = idx & 15;
                uint32_t d = sb + S_BHI + swz(row, cg);
                cp_async16(d,         (const char*)g_wHi[L+1] + idx * 16);
                cp_async16(d + 32768, (const char*)g_wLo[L+1] + idx * 16);
            }
            CP_COMMIT();

#pragma unroll
            for (int mt = 0; mt < 4; ++mt) {
                int r = wm*64 + mt*16 + lr;
                uint32_t rowad = sb + S_A + (uint32_t)(r * 256);
#pragma unroll
                for (int ntp = 0; ntp < 2; ++ntp) {
                    int nt0 = ntp*2, nt1 = ntp*2 + 1;
                    __half2 pa = *(__half2*)&c16[mt][nt0][0];
                    __half2 pb = *(__half2*)&c16[mt][nt0][1];
                    __half2 pc = *(__half2*)&c16[mt][nt1][0];
                    __half2 pd = *(__half2*)&c16[mt][nt1][1];
                    __half2 h0 = __floats2half2_rn(
                        lrelu(acc[mt][nt0][0] + __half2float(pa.x)),
                        lrelu(acc[mt][nt0][1] + __half2float(pa.y)));
                    __half2 h1 = __floats2half2_rn(
                        lrelu(acc[mt][nt0][2] + __half2float(pb.x)),
                        lrelu(acc[mt][nt0][3] + __half2float(pb.y)));
                    __half2 h2 = __floats2half2_rn(
                        lrelu(acc[mt][nt1][0] + __half2float(pc.x)),
                        lrelu(acc[mt][nt1][1] + __half2float(pc.y)));
                    __half2 h3 = __floats2half2_rn(
                        lrelu(acc[mt][nt1][2] + __half2float(pd.x)),
                        lrelu(acc[mt][nt1][3] + __half2float(pd.y)));
                    uint32_t cg = (uint32_t)((wn*4 + ntp*2 + lh) ^ (r & 7));
                    stsm_x4(rowad + (cg << 4),
                            *(uint32_t*)&h0, *(uint32_t*)&h1,
                            *(uint32_t*)&h2, *(uint32_t*)&h3);
                }
            }
        } else {
            float* lwS = (float*)(smem + S_LW);
#pragma unroll
            for (int mt = 0; mt < 4; ++mt) {
                int r0 = wm*64 + mt*16 + (lane >> 2);
#pragma unroll
                for (int nt = 0; nt < 4; ++nt) {
                    int c = wn*32 + nt*8 + (lane & 3)*2;
                    __half2 p0 = *(__half2*)&c16[mt][nt][0];
                    __half2 p1 = *(__half2*)&c16[mt][nt][1];
                    if (c < 81) {
                        lwS[r0 * LWST + c]     = acc[mt][nt][0] + __half2float(p0.x);
                        lwS[(r0+8) * LWST + c] = acc[mt][nt][2] + __half2float(p1.x);
                    }
                    if (c + 1 < 81) {
                        lwS[r0 * LWST + c + 1]     = acc[mt][nt][1] + __half2float(p0.y);
                        lwS[(r0+8) * LWST + c + 1] = acc[mt][nt][3] + __half2float(p1.y);
                    }
                }
            }
        }
    }

    float* xp = (float*)(smem + S_INP);        // [3][3][132]
    for (int idx = tid; idx < 3*3*130; idx += 256) {
        int c = idx / 390, rem = idx % 390, ki = rem / 130, jj = rem % 130;
        int yy = irow + ki - 1;
        int xx = j0 + jj - 1;
        float v = 0.f;
        if (yy >= 0 && yy < HH && xx >= 0 && xx < WW)
            v = x[((long)(bimg*3 + c) * HH + yy) * WW + xx];
        xp[(c*3 + ki) * 132 + jj] = v;
    }
    __syncthreads();

    for (int idx = tid; idx < 384; idx += 256) {
        int p = idx & 127, oc = idx >> 7;
        const float* lwr = (const float*)(smem + S_LW) + p * LWST;
        float o = 0.f;
#pragma unroll
        for (int c = 0; c < 3; ++c)
#pragma unroll
            for (int ki = 0; ki < 3; ++ki) {
                const float* xr = xp + (c*3 + ki) * 132 + p;
#pragma unroll
                for (int kj = 0; kj < 3; ++kj)
                    o += xr[kj] * lwr[(c*9 + ki*3 + kj) * 3 + oc];
            }
        outp[(long)(bimg*3 + oc) * HWp + n0 + p] = o;
    }
}

// ---------------- 3x3 stride-2 pad-1 conv, 3 -> 64 channels (512 input) -----
__global__ __launch_bounds__(256) void k_conv3x3s2(const float* __restrict__ in,
    const float* __restrict__ wt, const float* __restrict__ bias,
    float* __restrict__ outp, int S)
{
    __shared__ float w_s[1728];
    __shared__ float in_s[3][33][33];
    int tid = threadIdx.x;
    for (int i = tid; i < 1728; i += 256) w_s[i] = wt[i];
    int OS = S >> 1;
    int ox0 = blockIdx.x * 16, oy0 = blockIdx.y * 16, b = blockIdx.z;
    for (int idx = tid; idx < 3*33*33; idx += 256) {
        int c = idx / 1089, rem = idx % 1089, r = rem / 33, col = rem % 33;
        int iy = oy0*2 - 1 + r, ix = ox0*2 - 1 + col;
        float v = 0.f;
        if (iy >= 0 && iy < S && ix >= 0 && ix < S)
            v = in[((long)(b*3 + c) * S + iy) * S + ix];
        in_s[c][r][col] = v;
    }
    __syncthreads();
    int ox = tid & 15, oy = tid >> 4;
    float pix[27];
#pragma unroll
    for (int c = 0; c < 3; ++c)
#pragma unroll
        for (int ki = 0; ki < 3; ++ki)
#pragma unroll
            for (int kj = 0; kj < 3; ++kj)
                pix[c*9 + ki*3 + kj] = in_s[c][2*oy + ki][2*ox + kj];
#pragma unroll 4
    for (int oc = 0; oc < 64; ++oc) {
        float acc = bias[oc];
#pragma unroll
        for (int q = 0; q < 27; ++q) acc += pix[q] * w_s[oc*27 + q];
        outp[(((long)b*64 + oc) * OS + oy0 + oy) * OS + ox0 + ox] = acc;
    }
}

// ---------------- fused conv3x3s2(256->128) + bicubic up2(128->256) ---------
// One block: 16x16 conv tile (+2 halo -> 20x20) for all 64 ch in groups of 16,
// upsampled to a 32x32x64 output tile. Bit-identical to conv->up2 in fp32.
#define CU_IN   0               // 3*41*44 floats = 5412
#define CU_W    5412            // 1728
#define CU_B    7140            // 64
#define CU_CV   7232            // 16*20*22 = 7040
#define CU_TOTF 14272           // floats
__global__ __launch_bounds__(256) void k_conv_up2(const float* __restrict__ in,
    const float* __restrict__ wt, const float* __restrict__ bias,
    float* __restrict__ outp)
{
    extern __shared__ __align__(16) float cus[];
    float* in_s = cus + CU_IN;      // [3][41][44]
    float* w_s  = cus + CU_W;       // [1728]
    float* b_s  = cus + CU_B;       // [64]
    float* cv   = cus + CU_CV;      // [16][20][22]
    const int tid = threadIdx.x;
    const int cy0 = blockIdx.y * 16, cx0 = blockIdx.x * 16, b = blockIdx.z;

    for (int i = tid; i < 1728; i += 256) w_s[i] = wt[i];
    if (tid < 64) b_s[tid] = bias[tid];
    // input tile: rows 2*cy0-5 .. +40, cols 2*cx0-5 .. +40 (zero padded)
    for (int idx = tid; idx < 3*41*41; idx += 256) {
        int c = idx / 1681, rem = idx % 1681, r = rem / 41, col = rem % 41;
        int gy = 2*cy0 - 5 + r, gx = 2*cx0 - 5 + col;
        float v = 0.f;
        if (gy >= 0 && gy < DH && gx >= 0 && gx < DH)
            v = in[((long)(b*3 + c) * DH + gy) * DH + gx];
        in_s[(c*41 + r) * 44 + col] = v;
    }
    __syncthreads();

#pragma unroll 1
    for (int g = 0; g < 4; ++g) {
        // conv: 20x20 x 16 channels (conv coords cy0-2 .. cy0+17)
        for (int idx = tid; idx < 16*400; idx += 256) {
            int ocl = idx / 400, rem = idx % 400, cr = rem / 20, cc = rem % 20;
            int oc = g*16 + ocl;
            const float* wk = w_s + oc*27;
            float acc = b_s[oc];
#pragma unroll
            for (int c = 0; c < 3; ++c) {
                const float* ip = in_s + (c*41 + 2*cr) * 44 + 2*cc;
#pragma unroll
                for (int ki = 0; ki < 3; ++ki)
#pragma unroll
                    for (int kj = 0; kj < 3; ++kj)
                        acc += ip[ki*44 + kj] * wk[c*9 + ki*3 + kj];
            }
            cv[(ocl*20 + cr) * 22 + cc] = acc;
        }
        __syncthreads();
        // up2: 32x32 positions x 16 channels
        for (int pos = tid; pos < 1024; pos += 256) {
            int oyl = pos >> 5, oxl = pos & 31;
            int oy = 2*cy0 + oyl, ox = 2*cx0 + oxl;
            int iy[4], ix[4]; float wy[4], wx[4];
            taps_up2(oy, 128, iy, wy);
            taps_up2(ox, 128, ix, wx);
            int ly[4], lxl[4];
#pragma unroll
            for (int t = 0; t < 4; ++t) {
                int l = iy[t] - (cy0 - 2);
                ly[t] = l < 0 ? 0 : (l > 19 ? 19 : l);
                l = ix[t] - (cx0 - 2);
                lxl[t] = l < 0 ? 0 : (l > 19 ? 19 : l);
            }
#pragma unroll 4
            for (int ocl = 0; ocl < 16; ++ocl) {
                const float* cvp = cv + ocl*440;
                float s = 0.f;
#pragma unroll
                for (int a = 0; a < 4; ++a) {
                    float r = 0.f;
#pragma unroll
                    for (int q = 0; q < 4; ++q) r += wx[q] * cvp[ly[a]*22 + lxl[q]];
                    s += wy[a] * r;
                }
                outp[(((long)b*64 + g*16 + ocl) * 256 + oy) * 256 + ox] = s;
            }
        }
        __syncthreads();
    }
}

// ---------------- launch: fork-join two streams ------------------------------
extern "C" void kernel_launch(void* const* d_in, const int* in_sizes, int n_in,
                              void* d_out, int out_size)
{
    const float* x      = (const float*)d_in[0];
    const float* W_in   = (const float*)d_in[1];
    const float* W_h1   = (const float*)d_in[2];
    const float* W_h2   = (const float*)d_in[3];
    const float* W_h3   = (const float*)d_in[4];
    const float* W_h4   = (const float*)d_in[5];
    const float* W_out  = (const float*)d_in[6];
    const float* feat_w = (const float*)d_in[7];
    const float* feat_b = (const float*)d_in[8];
    const float* mod_w  = (const float*)d_in[9];
    const float* mod_b  = (const float*)d_in[10];

    float* outF = (float*)d_out;
    float* dout_mod = outF;                       // 2*3*256*256   = 393216
    float* dout_hr  = outF + 393216;              // 2*64*256*256  = 8388608
    float* dout_new = outF + 8781824;             // 8388608
    float* dout_ori = outF + 17170432;            // 8388608
    float* dout_out = outF + 25559040;            // 393216

    float *downx, *outfull;
    cudaGetSymbolAddress((void**)&downx,   g_down_x);
    cudaGetSymbolAddress((void**)&outfull, g_out_full);

    static cudaStream_t s1 = nullptr, s2 = nullptr;
    static cudaEvent_t ev0, evdx, evw, evs1, evs2;
    if (!s1) {
        cudaStreamCreateWithFlags(&s1, cudaStreamNonBlocking);
        cudaStreamCreateWithFlags(&s2, cudaStreamNonBlocking);
        cudaEventCreateWithFlags(&ev0,  cudaEventDisableTiming);
        cudaEventCreateWithFlags(&evdx, cudaEventDisableTiming);
        cudaEventCreateWithFlags(&evw,  cudaEventDisableTiming);
        cudaEventCreateWithFlags(&evs1, cudaEventDisableTiming);
        cudaEventCreateWithFlags(&evs2, cudaEventDisableTiming);
        cudaFuncSetAttribute(fused_mlp_mma,
                             cudaFuncAttributeMaxDynamicSharedMemorySize, S_TOT);
        cudaFuncSetAttribute(k_conv_up2,
                             cudaFuncAttributeMaxDynamicSharedMemorySize, CU_TOTF*4);
    }

    cudaEventRecord(ev0, 0);
    cudaStreamWaitEvent(s1, ev0, 0);
    cudaStreamWaitEvent(s2, ev0, 0);

    // ---- stream 2 first: weight prep + independent features ----
    k_prep_w<<<320, 256, 0, s2>>>(W_h1, W_h2, W_h3, W_h4, W_out);
    cudaEventRecord(evw, s2);
    {
        dim3 g(16, 16, BB);
        k_conv3x3s2<<<g, 256, 0, s2>>>(x, feat_w, feat_b, dout_hr, 512);
    }

    // ---- stream 1: critical path ----
    k_down2<<<(BB*3*DH*DH + 255)/256, 256, 0, s1>>>(x, downx, BB*3, HH);
    cudaEventRecord(evdx, s1);
    cudaStreamWaitEvent(s1, evw, 0);
    fused_mlp_mma<<<MROWS/128, 256, S_TOT, s1>>>(x, W_in, outfull);
    k_down2_mod<<<(BB*DH*DH + 255)/256, 256, 0, s1>>>(outfull, downx, mod_w, mod_b,
                                                      dout_out, dout_mod);
    {
        dim3 g(8, 8, BB);
        k_conv_up2<<<g, 256, CU_TOTF*4, s1>>>(dout_mod, feat_w, feat_b, dout_new);
    }
    cudaEventRecord(evs1, s1);

    // ---- stream 2 continues: ori_lr_feature ----
    cudaStreamWaitEvent(s2, evdx, 0);
    {
        dim3 g(8, 8, BB);
        k_conv_up2<<<g, 256, CU_TOTF*4, s2>>>(downx, feat_w, feat_b, dout_ori);
    }
    cudaEventRecord(evs2, s2);

    cudaStreamWaitEvent(0, evs1, 0);
    cudaStreamWaitEvent(0, evs2, 0);
}

// round 16
// speedup vs baseline: 1.9145x; 1.0044x over previous
#include <cuda_runtime.h>
#include <cuda_fp16.h>
#include <cstdint>

#define HH 512
#define WW 512
#define DH 256
#define HWp (HH*WW)          // 262144
#define BB 2
#define MROWS (BB*HWp)       // 524288

// ---------------- scratch (device globals; no allocation allowed) ----------
__device__ float g_down_x[BB*3*DH*DH];                 // 1.5 MB
__device__ float g_out_full[BB*3*HH*WW];               // 6 MB
__device__ __align__(16) __half g_wHi[5][16384];       // [k][n] row-major, n padded to 128
__device__ __align__(16) __half g_wLo[5][16384];

// ---------------- mma/ldmatrix/stmatrix/cp.async helpers (base ISA) ---------
__device__ __forceinline__ uint32_t smem_u32(const void* p) {
    uint32_t a;
    asm("{ .reg .u64 t; cvta.to.shared.u64 t, %1; cvt.u32.u64 %0, t; }" : "=r"(a) : "l"(p));
    return a;
}
__device__ __forceinline__ void ldsm_x4(uint32_t addr, uint32_t r[4]) {
    asm volatile("ldmatrix.sync.aligned.m8n8.x4.shared.b16 {%0,%1,%2,%3}, [%4];"
        : "=r"(r[0]), "=r"(r[1]), "=r"(r[2]), "=r"(r[3]) : "r"(addr));
}
__device__ __forceinline__ void ldsm_x4t(uint32_t addr, uint32_t r[4]) {
    asm volatile("ldmatrix.sync.aligned.m8n8.x4.trans.shared.b16 {%0,%1,%2,%3}, [%4];"
        : "=r"(r[0]), "=r"(r[1]), "=r"(r[2]), "=r"(r[3]) : "r"(addr));
}
__device__ __forceinline__ void stsm_x4(uint32_t addr, uint32_t t0, uint32_t t1,
                                        uint32_t t2, uint32_t t3) {
    asm volatile("stmatrix.sync.aligned.m8n8.x4.shared.b16 [%0], {%1,%2,%3,%4};"
        :: "r"(addr), "r"(t0), "r"(t1), "r"(t2), "r"(t3) : "memory");
}
__device__ __forceinline__ void mma_f32(float d[4], const uint32_t a[4], const uint32_t* b) {
    asm volatile("mma.sync.aligned.m16n8k16.row.col.f32.f16.f16.f32 "
        "{%0,%1,%2,%3}, {%4,%5,%6,%7}, {%8,%9}, {%0,%1,%2,%3};"
        : "+f"(d[0]), "+f"(d[1]), "+f"(d[2]), "+f"(d[3])
        : "r"(a[0]), "r"(a[1]), "r"(a[2]), "r"(a[3]), "r"(b[0]), "r"(b[1]));
}
__device__ __forceinline__ void mma_f16(uint32_t d[2], const uint32_t a[4], const uint32_t* b) {
    asm volatile("mma.sync.aligned.m16n8k16.row.col.f16.f16.f16.f16 "
        "{%0,%1}, {%2,%3,%4,%5}, {%6,%7}, {%0,%1};"
        : "+r"(d[0]), "+r"(d[1])
        : "r"(a[0]), "r"(a[1]), "r"(a[2]), "r"(a[3]), "r"(b[0]), "r"(b[1]));
}
__device__ __forceinline__ void cp_async16(uint32_t dst, const void* src) {
    asm volatile("cp.async.cg.shared.global [%0], [%1], 16;" :: "r"(dst), "l"(src));
}
#define CP_COMMIT() asm volatile("cp.async.commit_group;" ::: "memory")
#define CP_WAIT(n)  asm volatile("cp.async.wait_group %0;" :: "n"(n) : "memory")

__device__ __forceinline__ uint32_t swz(int row, int cg) {
    return (uint32_t)(row * 256 + ((cg ^ (row & 7)) << 4));
}
__device__ __forceinline__ float lrelu(float v) { return v > 0.f ? v : 0.01f * v; }

// ---------------- bicubic tap helpers (match jax.image.resize, a=-0.5) -----
__device__ __forceinline__ void taps_down2(int o, int n, int idx[4], float w[4]) {
    const float kw0 = -0.0625f, kw1 = 0.5625f;
    float kw[4] = {kw0, kw1, kw1, kw0};
    float s = 0.f;
#pragma unroll
    for (int t = 0; t < 4; ++t) {
        int i = 2*o - 1 + t;
        bool ok = (i >= 0) && (i < n);
        idx[t] = ok ? i : 0;
        w[t]   = ok ? kw[t] : 0.f;
        s += w[t];
    }
    float inv = 1.f / s;
#pragma unroll
    for (int t = 0; t < 4; ++t) w[t] *= inv;
}
__device__ __forceinline__ void taps_up2(int o, int n, int idx[4], float w[4]) {
    int m = o >> 1;
    float kw[4];
    int base;
    if ((o & 1) == 0) {
        base = m - 2;
        kw[0] = -0.0234375f; kw[1] = 0.2265625f; kw[2] = 0.8671875f; kw[3] = -0.0703125f;
    } else {
        base = m - 1;
        kw[0] = -0.0703125f; kw[1] = 0.8671875f; kw[2] = 0.2265625f; kw[3] = -0.0234375f;
    }
    float s = 0.f;
#pragma unroll
    for (int t = 0; t < 4; ++t) {
        int i = base + t;
        bool ok = (i >= 0) && (i < n);
        idx[t] = ok ? i : 0;
        w[t]   = ok ? kw[t] : 0.f;
        s += w[t];
    }
    float inv = 1.f / s;
#pragma unroll
    for (int t = 0; t < 4; ++t) w[t] *= inv;
}

// ---------------- bicubic 2x down -------------------------------------------
__global__ void k_down2(const float* __restrict__ in, float* __restrict__ out1,
                        int Cn, int n_in)
{
    int n_out = n_in >> 1;
    long total = (long)Cn * n_out * n_out;
    long t = (long)blockIdx.x * blockDim.x + threadIdx.x;
    if (t >= total) return;
    int ox = (int)(t % n_out);
    int oy = (int)((t / n_out) % n_out);
    long c = t / ((long)n_out * n_out);
    int iy[4], ix[4]; float wy[4], wx[4];
    taps_down2(oy, n_in, iy, wy);
    taps_down2(ox, n_in, ix, wx);
    const float* ip = in + c * n_in * n_in;
    float s = 0.f;
#pragma unroll
    for (int a = 0; a < 4; ++a) {
        float r = 0.f;
#pragma unroll
        for (int b2 = 0; b2 < 4; ++b2) r += wx[b2] * ip[iy[a]*n_in + ix[b2]];
        s += wy[a] * r;
    }
    out1[t] = s;
}

// ---------------- fused: out = down2(out_full); down_x_mod = mod conv -------
__global__ void k_down2_mod(const float* __restrict__ of, const float* __restrict__ dx,
                            const float* __restrict__ mw, const float* __restrict__ mb,
                            float* __restrict__ dout_out, float* __restrict__ dout_mod)
{
    int t = blockIdx.x * 256 + threadIdx.x;
    if (t >= BB * DH * DH) return;
    int b = t >> 16, p = t & 65535;
    int oy = p >> 8, ox = p & 255;
    int iy[4], ix[4]; float wy[4], wx[4];
    taps_down2(oy, HH, iy, wy);
    taps_down2(ox, WW, ix, wx);
    float in6[6];
#pragma unroll
    for (int c = 0; c < 3; ++c) {
        const float* ip = of + (long)(b*3 + c) * HWp;
        float s = 0.f;
#pragma unroll
        for (int a = 0; a < 4; ++a) {
            float r = 0.f;
#pragma unroll
            for (int q = 0; q < 4; ++q) r += wx[q] * ip[iy[a]*WW + ix[q]];
            s += wy[a] * r;
        }
        dout_out[(b*3 + c)*65536 + p] = s;
        in6[3 + c] = s;
    }
#pragma unroll
    for (int c = 0; c < 3; ++c) in6[c] = dx[(b*3 + c)*65536 + p];
#pragma unroll
    for (int oc = 0; oc < 3; ++oc) {
        float a = mb[oc];
#pragma unroll
        for (int ic = 0; ic < 6; ++ic) a += in6[ic] * mw[oc*6 + ic];
        dout_mod[(b*3 + oc)*65536 + p] = a;
    }
}

// ---------------- weight prep: f32 -> (hi,lo) fp16, [k][n] n-padded --------
__global__ void k_prep_w(const float* __restrict__ W1, const float* __restrict__ W2,
                         const float* __restrict__ W3, const float* __restrict__ W4,
                         const float* __restrict__ Wout)
{
    int t = blockIdx.x * 256 + threadIdx.x;     // 5*16384 = 81920
    if (t >= 81920) return;
    int L = t >> 14, r = t & 16383;
    int k = r >> 7, n = r & 127;
    const float* W = (L == 0) ? W1 : (L == 1) ? W2 : (L == 2) ? W3 : (L == 3) ? W4 : Wout;
    float v = (L < 4) ? W[k * 128 + n] : ((n < 81) ? W[k * 81 + n] : 0.f);
    __half h = __float2half(v);
    g_wHi[L][r] = h;
    g_wLo[L][r] = __float2half(v - __half2float(h));
}

// ---------------- fused MLP + dynamic-filter apply --------------------------
// 128 px/CTA, 256 thr, 103.5KB smem, 2 CTAs/SM; down_x slice computed inline.
#define S_A   0
#define S_BHI 32768
#define S_BLO 65536
#define S_LW  32768
#define S_INP 98304
#define S_WIN 102400           // also holds dslice [3][4][68] during prologue
#define S_TOT 105984
#define LWST 84

__device__ __forceinline__ void st_hi2(char* smem, int row, int col,
                                       float v0, float v1)
{
    __half2 hp = __floats2half2_rn(v0, v1);
    *(uint32_t*)(smem + S_A + swz(row, col >> 3) + (col & 7) * 2) = *(uint32_t*)&hp;
}

__global__ __launch_bounds__(256, 2) void fused_mlp_mma(
    const float* __restrict__ x, const float* __restrict__ Win,
    float* __restrict__ outp)
{
    extern __shared__ __align__(16) char smem[];
    const uint32_t sb = smem_u32(smem);
    const int tid = threadIdx.x;
    const int wid = tid >> 5, lane = tid & 31;
    const long row0 = (long)blockIdx.x * 128;
    const int bimg = (int)(row0 >> 18);
    const int n0 = (int)(row0 & (HWp - 1));
    const int irow = n0 >> 9, j0 = n0 & 511;

    // kick off layer-0 weight staging (B region; no conflicts)
#pragma unroll
    for (int it = 0; it < 8; ++it) {
        int idx = it * 256 + tid;
        int row = idx >> 4, cg = idx & 15;
        uint32_t d = sb + S_BHI + swz(row, cg);
        cp_async16(d,         (const char*)g_wHi[0] + idx * 16);
        cp_async16(d + 32768, (const char*)g_wLo[0] + idx * 16);
    }
    CP_COMMIT();

    // ---- 1) inline down_x slice [3][4][68] into S_WIN region ----
    {
        float* ds = (float*)(smem + S_WIN);
        int iyg[4]; float wyg[4];
        taps_up2(irow, DH, iyg, wyg);
        const int c0 = (j0 >> 1) - 2;
        for (int idx = tid; idx < 816; idx += 256) {
            int c = idx / 272, rem = idx % 272, rl = rem / 68, cl = rem % 68;
            int dy = iyg[rl];
            int dc = c0 + cl;
            dc = dc < 0 ? 0 : (dc > DH-1 ? DH-1 : dc);
            int sy[4], sx[4]; float vy[4], vx[4];
            taps_down2(dy, HH, sy, vy);
            taps_down2(dc, WW, sx, vx);
            const float* ipx = x + (long)(bimg*3 + c) * HWp;
            float s = 0.f;
#pragma unroll
            for (int a = 0; a < 4; ++a) {
                float r = 0.f;
#pragma unroll
                for (int q = 0; q < 4; ++q) r += vx[q] * ipx[sy[a]*WW + sx[q]];
                s += vy[a] * r;
            }
            ds[(c*4 + rl) * 68 + cl] = s;
        }
    }
    __syncthreads();

    // ---- 2) per-pixel MLP inputs (reads dslice) ----
    if (tid < 128) {
        int i = irow, j = j0 + tid;
        int iy[4], ix[4]; float wy[4], wx[4];
        taps_up2(i, DH, iy, wy);
        taps_up2(j, DH, ix, wx);
        const int c0 = (j0 >> 1) - 2;
        int lxc[4];
#pragma unroll
        for (int t = 0; t < 4; ++t) {
            int l = ix[t] - c0;
            lxc[t] = l < 0 ? 0 : (l > 67 ? 67 : l);
        }
        const float* ds = (const float*)(smem + S_WIN);
        float* ip = (float*)(smem + S_INP) + tid * 8;
        ip[0] = (i & 1) ? 0.5f : -0.5f;
        ip[1] = (j & 1) ? 0.5f : -0.5f;
        ip[2] = 1.f; ip[3] = 1.f;
#pragma unroll
        for (int c = 0; c < 3; ++c) {
            const float* dsc = ds + c*4*68;
            float s = 0.f;
#pragma unroll
            for (int a = 0; a < 4; ++a) {
                float rr = 0.f;
#pragma unroll
                for (int b2 = 0; b2 < 4; ++b2) rr += wx[b2] * dsc[a*68 + lxc[b2]];
                s += wy[a] * rr;
            }
            ip[4 + c] = x[((long)(bimg*3 + c) * HH + i) * WW + j] - s;
        }
        ip[7] = 0.f;
    }
    __syncthreads();

    // ---- 3) stage W_in (overwrites dslice) ----
    for (int i = tid; i < 896; i += 256) *(float*)(smem + S_WIN + i*4) = Win[i];
    __syncthreads();

    // ---- 4) layer 0 (7 -> 128) SIMT ----
    {
        int row = tid >> 1;
        int cbase = (tid & 1) * 64;
        const float* ip = (const float*)(smem + S_INP) + row * 8;
        float a0 = ip[0], a1 = ip[1], a2 = ip[2], a3 = ip[3];
        float a4 = ip[4], a5 = ip[5], a6 = ip[6];
        const float* Wn = (const float*)(smem + S_WIN);
#pragma unroll 8
        for (int c = 0; c < 64; c += 2) {
            int o = cbase + c;
            float v0 = a0*Wn[o] + a1*Wn[128+o] + a2*Wn[256+o] + a3*Wn[384+o]
                     + a4*Wn[512+o] + a5*Wn[640+o] + a6*Wn[768+o];
            float v1 = a0*Wn[o+1] + a1*Wn[128+o+1] + a2*Wn[256+o+1] + a3*Wn[384+o+1]
                     + a4*Wn[512+o+1] + a5*Wn[640+o+1] + a6*Wn[768+o+1];
            st_hi2(smem, row, o, lrelu(v0), lrelu(v1));
        }
    }

    const int wm = wid & 1, wn = wid >> 1;
    const int lr = lane & 15, lh = lane >> 4, lx = lane & 7;

#pragma unroll 1
    for (int L = 0; L < 5; ++L) {
        CP_WAIT(0);
        __syncthreads();

        float acc[4][4][4];
        uint32_t c16[4][4][2];
#pragma unroll
        for (int mt = 0; mt < 4; ++mt)
#pragma unroll
            for (int nt = 0; nt < 4; ++nt) {
#pragma unroll
                for (int q = 0; q < 4; ++q) acc[mt][nt][q] = 0.f;
                c16[mt][nt][0] = 0u; c16[mt][nt][1] = 0u;
            }

        if (L < 4 || wn < 3) {
#pragma unroll 1
            for (int k = 0; k < 8; ++k) {
                uint32_t ah[4][4];
#pragma unroll
                for (int mt = 0; mt < 4; ++mt) {
                    uint32_t a = sb + S_A
                        + (uint32_t)((wm*64 + mt*16 + lr) * 256)
                        + (uint32_t)((((k*2 + lh) ^ lx)) << 4);
                    ldsm_x4(a, ah[mt]);
                }
#pragma unroll
                for (int np = 0; np < 2; ++np) {
                    uint32_t bh[4], bl[4];
                    uint32_t b = sb + S_BHI
                        + (uint32_t)((k*16 + lr) * 256)
                        + (uint32_t)(((wn*4 + np*2 + lh) ^ lx) << 4);
                    ldsm_x4t(b, bh);
                    ldsm_x4t(b + 32768, bl);
                    mma_f32(acc[0][np*2],   ah[0], bh);
                    mma_f32(acc[0][np*2+1], ah[0], bh + 2);
                    mma_f32(acc[1][np*2],   ah[1], bh);
                    mma_f32(acc[1][np*2+1], ah[1], bh + 2);
                    mma_f32(acc[2][np*2],   ah[2], bh);
                    mma_f32(acc[2][np*2+1], ah[2], bh + 2);
                    mma_f32(acc[3][np*2],   ah[3], bh);
                    mma_f32(acc[3][np*2+1], ah[3], bh + 2);
                    mma_f16(c16[0][np*2],   ah[0], bl);
                    mma_f16(c16[0][np*2+1], ah[0], bl + 2);
                    mma_f16(c16[1][np*2],   ah[1], bl);
                    mma_f16(c16[1][np*2+1], ah[1], bl + 2);
                    mma_f16(c16[2][np*2],   ah[2], bl);
                    mma_f16(c16[2][np*2+1], ah[2], bl + 2);
                    mma_f16(c16[3][np*2],   ah[3], bl);
                    mma_f16(c16[3][np*2+1], ah[3], bl + 2);
                }
            }
        }
        __syncthreads();

        if (L < 4) {
#pragma unroll
            for (int it = 0; it < 8; ++it) {
                int idx = it * 256 + tid;
                int row = idx >> 4, cg = idx & 15;
                uint32_t d = sb + S_BHI + swz(row, cg);
                cp_async16(d,         (const char*)g_wHi[L+1] + idx * 16);
                cp_async16(d + 32768, (const char*)g_wLo[L+1] + idx * 16);
            }
            CP_COMMIT();

#pragma unroll
            for (int mt = 0; mt < 4; ++mt) {
                int r = wm*64 + mt*16 + lr;
                uint32_t rowad = sb + S_A + (uint32_t)(r * 256);
#pragma unroll
                for (int ntp = 0; ntp < 2; ++ntp) {
                    int nt0 = ntp*2, nt1 = ntp*2 + 1;
                    __half2 pa = *(__half2*)&c16[mt][nt0][0];
                    __half2 pb = *(__half2*)&c16[mt][nt0][1];
                    __half2 pc = *(__half2*)&c16[mt][nt1][0];
                    __half2 pd = *(__half2*)&c16[mt][nt1][1];
                    __half2 h0 = __floats2half2_rn(
                        lrelu(acc[mt][nt0][0] + __half2float(pa.x)),
                        lrelu(acc[mt][nt0][1] + __half2float(pa.y)));
                    __half2 h1 = __floats2half2_rn(
                        lrelu(acc[mt][nt0][2] + __half2float(pb.x)),
                        lrelu(acc[mt][nt0][3] + __half2float(pb.y)));
                    __half2 h2 = __floats2half2_rn(
                        lrelu(acc[mt][nt1][0] + __half2float(pc.x)),
                        lrelu(acc[mt][nt1][1] + __half2float(pc.y)));
                    __half2 h3 = __floats2half2_rn(
                        lrelu(acc[mt][nt1][2] + __half2float(pd.x)),
                        lrelu(acc[mt][nt1][3] + __half2float(pd.y)));
                    uint32_t cg = (uint32_t)((wn*4 + ntp*2 + lh) ^ (r & 7));
                    stsm_x4(rowad + (cg << 4),
                            *(uint32_t*)&h0, *(uint32_t*)&h1,
                            *(uint32_t*)&h2, *(uint32_t*)&h3);
                }
            }
        } else {
            float* lwS = (float*)(smem + S_LW);
#pragma unroll
            for (int mt = 0; mt < 4; ++mt) {
                int r0 = wm*64 + mt*16 + (lane >> 2);
#pragma unroll
                for (int nt = 0; nt < 4; ++nt) {
                    int c = wn*32 + nt*8 + (lane & 3)*2;
                    __half2 p0 = *(__half2*)&c16[mt][nt][0];
                    __half2 p1 = *(__half2*)&c16[mt][nt][1];
                    if (c < 81) {
                        lwS[r0 * LWST + c]     = acc[mt][nt][0] + __half2float(p0.x);
                        lwS[(r0+8) * LWST + c] = acc[mt][nt][2] + __half2float(p1.x);
                    }
                    if (c + 1 < 81) {
                        lwS[r0 * LWST + c + 1]     = acc[mt][nt][1] + __half2float(p0.y);
                        lwS[(r0+8) * LWST + c + 1] = acc[mt][nt][3] + __half2float(p1.y);
                    }
                }
            }
        }
    }

    float* xp = (float*)(smem + S_INP);        // [3][3][132]
    for (int idx = tid; idx < 3*3*130; idx += 256) {
        int c = idx / 390, rem = idx % 390, ki = rem / 130, jj = rem % 130;
        int yy = irow + ki - 1;
        int xx = j0 + jj - 1;
        float v = 0.f;
        if (yy >= 0 && yy < HH && xx >= 0 && xx < WW)
            v = x[((long)(bimg*3 + c) * HH + yy) * WW + xx];
        xp[(c*3 + ki) * 132 + jj] = v;
    }
    __syncthreads();

    for (int idx = tid; idx < 384; idx += 256) {
        int p = idx & 127, oc = idx >> 7;
        const float* lwr = (const float*)(smem + S_LW) + p * LWST;
        float o = 0.f;
#pragma unroll
        for (int c = 0; c < 3; ++c)
#pragma unroll
            for (int ki = 0; ki < 3; ++ki) {
                const float* xr = xp + (c*3 + ki) * 132 + p;
#pragma unroll
                for (int kj = 0; kj < 3; ++kj)
                    o += xr[kj] * lwr[(c*9 + ki*3 + kj) * 3 + oc];
            }
        outp[(long)(bimg*3 + oc) * HWp + n0 + p] = o;
    }
}

// ---------------- 3x3 stride-2 pad-1 conv, 3 -> 64 channels (512 input) -----
__global__ __launch_bounds__(256) void k_conv3x3s2(const float* __restrict__ in,
    const float* __restrict__ wt, const float* __restrict__ bias,
    float* __restrict__ outp, int S)
{
    __shared__ float w_s[1728];
    __shared__ float in_s[3][33][33];
    int tid = threadIdx.x;
    for (int i = tid; i < 1728; i += 256) w_s[i] = wt[i];
    int OS = S >> 1;
    int ox0 = blockIdx.x * 16, oy0 = blockIdx.y * 16, b = blockIdx.z;
    for (int idx = tid; idx < 3*33*33; idx += 256) {
        int c = idx / 1089, rem = idx % 1089, r = rem / 33, col = rem % 33;
        int iy = oy0*2 - 1 + r, ix = ox0*2 - 1 + col;
        float v = 0.f;
        if (iy >= 0 && iy < S && ix >= 0 && ix < S)
            v = in[((long)(b*3 + c) * S + iy) * S + ix];
        in_s[c][r][col] = v;
    }
    __syncthreads();
    int ox = tid & 15, oy = tid >> 4;
    float pix[27];
#pragma unroll
    for (int c = 0; c < 3; ++c)
#pragma unroll
        for (int ki = 0; ki < 3; ++ki)
#pragma unroll
            for (int kj = 0; kj < 3; ++kj)
                pix[c*9 + ki*3 + kj] = in_s[c][2*oy + ki][2*ox + kj];
#pragma unroll 4
    for (int oc = 0; oc < 64; ++oc) {
        float acc = bias[oc];
#pragma unroll
        for (int q = 0; q < 27; ++q) acc += pix[q] * w_s[oc*27 + q];
        outp[(((long)b*64 + oc) * OS + oy0 + oy) * OS + ox0 + ox] = acc;
    }
}

// ---------------- fused conv3x3s2(256->128) + bicubic up2(128->256) ---------
#define CU_IN   0               // 3*41*44 floats = 5412
#define CU_W    5412            // 1728
#define CU_B    7140            // 64
#define CU_CV   7232            // 16*20*22 = 7040
#define CU_TOTF 14272           // floats
__global__ __launch_bounds__(256) void k_conv_up2(const float* __restrict__ in,
    const float* __restrict__ wt, const float* __restrict__ bias,
    float* __restrict__ outp)
{
    extern __shared__ __align__(16) float cus[];
    float* in_s = cus + CU_IN;
    float* w_s  = cus + CU_W;
    float* b_s  = cus + CU_B;
    float* cv   = cus + CU_CV;
    const int tid = threadIdx.x;
    const int cy0 = blockIdx.y * 16, cx0 = blockIdx.x * 16, b = blockIdx.z;

    for (int i = tid; i < 1728; i += 256) w_s[i] = wt[i];
    if (tid < 64) b_s[tid] = bias[tid];
    for (int idx = tid; idx < 3*41*41; idx += 256) {
        int c = idx / 1681, rem = idx % 1681, r = rem / 41, col = rem % 41;
        int gy = 2*cy0 - 5 + r, gx = 2*cx0 - 5 + col;
        float v = 0.f;
        if (gy >= 0 && gy < DH && gx >= 0 && gx < DH)
            v = in[((long)(b*3 + c) * DH + gy) * DH + gx];
        in_s[(c*41 + r) * 44 + col] = v;
    }
    __syncthreads();

#pragma unroll 1
    for (int g = 0; g < 4; ++g) {
        for (int idx = tid; idx < 16*400; idx += 256) {
            int ocl = idx / 400, rem = idx % 400, cr = rem / 20, cc = rem % 20;
            int oc = g*16 + ocl;
            const float* wk = w_s + oc*27;
            float acc = b_s[oc];
#pragma unroll
            for (int c = 0; c < 3; ++c) {
                const float* ip = in_s + (c*41 + 2*cr) * 44 + 2*cc;
#pragma unroll
                for (int ki = 0; ki < 3; ++ki)
#pragma unroll
                    for (int kj = 0; kj < 3; ++kj)
                        acc += ip[ki*44 + kj] * wk[c*9 + ki*3 + kj];
            }
            cv[(ocl*20 + cr) * 22 + cc] = acc;
        }
        __syncthreads();
        for (int pos = tid; pos < 1024; pos += 256) {
            int oyl = pos >> 5, oxl = pos & 31;
            int oy = 2*cy0 + oyl, ox = 2*cx0 + oxl;
            int iy[4], ix[4]; float wy[4], wx[4];
            taps_up2(oy, 128, iy, wy);
            taps_up2(ox, 128, ix, wx);
            int ly[4], lxl[4];
#pragma unroll
            for (int t = 0; t < 4; ++t) {
                int l = iy[t] - (cy0 - 2);
                ly[t] = l < 0 ? 0 : (l > 19 ? 19 : l);
                l = ix[t] - (cx0 - 2);
                lxl[t] = l < 0 ? 0 : (l > 19 ? 19 : l);
            }
#pragma unroll 4
            for (int ocl = 0; ocl < 16; ++ocl) {
                const float* cvp = cv + ocl*440;
                float s = 0.f;
#pragma unroll
                for (int a = 0; a < 4; ++a) {
                    float r = 0.f;
#pragma unroll
                    for (int q = 0; q < 4; ++q) r += wx[q] * cvp[ly[a]*22 + lxl[q]];
                    s += wy[a] * r;
                }
                outp[(((long)b*64 + g*16 + ocl) * 256 + oy) * 256 + ox] = s;
            }
        }
        __syncthreads();
    }
}

// ---------------- launch: fork-join two streams (capture-legal order) --------
extern "C" void kernel_launch(void* const* d_in, const int* in_sizes, int n_in,
                              void* d_out, int out_size)
{
    const float* x      = (const float*)d_in[0];
    const float* W_in   = (const float*)d_in[1];
    const float* W_h1   = (const float*)d_in[2];
    const float* W_h2   = (const float*)d_in[3];
    const float* W_h3   = (const float*)d_in[4];
    const float* W_h4   = (const float*)d_in[5];
    const float* W_out  = (const float*)d_in[6];
    const float* feat_w = (const float*)d_in[7];
    const float* feat_b = (const float*)d_in[8];
    const float* mod_w  = (const float*)d_in[9];
    const float* mod_b  = (const float*)d_in[10];

    float* outF = (float*)d_out;
    float* dout_mod = outF;                       // 2*3*256*256   = 393216
    float* dout_hr  = outF + 393216;              // 2*64*256*256  = 8388608
    float* dout_new = outF + 8781824;             // 8388608
    float* dout_ori = outF + 17170432;            // 8388608
    float* dout_out = outF + 25559040;            // 393216

    float *downx, *outfull;
    cudaGetSymbolAddress((void**)&downx,   g_down_x);
    cudaGetSymbolAddress((void**)&outfull, g_out_full);

    static cudaStream_t s1 = nullptr, s2 = nullptr;
    static cudaEvent_t ev0, evdx, evs1, evs2;
    if (!s1) {
        cudaStreamCreateWithFlags(&s1, cudaStreamNonBlocking);
        cudaStreamCreateWithFlags(&s2, cudaStreamNonBlocking);
        cudaEventCreateWithFlags(&ev0,  cudaEventDisableTiming);
        cudaEventCreateWithFlags(&evdx, cudaEventDisableTiming);
        cudaEventCreateWithFlags(&evs1, cudaEventDisableTiming);
        cudaEventCreateWithFlags(&evs2, cudaEventDisableTiming);
        cudaFuncSetAttribute(fused_mlp_mma,
                             cudaFuncAttributeMaxDynamicSharedMemorySize, S_TOT);
        cudaFuncSetAttribute(k_conv_up2,
                             cudaFuncAttributeMaxDynamicSharedMemorySize, CU_TOTF*4);
    }

    cudaEventRecord(ev0, 0);
    cudaStreamWaitEvent(s1, ev0, 0);
    cudaStreamWaitEvent(s2, ev0, 0);

    // ---- stream 2 FIRST: down2 + record evdx (must precede s1's wait) ----
    k_down2<<<(BB*3*DH*DH + 255)/256, 256, 0, s2>>>(x, downx, BB*3, HH);
    cudaEventRecord(evdx, s2);

    // ---- stream 1: critical path ----
    k_prep_w<<<320, 256, 0, s1>>>(W_h1, W_h2, W_h3, W_h4, W_out);
    fused_mlp_mma<<<MROWS/128, 256, S_TOT, s1>>>(x, W_in, outfull);
    cudaStreamWaitEvent(s1, evdx, 0);            // down2_mod needs downx
    k_down2_mod<<<(BB*DH*DH + 255)/256, 256, 0, s1>>>(outfull, downx, mod_w, mod_b,
                                                      dout_out, dout_mod);
    {
        dim3 g(8, 8, BB);
        k_conv_up2<<<g, 256, CU_TOTF*4, s1>>>(dout_mod, feat_w, feat_b, dout_new);
    }
    cudaEventRecord(evs1, s1);

    // ---- stream 2 continues: independent features ----
    {
        dim3 g(16, 16, BB);
        k_conv3x3s2<<<g, 256, 0, s2>>>(x, feat_w, feat_b, dout_hr, 512);
    }
    {
        dim3 g(8, 8, BB);
        k_conv_up2<<<g, 256, CU_TOTF*4, s2>>>(downx, feat_w, feat_b, dout_ori);
    }
    cudaEventRecord(evs2, s2);

    cudaStreamWaitEvent(0, evs1, 0);
    cudaStreamWaitEvent(0, evs2, 0);
}

// round 17
// speedup vs baseline: 2.0598x; 1.0759x over previous
#include <cuda_runtime.h>
#include <cuda_fp16.h>
#include <cstdint>

#define HH 512
#define WW 512
#define DH 256
#define HWp (HH*WW)          // 262144
#define BB 2
#define MROWS (BB*HWp)       // 524288

// ---------------- scratch (device globals; no allocation allowed) ----------
__device__ float g_down_x[BB*3*DH*DH];                 // 1.5 MB
__device__ float g_out_full[BB*3*HH*WW];               // 6 MB
__device__ __align__(16) __half g_wHi[5][16384];       // [k][n] row-major, n padded to 128
__device__ __align__(16) __half g_wLo[5][16384];

// ---------------- mma/ldmatrix/stmatrix/cp.async helpers (base ISA) ---------
__device__ __forceinline__ uint32_t smem_u32(const void* p) {
    uint32_t a;
    asm("{ .reg .u64 t; cvta.to.shared.u64 t, %1; cvt.u32.u64 %0, t; }" : "=r"(a) : "l"(p));
    return a;
}
__device__ __forceinline__ void ldsm_x4(uint32_t addr, uint32_t r[4]) {
    asm volatile("ldmatrix.sync.aligned.m8n8.x4.shared.b16 {%0,%1,%2,%3}, [%4];"
        : "=r"(r[0]), "=r"(r[1]), "=r"(r[2]), "=r"(r[3]) : "r"(addr));
}
__device__ __forceinline__ void ldsm_x4t(uint32_t addr, uint32_t r[4]) {
    asm volatile("ldmatrix.sync.aligned.m8n8.x4.trans.shared.b16 {%0,%1,%2,%3}, [%4];"
        : "=r"(r[0]), "=r"(r[1]), "=r"(r[2]), "=r"(r[3]) : "r"(addr));
}
__device__ __forceinline__ void stsm_x4(uint32_t addr, uint32_t t0, uint32_t t1,
                                        uint32_t t2, uint32_t t3) {
    asm volatile("stmatrix.sync.aligned.m8n8.x4.shared.b16 [%0], {%1,%2,%3,%4};"
        :: "r"(addr), "r"(t0), "r"(t1), "r"(t2), "r"(t3) : "memory");
}
__device__ __forceinline__ void mma_f32(float d[4], const uint32_t a[4], const uint32_t* b) {
    asm volatile("mma.sync.aligned.m16n8k16.row.col.f32.f16.f16.f32 "
        "{%0,%1,%2,%3}, {%4,%5,%6,%7}, {%8,%9}, {%0,%1,%2,%3};"
        : "+f"(d[0]), "+f"(d[1]), "+f"(d[2]), "+f"(d[3])
        : "r"(a[0]), "r"(a[1]), "r"(a[2]), "r"(a[3]), "r"(b[0]), "r"(b[1]));
}
__device__ __forceinline__ void mma_f16(uint32_t d[2], const uint32_t a[4], const uint32_t* b) {
    asm volatile("mma.sync.aligned.m16n8k16.row.col.f16.f16.f16.f16 "
        "{%0,%1}, {%2,%3,%4,%5}, {%6,%7}, {%0,%1};"
        : "+r"(d[0]), "+r"(d[1])
        : "r"(a[0]), "r"(a[1]), "r"(a[2]), "r"(a[3]), "r"(b[0]), "r"(b[1]));
}
__device__ __forceinline__ void cp_async16(uint32_t dst, const void* src) {
    asm volatile("cp.async.cg.shared.global [%0], [%1], 16;" :: "r"(dst), "l"(src));
}
#define CP_COMMIT() asm volatile("cp.async.commit_group;" ::: "memory")
#define CP_WAIT(n)  asm volatile("cp.async.wait_group %0;" :: "n"(n) : "memory")

__device__ __forceinline__ uint32_t swz(int row, int cg) {
    return (uint32_t)(row * 256 + ((cg ^ (row & 7)) << 4));
}
__device__ __forceinline__ float lrelu(float v) { return v > 0.f ? v : 0.01f * v; }

// ---------------- bicubic tap helpers (match jax.image.resize, a=-0.5) -----
__device__ __forceinline__ void taps_down2(int o, int n, int idx[4], float w[4]) {
    const float kw0 = -0.0625f, kw1 = 0.5625f;
    float kw[4] = {kw0, kw1, kw1, kw0};
    float s = 0.f;
#pragma unroll
    for (int t = 0; t < 4; ++t) {
        int i = 2*o - 1 + t;
        bool ok = (i >= 0) && (i < n);
        idx[t] = ok ? i : 0;
        w[t]   = ok ? kw[t] : 0.f;
        s += w[t];
    }
    float inv = 1.f / s;
#pragma unroll
    for (int t = 0; t < 4; ++t) w[t] *= inv;
}
__device__ __forceinline__ void taps_up2(int o, int n, int idx[4], float w[4]) {
    int m = o >> 1;
    float kw[4];
    int base;
    if ((o & 1) == 0) {
        base = m - 2;
        kw[0] = -0.0234375f; kw[1] = 0.2265625f; kw[2] = 0.8671875f; kw[3] = -0.0703125f;
    } else {
        base = m - 1;
        kw[0] = -0.0703125f; kw[1] = 0.8671875f; kw[2] = 0.2265625f; kw[3] = -0.0234375f;
    }
    float s = 0.f;
#pragma unroll
    for (int t = 0; t < 4; ++t) {
        int i = base + t;
        bool ok = (i >= 0) && (i < n);
        idx[t] = ok ? i : 0;
        w[t]   = ok ? kw[t] : 0.f;
        s += w[t];
    }
    float inv = 1.f / s;
#pragma unroll
    for (int t = 0; t < 4; ++t) w[t] *= inv;
}

// ---------------- bicubic 2x down -------------------------------------------
__global__ void k_down2(const float* __restrict__ in, float* __restrict__ out1,
                        int Cn, int n_in)
{
    int n_out = n_in >> 1;
    long total = (long)Cn * n_out * n_out;
    long t = (long)blockIdx.x * blockDim.x + threadIdx.x;
    if (t >= total) return;
    int ox = (int)(t % n_out);
    int oy = (int)((t / n_out) % n_out);
    long c = t / ((long)n_out * n_out);
    int iy[4], ix[4]; float wy[4], wx[4];
    taps_down2(oy, n_in, iy, wy);
    taps_down2(ox, n_in, ix, wx);
    const float* ip = in + c * n_in * n_in;
    float s = 0.f;
#pragma unroll
    for (int a = 0; a < 4; ++a) {
        float r = 0.f;
#pragma unroll
        for (int b2 = 0; b2 < 4; ++b2) r += wx[b2] * ip[iy[a]*n_in + ix[b2]];
        s += wy[a] * r;
    }
    out1[t] = s;
}

// ---------------- fused: out = down2(out_full); down_x_mod = mod conv -------
__global__ void k_down2_mod(const float* __restrict__ of, const float* __restrict__ dx,
                            const float* __restrict__ mw, const float* __restrict__ mb,
                            float* __restrict__ dout_out, float* __restrict__ dout_mod)
{
    int t = blockIdx.x * 256 + threadIdx.x;
    if (t >= BB * DH * DH) return;
    int b = t >> 16, p = t & 65535;
    int oy = p >> 8, ox = p & 255;
    int iy[4], ix[4]; float wy[4], wx[4];
    taps_down2(oy, HH, iy, wy);
    taps_down2(ox, WW, ix, wx);
    float in6[6];
#pragma unroll
    for (int c = 0; c < 3; ++c) {
        const float* ip = of + (long)(b*3 + c) * HWp;
        float s = 0.f;
#pragma unroll
        for (int a = 0; a < 4; ++a) {
            float r = 0.f;
#pragma unroll
            for (int q = 0; q < 4; ++q) r += wx[q] * ip[iy[a]*WW + ix[q]];
            s += wy[a] * r;
        }
        dout_out[(b*3 + c)*65536 + p] = s;
        in6[3 + c] = s;
    }
#pragma unroll
    for (int c = 0; c < 3; ++c) in6[c] = dx[(b*3 + c)*65536 + p];
#pragma unroll
    for (int oc = 0; oc < 3; ++oc) {
        float a = mb[oc];
#pragma unroll
        for (int ic = 0; ic < 6; ++ic) a += in6[ic] * mw[oc*6 + ic];
        dout_mod[(b*3 + oc)*65536 + p] = a;
    }
}

// ---------------- weight prep: f32 -> (hi,lo) fp16, [k][n] n-padded --------
__global__ void k_prep_w(const float* __restrict__ W1, const float* __restrict__ W2,
                         const float* __restrict__ W3, const float* __restrict__ W4,
                         const float* __restrict__ Wout)
{
    int t = blockIdx.x * 256 + threadIdx.x;     // 5*16384 = 81920
    if (t >= 81920) return;
    int L = t >> 14, r = t & 16383;
    int k = r >> 7, n = r & 127;
    const float* W = (L == 0) ? W1 : (L == 1) ? W2 : (L == 2) ? W3 : (L == 3) ? W4 : Wout;
    float v = (L < 4) ? W[k * 128 + n] : ((n < 81) ? W[k * 81 + n] : 0.f);
    __half h = __float2half(v);
    g_wHi[L][r] = h;
    g_wLo[L][r] = __float2half(v - __half2float(h));
}

// ---------------- fused MLP + dynamic-filter apply --------------------------
// 128 px/CTA, 256 thr, 103.5KB smem, 2 CTAs/SM; down_x slice inline;
// weight-lo correction applied on layers 0,2,4 only (L=1,3 skip).
#define S_A   0
#define S_BHI 32768
#define S_BLO 65536
#define S_LW  32768
#define S_INP 98304
#define S_WIN 102400           // also holds dslice [3][4][68] during prologue
#define S_TOT 105984
#define LWST 84

__device__ __forceinline__ void st_hi2(char* smem, int row, int col,
                                       float v0, float v1)
{
    __half2 hp = __floats2half2_rn(v0, v1);
    *(uint32_t*)(smem + S_A + swz(row, col >> 3) + (col & 7) * 2) = *(uint32_t*)&hp;
}

__global__ __launch_bounds__(256, 2) void fused_mlp_mma(
    const float* __restrict__ x, const float* __restrict__ Win,
    float* __restrict__ outp)
{
    extern __shared__ __align__(16) char smem[];
    const uint32_t sb = smem_u32(smem);
    const int tid = threadIdx.x;
    const int wid = tid >> 5, lane = tid & 31;
    const long row0 = (long)blockIdx.x * 128;
    const int bimg = (int)(row0 >> 18);
    const int n0 = (int)(row0 & (HWp - 1));
    const int irow = n0 >> 9, j0 = n0 & 511;

    // kick off layer-0 weight staging (hi + lo: layer 0 uses correction)
#pragma unroll
    for (int it = 0; it < 8; ++it) {
        int idx = it * 256 + tid;
        int row = idx >> 4, cg = idx & 15;
        uint32_t d = sb + S_BHI + swz(row, cg);
        cp_async16(d,         (const char*)g_wHi[0] + idx * 16);
        cp_async16(d + 32768, (const char*)g_wLo[0] + idx * 16);
    }
    CP_COMMIT();

    // ---- 1) inline down_x slice [3][4][68] into S_WIN region ----
    {
        float* ds = (float*)(smem + S_WIN);
        int iyg[4]; float wyg[4];
        taps_up2(irow, DH, iyg, wyg);
        const int c0 = (j0 >> 1) - 2;
        for (int idx = tid; idx < 816; idx += 256) {
            int c = idx / 272, rem = idx % 272, rl = rem / 68, cl = rem % 68;
            int dy = iyg[rl];
            int dc = c0 + cl;
            dc = dc < 0 ? 0 : (dc > DH-1 ? DH-1 : dc);
            int sy[4], sx[4]; float vy[4], vx[4];
            taps_down2(dy, HH, sy, vy);
            taps_down2(dc, WW, sx, vx);
            const float* ipx = x + (long)(bimg*3 + c) * HWp;
            float s = 0.f;
#pragma unroll
            for (int a = 0; a < 4; ++a) {
                float r = 0.f;
#pragma unroll
                for (int q = 0; q < 4; ++q) r += vx[q] * ipx[sy[a]*WW + sx[q]];
                s += vy[a] * r;
            }
            ds[(c*4 + rl) * 68 + cl] = s;
        }
    }
    __syncthreads();

    // ---- 2) per-pixel MLP inputs (reads dslice) ----
    if (tid < 128) {
        int i = irow, j = j0 + tid;
        int iy[4], ix[4]; float wy[4], wx[4];
        taps_up2(i, DH, iy, wy);
        taps_up2(j, DH, ix, wx);
        const int c0 = (j0 >> 1) - 2;
        int lxc[4];
#pragma unroll
        for (int t = 0; t < 4; ++t) {
            int l = ix[t] - c0;
            lxc[t] = l < 0 ? 0 : (l > 67 ? 67 : l);
        }
        const float* ds = (const float*)(smem + S_WIN);
        float* ip = (float*)(smem + S_INP) + tid * 8;
        ip[0] = (i & 1) ? 0.5f : -0.5f;
        ip[1] = (j & 1) ? 0.5f : -0.5f;
        ip[2] = 1.f; ip[3] = 1.f;
#pragma unroll
        for (int c = 0; c < 3; ++c) {
            const float* dsc = ds + c*4*68;
            float s = 0.f;
#pragma unroll
            for (int a = 0; a < 4; ++a) {
                float rr = 0.f;
#pragma unroll
                for (int b2 = 0; b2 < 4; ++b2) rr += wx[b2] * dsc[a*68 + lxc[b2]];
                s += wy[a] * rr;
            }
            ip[4 + c] = x[((long)(bimg*3 + c) * HH + i) * WW + j] - s;
        }
        ip[7] = 0.f;
    }
    __syncthreads();

    // ---- 3) stage W_in (overwrites dslice) ----
    for (int i = tid; i < 896; i += 256) *(float*)(smem + S_WIN + i*4) = Win[i];
    __syncthreads();

    // ---- 4) layer 0 (7 -> 128) SIMT ----
    {
        int row = tid >> 1;
        int cbase = (tid & 1) * 64;
        const float* ip = (const float*)(smem + S_INP) + row * 8;
        float a0 = ip[0], a1 = ip[1], a2 = ip[2], a3 = ip[3];
        float a4 = ip[4], a5 = ip[5], a6 = ip[6];
        const float* Wn = (const float*)(smem + S_WIN);
#pragma unroll 8
        for (int c = 0; c < 64; c += 2) {
            int o = cbase + c;
            float v0 = a0*Wn[o] + a1*Wn[128+o] + a2*Wn[256+o] + a3*Wn[384+o]
                     + a4*Wn[512+o] + a5*Wn[640+o] + a6*Wn[768+o];
            float v1 = a0*Wn[o+1] + a1*Wn[128+o+1] + a2*Wn[256+o+1] + a3*Wn[384+o+1]
                     + a4*Wn[512+o+1] + a5*Wn[640+o+1] + a6*Wn[768+o+1];
            st_hi2(smem, row, o, lrelu(v0), lrelu(v1));
        }
    }

    const int wm = wid & 1, wn = wid >> 1;
    const int lr = lane & 15, lh = lane >> 4, lx = lane & 7;

#pragma unroll 1
    for (int L = 0; L < 5; ++L) {
        CP_WAIT(0);
        __syncthreads();

        const bool corr = ((L & 1) == 0);   // weight-lo correction on L=0,2,4

        float acc[4][4][4];
        uint32_t c16[4][4][2];
#pragma unroll
        for (int mt = 0; mt < 4; ++mt)
#pragma unroll
            for (int nt = 0; nt < 4; ++nt) {
#pragma unroll
                for (int q = 0; q < 4; ++q) acc[mt][nt][q] = 0.f;
                c16[mt][nt][0] = 0u; c16[mt][nt][1] = 0u;
            }

        if (L < 4 || wn < 3) {
#pragma unroll 1
            for (int k = 0; k < 8; ++k) {
                uint32_t ah[4][4];
#pragma unroll
                for (int mt = 0; mt < 4; ++mt) {
                    uint32_t a = sb + S_A
                        + (uint32_t)((wm*64 + mt*16 + lr) * 256)
                        + (uint32_t)((((k*2 + lh) ^ lx)) << 4);
                    ldsm_x4(a, ah[mt]);
                }
#pragma unroll
                for (int np = 0; np < 2; ++np) {
                    uint32_t bh[4];
                    uint32_t b = sb + S_BHI
                        + (uint32_t)((k*16 + lr) * 256)
                        + (uint32_t)(((wn*4 + np*2 + lh) ^ lx) << 4);
                    ldsm_x4t(b, bh);
                    mma_f32(acc[0][np*2],   ah[0], bh);
                    mma_f32(acc[0][np*2+1], ah[0], bh + 2);
                    mma_f32(acc[1][np*2],   ah[1], bh);
                    mma_f32(acc[1][np*2+1], ah[1], bh + 2);
                    mma_f32(acc[2][np*2],   ah[2], bh);
                    mma_f32(acc[2][np*2+1], ah[2], bh + 2);
                    mma_f32(acc[3][np*2],   ah[3], bh);
                    mma_f32(acc[3][np*2+1], ah[3], bh + 2);
                    if (corr) {
                        uint32_t bl[4];
                        ldsm_x4t(b + 32768, bl);
                        mma_f16(c16[0][np*2],   ah[0], bl);
                        mma_f16(c16[0][np*2+1], ah[0], bl + 2);
                        mma_f16(c16[1][np*2],   ah[1], bl);
                        mma_f16(c16[1][np*2+1], ah[1], bl + 2);
                        mma_f16(c16[2][np*2],   ah[2], bl);
                        mma_f16(c16[2][np*2+1], ah[2], bl + 2);
                        mma_f16(c16[3][np*2],   ah[3], bl);
                        mma_f16(c16[3][np*2+1], ah[3], bl + 2);
                    }
                }
            }
        }
        __syncthreads();

        if (L < 4) {
            // prefetch next layer's weights (lo only if L+1 uses correction)
#pragma unroll
            for (int it = 0; it < 8; ++it) {
                int idx = it * 256 + tid;
                int row = idx >> 4, cg = idx & 15;
                uint32_t d = sb + S_BHI + swz(row, cg);
                cp_async16(d, (const char*)g_wHi[L+1] + idx * 16);
                if (((L + 1) & 1) == 0)
                    cp_async16(d + 32768, (const char*)g_wLo[L+1] + idx * 16);
            }
            CP_COMMIT();

            // stmatrix epilogue: C-fragment layout == ldmatrix 8x8 layout
#pragma unroll
            for (int mt = 0; mt < 4; ++mt) {
                int r = wm*64 + mt*16 + lr;
                uint32_t rowad = sb + S_A + (uint32_t)(r * 256);
#pragma unroll
                for (int ntp = 0; ntp < 2; ++ntp) {
                    int nt0 = ntp*2, nt1 = ntp*2 + 1;
                    __half2 pa = *(__half2*)&c16[mt][nt0][0];
                    __half2 pb = *(__half2*)&c16[mt][nt0][1];
                    __half2 pc = *(__half2*)&c16[mt][nt1][0];
                    __half2 pd = *(__half2*)&c16[mt][nt1][1];
                    __half2 h0 = __floats2half2_rn(
                        lrelu(acc[mt][nt0][0] + __half2float(pa.x)),
                        lrelu(acc[mt][nt0][1] + __half2float(pa.y)));
                    __half2 h1 = __floats2half2_rn(
                        lrelu(acc[mt][nt0][2] + __half2float(pb.x)),
                        lrelu(acc[mt][nt0][3] + __half2float(pb.y)));
                    __half2 h2 = __floats2half2_rn(
                        lrelu(acc[mt][nt1][0] + __half2float(pc.x)),
                        lrelu(acc[mt][nt1][1] + __half2float(pc.y)));
                    __half2 h3 = __floats2half2_rn(
                        lrelu(acc[mt][nt1][2] + __half2float(pd.x)),
                        lrelu(acc[mt][nt1][3] + __half2float(pd.y)));
                    uint32_t cg = (uint32_t)((wn*4 + ntp*2 + lh) ^ (r & 7));
                    stsm_x4(rowad + (cg << 4),
                            *(uint32_t*)&h0, *(uint32_t*)&h1,
                            *(uint32_t*)&h2, *(uint32_t*)&h3);
                }
            }
        } else {
            float* lwS = (float*)(smem + S_LW);
#pragma unroll
            for (int mt = 0; mt < 4; ++mt) {
                int r0 = wm*64 + mt*16 + (lane >> 2);
#pragma unroll
                for (int nt = 0; nt < 4; ++nt) {
                    int c = wn*32 + nt*8 + (lane & 3)*2;
                    __half2 p0 = *(__half2*)&c16[mt][nt][0];
                    __half2 p1 = *(__half2*)&c16[mt][nt][1];
                    if (c < 81) {
                        lwS[r0 * LWST + c]     = acc[mt][nt][0] + __half2float(p0.x);
                        lwS[(r0+8) * LWST + c] = acc[mt][nt][2] + __half2float(p1.x);
                    }
                    if (c + 1 < 81) {
                        lwS[r0 * LWST + c + 1]     = acc[mt][nt][1] + __half2float(p0.y);
                        lwS[(r0+8) * LWST + c + 1] = acc[mt][nt][3] + __half2float(p1.y);
                    }
                }
            }
        }
    }

    float* xp = (float*)(smem + S_INP);        // [3][3][132]
    for (int idx = tid; idx < 3*3*130; idx += 256) {
        int c = idx / 390, rem = idx % 390, ki = rem / 130, jj = rem % 130;
        int yy = irow + ki - 1;
        int xx = j0 + jj - 1;
        float v = 0.f;
        if (yy >= 0 && yy < HH && xx >= 0 && xx < WW)
            v = x[((long)(bimg*3 + c) * HH + yy) * WW + xx];
        xp[(c*3 + ki) * 132 + jj] = v;
    }
    __syncthreads();

    for (int idx = tid; idx < 384; idx += 256) {
        int p = idx & 127, oc = idx >> 7;
        const float* lwr = (const float*)(smem + S_LW) + p * LWST;
        float o = 0.f;
#pragma unroll
        for (int c = 0; c < 3; ++c)
#pragma unroll
            for (int ki = 0; ki < 3; ++ki) {
                const float* xr = xp + (c*3 + ki) * 132 + p;
#pragma unroll
                for (int kj = 0; kj < 3; ++kj)
                    o += xr[kj] * lwr[(c*9 + ki*3 + kj) * 3 + oc];
            }
        outp[(long)(bimg*3 + oc) * HWp + n0 + p] = o;
    }
}

// ---------------- 3x3 stride-2 pad-1 conv, 3 -> 64 channels (512 input) -----
__global__ __launch_bounds__(256) void k_conv3x3s2(const float* __restrict__ in,
    const float* __restrict__ wt, const float* __restrict__ bias,
    float* __restrict__ outp, int S)
{
    __shared__ float w_s[1728];
    __shared__ float in_s[3][33][33];
    int tid = threadIdx.x;
    for (int i = tid; i < 1728; i += 256) w_s[i] = wt[i];
    int OS = S >> 1;
    int ox0 = blockIdx.x * 16, oy0 = blockIdx.y * 16, b = blockIdx.z;
    for (int idx = tid; idx < 3*33*33; idx += 256) {
        int c = idx / 1089, rem = idx % 1089, r = rem / 33, col = rem % 33;
        int iy = oy0*2 - 1 + r, ix = ox0*2 - 1 + col;
        float v = 0.f;
        if (iy >= 0 && iy < S && ix >= 0 && ix < S)
            v = in[((long)(b*3 + c) * S + iy) * S + ix];
        in_s[c][r][col] = v;
    }
    __syncthreads();
    int ox = tid & 15, oy = tid >> 4;
    float pix[27];
#pragma unroll
    for (int c = 0; c < 3; ++c)
#pragma unroll
        for (int ki = 0; ki < 3; ++ki)
#pragma unroll
            for (int kj = 0; kj < 3; ++kj)
                pix[c*9 + ki*3 + kj] = in_s[c][2*oy + ki][2*ox + kj];
#pragma unroll 4
    for (int oc = 0; oc < 64; ++oc) {
        float acc = bias[oc];
#pragma unroll
        for (int q = 0; q < 27; ++q) acc += pix[q] * w_s[oc*27 + q];
        outp[(((long)b*64 + oc) * OS + oy0 + oy) * OS + ox0 + ox] = acc;
    }
}

// ---------------- fused conv3x3s2(256->128) + bicubic up2(128->256) ---------
#define CU_IN   0               // 3*41*44 floats = 5412
#define CU_W    5412            // 1728
#define CU_B    7140            // 64
#define CU_CV   7232            // 16*20*22 = 7040
#define CU_TOTF 14272           // floats
__global__ __launch_bounds__(256) void k_conv_up2(const float* __restrict__ in,
    const float* __restrict__ wt, const float* __restrict__ bias,
    float* __restrict__ outp)
{
    extern __shared__ __align__(16) float cus[];
    float* in_s = cus + CU_IN;
    float* w_s  = cus + CU_W;
    float* b_s  = cus + CU_B;
    float* cv   = cus + CU_CV;
    const int tid = threadIdx.x;
    const int cy0 = blockIdx.y * 16, cx0 = blockIdx.x * 16, b = blockIdx.z;

    for (int i = tid; i < 1728; i += 256) w_s[i] = wt[i];
    if (tid < 64) b_s[tid] = bias[tid];
    for (int idx = tid; idx < 3*41*41; idx += 256) {
        int c = idx / 1681, rem = idx % 1681, r = rem / 41, col = rem % 41;
        int gy = 2*cy0 - 5 + r, gx = 2*cx0 - 5 + col;
        float v = 0.f;
        if (gy >= 0 && gy < DH && gx >= 0 && gx < DH)
            v = in[((long)(b*3 + c) * DH + gy) * DH + gx];
        in_s[(c*41 + r) * 44 + col] = v;
    }
    __syncthreads();

#pragma unroll 1
    for (int g = 0; g < 4; ++g) {
        for (int idx = tid; idx < 16*400; idx += 256) {
            int ocl = idx / 400, rem = idx % 400, cr = rem / 20, cc = rem % 20;
            int oc = g*16 + ocl;
            const float* wk = w_s + oc*27;
            float acc = b_s[oc];
#pragma unroll
            for (int c = 0; c < 3; ++c) {
                const float* ip = in_s + (c*41 + 2*cr) * 44 + 2*cc;
#pragma unroll
                for (int ki = 0; ki < 3; ++ki)
#pragma unroll
                    for (int kj = 0; kj < 3; ++kj)
                        acc += ip[ki*44 + kj] * wk[c*9 + ki*3 + kj];
            }
            cv[(ocl*20 + cr) * 22 + cc] = acc;
        }
        __syncthreads();
        for (int pos = tid; pos < 1024; pos += 256) {
            int oyl = pos >> 5, oxl = pos & 31;
            int oy = 2*cy0 + oyl, ox = 2*cx0 + oxl;
            int iy[4], ix[4]; float wy[4], wx[4];
            taps_up2(oy, 128, iy, wy);
            taps_up2(ox, 128, ix, wx);
            int ly[4], lxl[4];
#pragma unroll
            for (int t = 0; t < 4; ++t) {
                int l = iy[t] - (cy0 - 2);
                ly[t] = l < 0 ? 0 : (l > 19 ? 19 : l);
                l = ix[t] - (cx0 - 2);
                lxl[t] = l < 0 ? 0 : (l > 19 ? 19 : l);
            }
#pragma unroll 4
            for (int ocl = 0; ocl < 16; ++ocl) {
                const float* cvp = cv + ocl*440;
                float s = 0.f;
#pragma unroll
                for (int a = 0; a < 4; ++a) {
                    float r = 0.f;
#pragma unroll
                    for (int q = 0; q < 4; ++q) r += wx[q] * cvp[ly[a]*22 + lxl[q]];
                    s += wy[a] * r;
                }
                outp[(((long)b*64 + g*16 + ocl) * 256 + oy) * 256 + ox] = s;
            }
        }
        __syncthreads();
    }
}

// ---------------- launch: fork-join two streams (capture-legal order) --------
extern "C" void kernel_launch(void* const* d_in, const int* in_sizes, int n_in,
                              void* d_out, int out_size)
{
    const float* x      = (const float*)d_in[0];
    const float* W_in   = (const float*)d_in[1];
    const float* W_h1   = (const float*)d_in[2];
    const float* W_h2   = (const float*)d_in[3];
    const float* W_h3   = (const float*)d_in[4];
    const float* W_h4   = (const float*)d_in[5];
    const float* W_out  = (const float*)d_in[6];
    const float* feat_w = (const float*)d_in[7];
    const float* feat_b = (const float*)d_in[8];
    const float* mod_w  = (const float*)d_in[9];
    const float* mod_b  = (const float*)d_in[10];

    float* outF = (float*)d_out;
    float* dout_mod = outF;                       // 2*3*256*256   = 393216
    float* dout_hr  = outF + 393216;              // 2*64*256*256  = 8388608
    float* dout_new = outF + 8781824;             // 8388608
    float* dout_ori = outF + 17170432;            // 8388608
    float* dout_out = outF + 25559040;            // 393216

    float *downx, *outfull;
    cudaGetSymbolAddress((void**)&downx,   g_down_x);
    cudaGetSymbolAddress((void**)&outfull, g_out_full);

    static cudaStream_t s1 = nullptr, s2 = nullptr;
    static cudaEvent_t ev0, evdx, evs1, evs2;
    if (!s1) {
        cudaStreamCreateWithFlags(&s1, cudaStreamNonBlocking);
        cudaStreamCreateWithFlags(&s2, cudaStreamNonBlocking);
        cudaEventCreateWithFlags(&ev0,  cudaEventDisableTiming);
        cudaEventCreateWithFlags(&evdx, cudaEventDisableTiming);
        cudaEventCreateWithFlags(&evs1, cudaEventDisableTiming);
        cudaEventCreateWithFlags(&evs2, cudaEventDisableTiming);
        cudaFuncSetAttribute(fused_mlp_mma,
                             cudaFuncAttributeMaxDynamicSharedMemorySize, S_TOT);
        cudaFuncSetAttribute(k_conv_up2,
                             cudaFuncAttributeMaxDynamicSharedMemorySize, CU_TOTF*4);
    }

    cudaEventRecord(ev0, 0);
    cudaStreamWaitEvent(s1, ev0, 0);
    cudaStreamWaitEvent(s2, ev0, 0);

    // ---- stream 2 FIRST: down2 + record evdx (must precede s1's wait) ----
    k_down2<<<(BB*3*DH*DH + 255)/256, 256, 0, s2>>>(x, downx, BB*3, HH);
    cudaEventRecord(evdx, s2);

    // ---- stream 1: critical path ----
    k_prep_w<<<320, 256, 0, s1>>>(W_h1, W_h2, W_h3, W_h4, W_out);
    fused_mlp_mma<<<MROWS/128, 256, S_TOT, s1>>>(x, W_in, outfull);
    cudaStreamWaitEvent(s1, evdx, 0);            // down2_mod needs downx
    k_down2_mod<<<(BB*DH*DH + 255)/256, 256, 0, s1>>>(outfull, downx, mod_w, mod_b,
                                                      dout_out, dout_mod);
    {
        dim3 g(8, 8, BB);
        k_conv_up2<<<g, 256, CU_TOTF*4, s1>>>(dout_mod, feat_w, feat_b, dout_new);
    }
    cudaEventRecord(evs1, s1);

    // ---- stream 2 continues: independent features ----
    {
        dim3 g(16, 16, BB);
        k_conv3x3s2<<<g, 256, 0, s2>>>(x, feat_w, feat_b, dout_hr, 512);
    }
    {
        dim3 g(8, 8, BB);
        k_conv_up2<<<g, 256, CU_TOTF*4, s2>>>(downx, feat_w, feat_b, dout_ori);
    }
    cudaEventRecord(evs2, s2);

    cudaStreamWaitEvent(0, evs1, 0);
    cudaStreamWaitEvent(0, evs2, 0);
}